// round 1
// baseline (speedup 1.0000x reference)
#include <cuda_runtime.h>
#include <math.h>

#define L_LAYERS 16
#define HD 64
#define NH 15
#define NKV 5
#define TH 960
#define TI 2560
#define EH 720
#define EI 2048
#define PL 512
#define EL 128
#define SS 640
#define QW (NH*HD)   // 960
#define KW (NKV*HD)  // 320

// ---------------- scratch (device globals; no allocation) ----------------
__device__ float g_vlm[PL*TH];
__device__ float g_exp[EL*EH];
__device__ float g_hv [PL*TH];
__device__ float g_he [EL*EH];
__device__ float g_q  [SS*QW];
__device__ float g_k  [SS*KW];
__device__ float g_v  [SS*KW];
__device__ float g_ke [PL*KW];
__device__ float g_ve [PL*KW];
__device__ float g_att[SS*QW];
__device__ float g_m1 [PL*TI];
__device__ float g_m2 [PL*TI];

// ---------------- GEMM: C[M,N] (+)= A[M,K] x B[K,N], row-major ----------------
#define BM 64
#define BN 64
#define BK 16
template<bool ACC>
__global__ void gemm_kernel(const float* __restrict__ A, const float* __restrict__ B,
                            float* __restrict__ C, int M, int N, int K) {
    __shared__ float As[BK][BM];
    __shared__ float Bs[BK][BN];
    int tx = threadIdx.x % 16, ty = threadIdx.x / 16;
    int row0 = blockIdx.y * BM + ty * 4;
    int col0 = blockIdx.x * BN + tx * 4;
    float acc[4][4] = {};
    for (int k0 = 0; k0 < K; k0 += BK) {
        for (int i = threadIdx.x; i < BM * BK; i += 256) {
            int r = i / BK, c = i % BK;
            int gr = blockIdx.y * BM + r;
            As[c][r] = (gr < M) ? A[(size_t)gr * K + k0 + c] : 0.f;
        }
        for (int i = threadIdx.x; i < BK * BN; i += 256) {
            int r = i / BN, c = i % BN;
            int gc = blockIdx.x * BN + c;
            Bs[r][c] = (gc < N) ? B[(size_t)(k0 + r) * N + gc] : 0.f;
        }
        __syncthreads();
        #pragma unroll
        for (int kk = 0; kk < BK; kk++) {
            float a[4], b[4];
            #pragma unroll
            for (int i = 0; i < 4; i++) a[i] = As[kk][ty * 4 + i];
            #pragma unroll
            for (int j = 0; j < 4; j++) b[j] = Bs[kk][tx * 4 + j];
            #pragma unroll
            for (int i = 0; i < 4; i++)
                #pragma unroll
                for (int j = 0; j < 4; j++)
                    acc[i][j] += a[i] * b[j];
        }
        __syncthreads();
    }
    for (int i = 0; i < 4; i++) {
        int r = row0 + i; if (r >= M) continue;
        for (int j = 0; j < 4; j++) {
            int c = col0 + j; if (c >= N) continue;
            if (ACC) C[(size_t)r * N + c] += acc[i][j];
            else     C[(size_t)r * N + c]  = acc[i][j];
        }
    }
}

// ---------------- RMSNorm: y[row] = w * x[row] * rsqrt(mean(x^2)+eps) ----------------
__global__ void rmsnorm_kernel(const float* __restrict__ x, const float* __restrict__ w,
                               float* __restrict__ y, int D) {
    int row = blockIdx.x;
    const float* xr = x + (size_t)row * D;
    __shared__ float red[256];
    float s = 0.f;
    for (int i = threadIdx.x; i < D; i += 256) { float v = xr[i]; s += v * v; }
    red[threadIdx.x] = s; __syncthreads();
    for (int o = 128; o > 0; o >>= 1) {
        if (threadIdx.x < o) red[threadIdx.x] += red[threadIdx.x + o];
        __syncthreads();
    }
    float scale = rsqrtf(red[0] / D + 1e-5f);
    for (int i = threadIdx.x; i < D; i += 256)
        y[(size_t)row * D + i] = w[i] * xr[i] * scale;
}

// ---------------- RoPE in-place: x[rows, H*64] ----------------
__global__ void rope_kernel(float* __restrict__ x, const int* __restrict__ pos_ids,
                            int pos_off, int H) {
    int row = blockIdx.x;
    int h = blockIdx.y;
    int j = threadIdx.x;              // 0..31
    float pos = (float)pos_ids[pos_off + row];
    float ts = powf(10000.f, (float)j / 32.f);
    float rad = pos / ts;
    float sn = sinf(rad), cs = cosf(rad);
    float* p = x + (size_t)row * (H * 64) + h * 64;
    float x1 = p[j], x2 = p[j + 32];
    p[j]      = x1 * cs - x2 * sn;
    p[j + 32] = x2 * cs + x1 * sn;
}

// ---------------- Attention: one block per (query row, head) ----------------
// mode 0: all-true mask. mode 1: attend iff k < PL || k <= (qoff + q).
__global__ void attn_kernel(const float* __restrict__ Q, const float* __restrict__ K,
                            const float* __restrict__ V, float* __restrict__ O,
                            int Lk, int qoff, int mode) {
    int q = blockIdx.x, h = blockIdx.y;
    int kvh = h / 3;
    int tid = threadIdx.x;            // 128 threads
    __shared__ float sc[SS];
    __shared__ float qd[64];
    __shared__ float red[128];
    const float* qp = Q + (size_t)q * QW + h * 64;
    if (tid < 64) qd[tid] = qp[tid];
    __syncthreads();
    int qg = qoff + q;
    for (int k = tid; k < Lk; k += 128) {
        bool ok = (mode == 0) || (k < PL) || (k <= qg);
        float d = 0.f;
        const float* kp = K + (size_t)k * KW + kvh * 64;
        #pragma unroll
        for (int i = 0; i < 64; i++) d += qd[i] * kp[i];
        sc[k] = ok ? d * 0.125f : -3.0e38f;
    }
    __syncthreads();
    float m = -3.0e38f;
    for (int k = tid; k < Lk; k += 128) m = fmaxf(m, sc[k]);
    red[tid] = m; __syncthreads();
    for (int o = 64; o > 0; o >>= 1) {
        if (tid < o) red[tid] = fmaxf(red[tid], red[tid + o]);
        __syncthreads();
    }
    m = red[0]; __syncthreads();
    float sum = 0.f;
    for (int k = tid; k < Lk; k += 128) {
        float e = expf(sc[k] - m);
        sc[k] = e; sum += e;
    }
    red[tid] = sum; __syncthreads();
    for (int o = 64; o > 0; o >>= 1) {
        if (tid < o) red[tid] += red[tid + o];
        __syncthreads();
    }
    float inv = 1.f / red[0];
    __syncthreads();
    if (tid < 64) {
        float acc = 0.f;
        const float* vp = V + kvh * 64 + tid;
        for (int k = 0; k < Lk; k++) acc += sc[k] * vp[(size_t)k * KW];
        O[(size_t)q * QW + h * 64 + tid] = acc * inv;
    }
}

// ---------------- u = silu(g) * u ----------------
__global__ void silu_mul_kernel(const float* __restrict__ g, float* __restrict__ u, int n) {
    int i = blockIdx.x * 256 + threadIdx.x;
    if (i < n) {
        float x = g[i];
        u[i] = (x / (1.f + expf(-x))) * u[i];
    }
}

// ---------------- host-side helpers ----------------
static void gemm(const float* A, const float* B, float* C, int M, int N, int K, bool acc) {
    dim3 grid((N + BN - 1) / BN, (M + BM - 1) / BM);
    if (acc) gemm_kernel<true ><<<grid, 256>>>(A, B, C, M, N, K);
    else     gemm_kernel<false><<<grid, 256>>>(A, B, C, M, N, K);
}

extern "C" void kernel_launch(void* const* d_in, const int* in_sizes, int n_in,
                              void* d_out, int out_size) {
    const float* in_vlm      = (const float*)d_in[0];
    const float* in_exp      = (const float*)d_in[1];
    const float* w_vq        = (const float*)d_in[2];
    const float* w_vk        = (const float*)d_in[3];
    const float* w_vv        = (const float*)d_in[4];
    const float* w_vo        = (const float*)d_in[5];
    const float* w_vln1      = (const float*)d_in[6];
    const float* w_vln2      = (const float*)d_in[7];
    const float* w_vg        = (const float*)d_in[8];
    const float* w_vu        = (const float*)d_in[9];
    const float* w_vd        = (const float*)d_in[10];
    const float* w_vfn       = (const float*)d_in[11];
    const float* w_eq        = (const float*)d_in[12];
    const float* w_eks       = (const float*)d_in[13];
    const float* w_evs       = (const float*)d_in[14];
    const float* w_ekc       = (const float*)d_in[15];
    const float* w_evc       = (const float*)d_in[16];
    const float* w_eo        = (const float*)d_in[17];
    const float* w_eln1      = (const float*)d_in[18];
    const float* w_eln2      = (const float*)d_in[19];
    const float* w_eg        = (const float*)d_in[20];
    const float* w_eu        = (const float*)d_in[21];
    const float* w_ed        = (const float*)d_in[22];
    const float* w_efn       = (const float*)d_in[23];
    const int*   pos_ids     = (const int*)d_in[24];
    float* out = (float*)d_out;

    float *vlm, *exps, *hv, *he, *q, *k, *v, *ke, *ve, *att, *m1, *m2;
    cudaGetSymbolAddress((void**)&vlm,  g_vlm);
    cudaGetSymbolAddress((void**)&exps, g_exp);
    cudaGetSymbolAddress((void**)&hv,   g_hv);
    cudaGetSymbolAddress((void**)&he,   g_he);
    cudaGetSymbolAddress((void**)&q,    g_q);
    cudaGetSymbolAddress((void**)&k,    g_k);
    cudaGetSymbolAddress((void**)&v,    g_v);
    cudaGetSymbolAddress((void**)&ke,   g_ke);
    cudaGetSymbolAddress((void**)&ve,   g_ve);
    cudaGetSymbolAddress((void**)&att,  g_att);
    cudaGetSymbolAddress((void**)&m1,   g_m1);
    cudaGetSymbolAddress((void**)&m2,   g_m2);

    cudaMemcpyAsync(vlm,  in_vlm, (size_t)PL * TH * sizeof(float), cudaMemcpyDeviceToDevice);
    cudaMemcpyAsync(exps, in_exp, (size_t)EL * EH * sizeof(float), cudaMemcpyDeviceToDevice);

    for (int li = 0; li < L_LAYERS; li++) {
        const float* vq  = w_vq  + (size_t)li * TH * QW;
        const float* vk  = w_vk  + (size_t)li * TH * KW;
        const float* vv  = w_vv  + (size_t)li * TH * KW;
        const float* vo  = w_vo  + (size_t)li * QW * TH;
        const float* vg  = w_vg  + (size_t)li * TH * TI;
        const float* vu  = w_vu  + (size_t)li * TH * TI;
        const float* vd  = w_vd  + (size_t)li * TI * TH;
        const float* eq  = w_eq  + (size_t)li * EH * QW;
        const float* eo  = w_eo  + (size_t)li * QW * EH;
        const float* eg  = w_eg  + (size_t)li * EH * EI;
        const float* eu  = w_eu  + (size_t)li * EH * EI;
        const float* ed  = w_ed  + (size_t)li * EI * EH;

        // pre-norms
        rmsnorm_kernel<<<PL, 256>>>(vlm,  w_vln1 + (size_t)li * TH, hv, TH);
        rmsnorm_kernel<<<EL, 256>>>(exps, w_eln1 + (size_t)li * EH, he, EH);

        // vlm q/k/v into concat buffers (rows 0..511)
        gemm(hv, vq, q, PL, QW, TH, false);
        gemm(hv, vk, k, PL, KW, TH, false);
        gemm(hv, vv, v, PL, KW, TH, false);

        if (li % 2 == 0) {
            const float* eks = w_eks + (size_t)(li / 2) * EH * KW;
            const float* evs = w_evs + (size_t)(li / 2) * EH * KW;
            // expert q/k/v into rows 512..639
            gemm(he, eq,  q + (size_t)PL * QW, EL, QW, EH, false);
            gemm(he, eks, k + (size_t)PL * KW, EL, KW, EH, false);
            gemm(he, evs, v + (size_t)PL * KW, EL, KW, EH, false);
            // rope on full concat
            rope_kernel<<<dim3(SS, NH),  32>>>(q, pos_ids, 0, NH);
            rope_kernel<<<dim3(SS, NKV), 32>>>(k, pos_ids, 0, NKV);
            // joint attention, prefix-causal mask
            attn_kernel<<<dim3(SS, NH), 128>>>(q, k, v, att, SS, 0, 1);
        } else {
            const float* ekc = w_ekc + (size_t)(li / 2) * KW * KW;
            const float* evc = w_evc + (size_t)(li / 2) * KW * KW;
            // rope on vlm q/k only
            rope_kernel<<<dim3(PL, NH),  32>>>(q, pos_ids, 0, NH);
            rope_kernel<<<dim3(PL, NKV), 32>>>(k, pos_ids, 0, NKV);
            // vlm self-attention (mask all-true over PL x PL)
            attn_kernel<<<dim3(PL, NH), 128>>>(q, k, v, att, PL, 0, 0);
            // cross K from roped k, cross V from un-roped v
            gemm(k, ekc, ke, PL, KW, KW, false);
            gemm(v, evc, ve, PL, KW, KW, false);
            // expert q + rope with expert positions
            gemm(he, eq, q + (size_t)PL * QW, EL, QW, EH, false);
            rope_kernel<<<dim3(EL, NH), 32>>>(q + (size_t)PL * QW, pos_ids, PL, NH);
            // expert cross-attention (mask all-true, 128 x 512)
            attn_kernel<<<dim3(EL, NH), 128>>>(q + (size_t)PL * QW, ke, ve,
                                               att + (size_t)PL * QW, PL, 0, 0);
        }

        // ---- vlm block_out ----
        gemm(att, vo, vlm, PL, TH, QW, true);                 // h += att @ wo
        rmsnorm_kernel<<<PL, 256>>>(vlm, w_vln2 + (size_t)li * TH, hv, TH);
        gemm(hv, vg, m1, PL, TI, TH, false);
        gemm(hv, vu, m2, PL, TI, TH, false);
        silu_mul_kernel<<<(PL * TI + 255) / 256, 256>>>(m1, m2, PL * TI);
        gemm(m2, vd, vlm, PL, TH, TI, true);                  // h += t @ wd

        // ---- expert block_out ----
        gemm(att + (size_t)PL * QW, eo, exps, EL, EH, QW, true);
        rmsnorm_kernel<<<EL, 256>>>(exps, w_eln2 + (size_t)li * EH, he, EH);
        gemm(he, eg, m1, EL, EI, EH, false);
        gemm(he, eu, m2, EL, EI, EH, false);
        silu_mul_kernel<<<(EL * EI + 255) / 256, 256>>>(m1, m2, EL * EI);
        gemm(m2, ed, exps, EL, EH, EI, true);
    }

    // final norms -> output (vlm first, then expert)
    rmsnorm_kernel<<<PL, 256>>>(vlm,  w_vfn, out, TH);
    rmsnorm_kernel<<<EL, 256>>>(exps, w_efn, out + (size_t)PL * TH, EH);
}

// round 2
// speedup vs baseline: 1.7538x; 1.7538x over previous
#include <cuda_runtime.h>
#include <math.h>
#include <stdint.h>

#define L_LAYERS 16
#define HD 64
#define NH 15
#define NKV 5
#define TH 960
#define TI 2560
#define EH 720
#define EI 2048
#define PL 512
#define EL 128
#define SS 640
#define QW (NH*HD)   // 960
#define KW (NKV*HD)  // 320

// ---------------- scratch (device globals; no allocation) ----------------
__device__ float g_vlm[PL*TH];
__device__ float g_exp[EL*EH];
__device__ float g_hv [PL*TH];
__device__ float g_he [EL*EH];
__device__ float g_q  [SS*QW];
__device__ float g_k  [SS*KW];
__device__ float g_v  [SS*KW];
__device__ float g_ke [PL*KW];
__device__ float g_ve [PL*KW];
__device__ float g_att[SS*QW];
__device__ float g_m1 [PL*TI];
__device__ float g_m2 [PL*TI];

// ---------------- tf32 tensor-core GEMM ----------------
// C[M,N] (+)= A[M,K] @ B[K,N], all row-major fp32 in gmem, tf32 mma compute.
// Block tile 128x64, BK=16, 4 warps each computing 64x32.
#define GBM 128
#define GBN 64
#define GBK 16
#define ASTR 20   // A smem row stride (pad 16->20, conflict-free frag reads)
#define BSTR 72   // B smem row stride (pad 64->72, conflict-free frag reads)

__device__ __forceinline__ uint32_t f2tf32(float x) {
    uint32_t r;
    asm("cvt.rna.tf32.f32 %0, %1;" : "=r"(r) : "f"(x));
    return r;
}

template<bool ACC>
__global__ __launch_bounds__(128)
void gemm_tc_kernel(const float* __restrict__ A, const float* __restrict__ B,
                    float* __restrict__ C, int M, int N, int K) {
    __shared__ uint32_t As[GBM * ASTR];
    __shared__ uint32_t Bs[GBK * BSTR];
    int tid  = threadIdx.x;
    int warp = tid >> 5, lane = tid & 31;
    int g = lane >> 2, t = lane & 3;     // group (0..7), thread-in-group (0..3)
    int wm = warp & 1, wn = warp >> 1;   // 2x2 warp grid
    int row0 = blockIdx.y * GBM;
    int col0 = blockIdx.x * GBN;

    float acc[4][4][4];
    #pragma unroll
    for (int i = 0; i < 4; i++)
        #pragma unroll
        for (int j = 0; j < 4; j++)
            #pragma unroll
            for (int c = 0; c < 4; c++) acc[i][j][c] = 0.f;

    for (int k0 = 0; k0 < K; k0 += GBK) {
        // --- load A slab: 128 rows x 16 k (512 float4, 4 per thread) ---
        #pragma unroll
        for (int i = 0; i < 4; i++) {
            int idx = tid + i * 128;
            int r = idx >> 2, c4 = (idx & 3) * 4;
            float4 v = make_float4(0.f, 0.f, 0.f, 0.f);
            if (row0 + r < M)
                v = *(const float4*)&A[(size_t)(row0 + r) * K + k0 + c4];
            As[r * ASTR + c4 + 0] = f2tf32(v.x);
            As[r * ASTR + c4 + 1] = f2tf32(v.y);
            As[r * ASTR + c4 + 2] = f2tf32(v.z);
            As[r * ASTR + c4 + 3] = f2tf32(v.w);
        }
        // --- load B slab: 16 rows x 64 n (256 float4, 2 per thread) ---
        #pragma unroll
        for (int i = 0; i < 2; i++) {
            int idx = tid + i * 128;
            int r = idx >> 4, c4 = (idx & 15) * 4;
            int col = col0 + c4;
            float4 v = make_float4(0.f, 0.f, 0.f, 0.f);
            if (col < N)
                v = *(const float4*)&B[(size_t)(k0 + r) * N + col];
            Bs[r * BSTR + c4 + 0] = f2tf32(v.x);
            Bs[r * BSTR + c4 + 1] = f2tf32(v.y);
            Bs[r * BSTR + c4 + 2] = f2tf32(v.z);
            Bs[r * BSTR + c4 + 3] = f2tf32(v.w);
        }
        __syncthreads();

        #pragma unroll
        for (int kk = 0; kk < GBK; kk += 8) {
            uint32_t af[4][4], bf[4][2];
            #pragma unroll
            for (int mi = 0; mi < 4; mi++) {
                int rb = wm * 64 + mi * 16;
                af[mi][0] = As[(rb + g    ) * ASTR + kk + t    ];
                af[mi][1] = As[(rb + g + 8) * ASTR + kk + t    ];
                af[mi][2] = As[(rb + g    ) * ASTR + kk + t + 4];
                af[mi][3] = As[(rb + g + 8) * ASTR + kk + t + 4];
            }
            #pragma unroll
            for (int ni = 0; ni < 4; ni++) {
                int cb = wn * 32 + ni * 8 + g;
                bf[ni][0] = Bs[(kk + t    ) * BSTR + cb];
                bf[ni][1] = Bs[(kk + t + 4) * BSTR + cb];
            }
            #pragma unroll
            for (int mi = 0; mi < 4; mi++)
                #pragma unroll
                for (int ni = 0; ni < 4; ni++)
                    asm volatile(
                        "mma.sync.aligned.m16n8k8.row.col.f32.tf32.tf32.f32 "
                        "{%0,%1,%2,%3}, {%4,%5,%6,%7}, {%8,%9}, {%0,%1,%2,%3};"
                        : "+f"(acc[mi][ni][0]), "+f"(acc[mi][ni][1]),
                          "+f"(acc[mi][ni][2]), "+f"(acc[mi][ni][3])
                        : "r"(af[mi][0]), "r"(af[mi][1]),
                          "r"(af[mi][2]), "r"(af[mi][3]),
                          "r"(bf[ni][0]), "r"(bf[ni][1]));
        }
        __syncthreads();
    }

    // --- epilogue ---
    #pragma unroll
    for (int mi = 0; mi < 4; mi++) {
        int rb = row0 + wm * 64 + mi * 16 + g;
        #pragma unroll
        for (int ni = 0; ni < 4; ni++) {
            int cb = col0 + wn * 32 + ni * 8 + t * 2;
            #pragma unroll
            for (int cj = 0; cj < 4; cj++) {
                int r = rb + ((cj >= 2) ? 8 : 0);
                int c = cb + (cj & 1);
                if (r < M && c < N) {
                    if (ACC) C[(size_t)r * N + c] += acc[mi][ni][cj];
                    else     C[(size_t)r * N + c]  = acc[mi][ni][cj];
                }
            }
        }
    }
}

// ---------------- RMSNorm ----------------
__global__ void rmsnorm_kernel(const float* __restrict__ x, const float* __restrict__ w,
                               float* __restrict__ y, int D) {
    int row = blockIdx.x;
    const float* xr = x + (size_t)row * D;
    __shared__ float red[256];
    float s = 0.f;
    for (int i = threadIdx.x; i < D; i += 256) { float v = xr[i]; s += v * v; }
    red[threadIdx.x] = s; __syncthreads();
    for (int o = 128; o > 0; o >>= 1) {
        if (threadIdx.x < o) red[threadIdx.x] += red[threadIdx.x + o];
        __syncthreads();
    }
    float scale = rsqrtf(red[0] / D + 1e-5f);
    for (int i = threadIdx.x; i < D; i += 256)
        y[(size_t)row * D + i] = w[i] * xr[i] * scale;
}

// ---------------- RoPE in-place ----------------
__global__ void rope_kernel(float* __restrict__ x, const int* __restrict__ pos_ids,
                            int pos_off, int H) {
    int row = blockIdx.x;
    int h = blockIdx.y;
    int j = threadIdx.x;              // 0..31
    float pos = (float)pos_ids[pos_off + row];
    float ts = powf(10000.f, (float)j / 32.f);
    float rad = pos / ts;
    float sn = sinf(rad), cs = cosf(rad);
    float* p = x + (size_t)row * (H * 64) + h * 64;
    float x1 = p[j], x2 = p[j + 32];
    p[j]      = x1 * cs - x2 * sn;
    p[j + 32] = x2 * cs + x1 * sn;
}

// ---------------- Attention: one block per (query row, head) ----------------
__global__ void attn_kernel(const float* __restrict__ Q, const float* __restrict__ K,
                            const float* __restrict__ V, float* __restrict__ O,
                            int Lk, int qoff, int mode) {
    int q = blockIdx.x, h = blockIdx.y;
    int kvh = h / 3;
    int tid = threadIdx.x;            // 128 threads
    __shared__ float sc[SS];
    __shared__ float qd[64];
    __shared__ float red[128];
    const float* qp = Q + (size_t)q * QW + h * 64;
    if (tid < 64) qd[tid] = qp[tid];
    __syncthreads();
    int qg = qoff + q;
    for (int k = tid; k < Lk; k += 128) {
        bool ok = (mode == 0) || (k < PL) || (k <= qg);
        float d = 0.f;
        const float* kp = K + (size_t)k * KW + kvh * 64;
        #pragma unroll
        for (int i = 0; i < 64; i++) d += qd[i] * kp[i];
        sc[k] = ok ? d * 0.125f : -3.0e38f;
    }
    __syncthreads();
    float m = -3.0e38f;
    for (int k = tid; k < Lk; k += 128) m = fmaxf(m, sc[k]);
    red[tid] = m; __syncthreads();
    for (int o = 64; o > 0; o >>= 1) {
        if (tid < o) red[tid] = fmaxf(red[tid], red[tid + o]);
        __syncthreads();
    }
    m = red[0]; __syncthreads();
    float sum = 0.f;
    for (int k = tid; k < Lk; k += 128) {
        float e = expf(sc[k] - m);
        sc[k] = e; sum += e;
    }
    red[tid] = sum; __syncthreads();
    for (int o = 64; o > 0; o >>= 1) {
        if (tid < o) red[tid] += red[tid + o];
        __syncthreads();
    }
    float inv = 1.f / red[0];
    __syncthreads();
    if (tid < 64) {
        float acc = 0.f;
        const float* vp = V + kvh * 64 + tid;
        for (int k = 0; k < Lk; k++) acc += sc[k] * vp[(size_t)k * KW];
        O[(size_t)q * QW + h * 64 + tid] = acc * inv;
    }
}

// ---------------- u = silu(g) * u ----------------
__global__ void silu_mul_kernel(const float* __restrict__ g, float* __restrict__ u, int n) {
    int i = blockIdx.x * 256 + threadIdx.x;
    if (i < n) {
        float x = g[i];
        u[i] = (x / (1.f + expf(-x))) * u[i];
    }
}

// ---------------- host-side helper ----------------
static void gemm(const float* A, const float* B, float* C, int M, int N, int K, bool acc) {
    dim3 grid((N + GBN - 1) / GBN, (M + GBM - 1) / GBM);
    if (acc) gemm_tc_kernel<true ><<<grid, 128>>>(A, B, C, M, N, K);
    else     gemm_tc_kernel<false><<<grid, 128>>>(A, B, C, M, N, K);
}

extern "C" void kernel_launch(void* const* d_in, const int* in_sizes, int n_in,
                              void* d_out, int out_size) {
    const float* in_vlm      = (const float*)d_in[0];
    const float* in_exp      = (const float*)d_in[1];
    const float* w_vq        = (const float*)d_in[2];
    const float* w_vk        = (const float*)d_in[3];
    const float* w_vv        = (const float*)d_in[4];
    const float* w_vo        = (const float*)d_in[5];
    const float* w_vln1      = (const float*)d_in[6];
    const float* w_vln2      = (const float*)d_in[7];
    const float* w_vg        = (const float*)d_in[8];
    const float* w_vu        = (const float*)d_in[9];
    const float* w_vd        = (const float*)d_in[10];
    const float* w_vfn       = (const float*)d_in[11];
    const float* w_eq        = (const float*)d_in[12];
    const float* w_eks       = (const float*)d_in[13];
    const float* w_evs       = (const float*)d_in[14];
    const float* w_ekc       = (const float*)d_in[15];
    const float* w_evc       = (const float*)d_in[16];
    const float* w_eo        = (const float*)d_in[17];
    const float* w_eln1      = (const float*)d_in[18];
    const float* w_eln2      = (const float*)d_in[19];
    const float* w_eg        = (const float*)d_in[20];
    const float* w_eu        = (const float*)d_in[21];
    const float* w_ed        = (const float*)d_in[22];
    const float* w_efn       = (const float*)d_in[23];
    const int*   pos_ids     = (const int*)d_in[24];
    float* out = (float*)d_out;

    float *vlm, *exps, *hv, *he, *q, *k, *v, *ke, *ve, *att, *m1, *m2;
    cudaGetSymbolAddress((void**)&vlm,  g_vlm);
    cudaGetSymbolAddress((void**)&exps, g_exp);
    cudaGetSymbolAddress((void**)&hv,   g_hv);
    cudaGetSymbolAddress((void**)&he,   g_he);
    cudaGetSymbolAddress((void**)&q,    g_q);
    cudaGetSymbolAddress((void**)&k,    g_k);
    cudaGetSymbolAddress((void**)&v,    g_v);
    cudaGetSymbolAddress((void**)&ke,   g_ke);
    cudaGetSymbolAddress((void**)&ve,   g_ve);
    cudaGetSymbolAddress((void**)&att,  g_att);
    cudaGetSymbolAddress((void**)&m1,   g_m1);
    cudaGetSymbolAddress((void**)&m2,   g_m2);

    cudaMemcpyAsync(vlm,  in_vlm, (size_t)PL * TH * sizeof(float), cudaMemcpyDeviceToDevice);
    cudaMemcpyAsync(exps, in_exp, (size_t)EL * EH * sizeof(float), cudaMemcpyDeviceToDevice);

    for (int li = 0; li < L_LAYERS; li++) {
        const float* vq  = w_vq  + (size_t)li * TH * QW;
        const float* vk  = w_vk  + (size_t)li * TH * KW;
        const float* vv  = w_vv  + (size_t)li * TH * KW;
        const float* vo  = w_vo  + (size_t)li * QW * TH;
        const float* vg  = w_vg  + (size_t)li * TH * TI;
        const float* vu  = w_vu  + (size_t)li * TH * TI;
        const float* vd  = w_vd  + (size_t)li * TI * TH;
        const float* eq  = w_eq  + (size_t)li * EH * QW;
        const float* eo  = w_eo  + (size_t)li * QW * EH;
        const float* eg  = w_eg  + (size_t)li * EH * EI;
        const float* eu  = w_eu  + (size_t)li * EH * EI;
        const float* ed  = w_ed  + (size_t)li * EI * EH;

        // pre-norms
        rmsnorm_kernel<<<PL, 256>>>(vlm,  w_vln1 + (size_t)li * TH, hv, TH);
        rmsnorm_kernel<<<EL, 256>>>(exps, w_eln1 + (size_t)li * EH, he, EH);

        // vlm q/k/v into concat buffers (rows 0..511)
        gemm(hv, vq, q, PL, QW, TH, false);
        gemm(hv, vk, k, PL, KW, TH, false);
        gemm(hv, vv, v, PL, KW, TH, false);

        if (li % 2 == 0) {
            const float* eks = w_eks + (size_t)(li / 2) * EH * KW;
            const float* evs = w_evs + (size_t)(li / 2) * EH * KW;
            gemm(he, eq,  q + (size_t)PL * QW, EL, QW, EH, false);
            gemm(he, eks, k + (size_t)PL * KW, EL, KW, EH, false);
            gemm(he, evs, v + (size_t)PL * KW, EL, KW, EH, false);
            rope_kernel<<<dim3(SS, NH),  32>>>(q, pos_ids, 0, NH);
            rope_kernel<<<dim3(SS, NKV), 32>>>(k, pos_ids, 0, NKV);
            attn_kernel<<<dim3(SS, NH), 128>>>(q, k, v, att, SS, 0, 1);
        } else {
            const float* ekc = w_ekc + (size_t)(li / 2) * KW * KW;
            const float* evc = w_evc + (size_t)(li / 2) * KW * KW;
            rope_kernel<<<dim3(PL, NH),  32>>>(q, pos_ids, 0, NH);
            rope_kernel<<<dim3(PL, NKV), 32>>>(k, pos_ids, 0, NKV);
            attn_kernel<<<dim3(PL, NH), 128>>>(q, k, v, att, PL, 0, 0);
            gemm(k, ekc, ke, PL, KW, KW, false);
            gemm(v, evc, ve, PL, KW, KW, false);
            gemm(he, eq, q + (size_t)PL * QW, EL, QW, EH, false);
            rope_kernel<<<dim3(EL, NH), 32>>>(q + (size_t)PL * QW, pos_ids, PL, NH);
            attn_kernel<<<dim3(EL, NH), 128>>>(q + (size_t)PL * QW, ke, ve,
                                               att + (size_t)PL * QW, PL, 0, 0);
        }

        // ---- vlm block_out ----
        gemm(att, vo, vlm, PL, TH, QW, true);
        rmsnorm_kernel<<<PL, 256>>>(vlm, w_vln2 + (size_t)li * TH, hv, TH);
        gemm(hv, vg, m1, PL, TI, TH, false);
        gemm(hv, vu, m2, PL, TI, TH, false);
        silu_mul_kernel<<<(PL * TI + 255) / 256, 256>>>(m1, m2, PL * TI);
        gemm(m2, vd, vlm, PL, TH, TI, true);

        // ---- expert block_out ----
        gemm(att + (size_t)PL * QW, eo, exps, EL, EH, QW, true);
        rmsnorm_kernel<<<EL, 256>>>(exps, w_eln2 + (size_t)li * EH, he, EH);
        gemm(he, eg, m1, EL, EI, EH, false);
        gemm(he, eu, m2, EL, EI, EH, false);
        silu_mul_kernel<<<(EL * EI + 255) / 256, 256>>>(m1, m2, EL * EI);
        gemm(m2, ed, exps, EL, EH, EI, true);
    }

    // final norms -> output (vlm first, then expert)
    rmsnorm_kernel<<<PL, 256>>>(vlm,  w_vfn, out, TH);
    rmsnorm_kernel<<<EL, 256>>>(exps, w_efn, out + (size_t)PL * TH, EH);
}

// round 3
// speedup vs baseline: 2.5330x; 1.4443x over previous
#include <cuda_runtime.h>
#include <math.h>
#include <stdint.h>

#define L_LAYERS 16
#define HD 64
#define NH 15
#define NKV 5
#define TH 960
#define TI 2560
#define EH 720
#define EI 2048
#define PL 512
#define EL 128
#define SS 640
#define QW (NH*HD)   // 960
#define KW (NKV*HD)  // 320

// ---------------- scratch (device globals; no allocation) ----------------
__device__ float g_vlm[PL*TH];
__device__ float g_exp[EL*EH];
__device__ float g_hv [PL*TH];
__device__ float g_he [EL*EH];
__device__ float g_q  [SS*QW];
__device__ float g_k  [SS*KW];
__device__ float g_v  [SS*KW];
__device__ float g_ke [PL*KW];
__device__ float g_ve [PL*KW];
__device__ float g_att[SS*QW];
__device__ float g_m1 [PL*TI];
__device__ float g_m2 [PL*TI];
__device__ float g_e1 [EL*EI];
__device__ float g_e2 [EL*EI];

// ---------------- grouped tf32 tensor-core GEMM ----------------
// Each launch runs up to 8 independent C[M,N] (+)= A[M,K] @ B[K,N] tasks.
// Tile 64x64, BK=16, 128 threads (4 warps, 2x2 of 32x32), cp.async 2-stage.
struct GemmTask {
    const float* A; const float* B; float* C;
    int M, N, K, acc;
    int blk_start, nbn;
};
struct GemmBatch { GemmTask t[8]; int nt; };

#define TBM 64
#define TBN 64
#define TBK 16
#define ASTR 20   // pad 16 -> 20 floats (conflict-free frag reads)
#define BSTR 72   // pad 64 -> 72 floats

__device__ __forceinline__ uint32_t f2tf32(float x) {
    uint32_t r;
    asm("cvt.rna.tf32.f32 %0, %1;" : "=r"(r) : "f"(x));
    return r;
}
__device__ __forceinline__ void cpasync16(uint32_t s, const void* g, int sz) {
    asm volatile("cp.async.ca.shared.global [%0], [%1], 16, %2;" :: "r"(s), "l"(g), "r"(sz));
}
__device__ __forceinline__ void cp_commit() { asm volatile("cp.async.commit_group;"); }
__device__ __forceinline__ void cp_wait1()  { asm volatile("cp.async.wait_group 1;"); }
__device__ __forceinline__ void cp_wait0()  { asm volatile("cp.async.wait_group 0;"); }

__global__ __launch_bounds__(128)
void gemm_grouped_kernel(GemmBatch batch) {
    __shared__ float As[2][TBM * ASTR];
    __shared__ float Bs[2][TBK * BSTR];

    int ti = 0;
    #pragma unroll
    for (int i = 1; i < 8; i++)
        if (i < batch.nt && (int)blockIdx.x >= batch.t[i].blk_start) ti = i;
    GemmTask T = batch.t[ti];
    int local = (int)blockIdx.x - T.blk_start;
    int bm = local / T.nbn, bn = local % T.nbn;
    int row0 = bm * TBM, col0 = bn * TBN;

    int tid  = threadIdx.x;
    int warp = tid >> 5, lane = tid & 31;
    int g = lane >> 2, t = lane & 3;
    int wm = warp & 1, wn = warp >> 1;   // 2x2 warps, warp tile 32x32

    // load lanes
    int ar = tid >> 2,  ac4 = (tid & 3) * 4;     // A: 2 float4/thread (rows ar, ar+32)
    int br = tid >> 4,  bc4 = (tid & 15) * 4;    // B: 2 float4/thread (rows br, br+8)
    int bvalid = (col0 + bc4 < T.N) ? 16 : 0;    // N multiple of 16 -> vector-granular

    float acc[2][4][4];
    #pragma unroll
    for (int mi = 0; mi < 2; mi++)
        #pragma unroll
        for (int ni = 0; ni < 4; ni++)
            #pragma unroll
            for (int c = 0; c < 4; c++) acc[mi][ni][c] = 0.f;

    int niter = T.K / TBK;

    // ---- prologue: stage 0 ----
    {
        uint32_t sA = (uint32_t)__cvta_generic_to_shared(&As[0][0]);
        uint32_t sB = (uint32_t)__cvta_generic_to_shared(&Bs[0][0]);
        cpasync16(sA + (ar * ASTR + ac4) * 4,
                  T.A + (size_t)(row0 + ar) * T.K + ac4, 16);
        cpasync16(sA + ((ar + 32) * ASTR + ac4) * 4,
                  T.A + (size_t)(row0 + ar + 32) * T.K + ac4, 16);
        cpasync16(sB + (br * BSTR + bc4) * 4,
                  T.B + (size_t)br * T.N + col0 + bc4, bvalid);
        cpasync16(sB + ((br + 8) * BSTR + bc4) * 4,
                  T.B + (size_t)(br + 8) * T.N + col0 + bc4, bvalid);
        cp_commit();
    }

    for (int it = 0; it < niter; it++) {
        int s = it & 1;
        if (it + 1 < niter) {
            int ns = (it + 1) & 1;
            int k0 = (it + 1) * TBK;
            uint32_t sA = (uint32_t)__cvta_generic_to_shared(&As[ns][0]);
            uint32_t sB = (uint32_t)__cvta_generic_to_shared(&Bs[ns][0]);
            cpasync16(sA + (ar * ASTR + ac4) * 4,
                      T.A + (size_t)(row0 + ar) * T.K + k0 + ac4, 16);
            cpasync16(sA + ((ar + 32) * ASTR + ac4) * 4,
                      T.A + (size_t)(row0 + ar + 32) * T.K + k0 + ac4, 16);
            cpasync16(sB + (br * BSTR + bc4) * 4,
                      T.B + (size_t)(k0 + br) * T.N + col0 + bc4, bvalid);
            cpasync16(sB + ((br + 8) * BSTR + bc4) * 4,
                      T.B + (size_t)(k0 + br + 8) * T.N + col0 + bc4, bvalid);
            cp_commit();
            cp_wait1();
        } else {
            cp_wait0();
        }
        __syncthreads();

        #pragma unroll
        for (int kk = 0; kk < TBK; kk += 8) {
            uint32_t af[2][4], bf[4][2];
            #pragma unroll
            for (int mi = 0; mi < 2; mi++) {
                int rb = wm * 32 + mi * 16;
                af[mi][0] = f2tf32(As[s][(rb + g    ) * ASTR + kk + t    ]);
                af[mi][1] = f2tf32(As[s][(rb + g + 8) * ASTR + kk + t    ]);
                af[mi][2] = f2tf32(As[s][(rb + g    ) * ASTR + kk + t + 4]);
                af[mi][3] = f2tf32(As[s][(rb + g + 8) * ASTR + kk + t + 4]);
            }
            #pragma unroll
            for (int ni = 0; ni < 4; ni++) {
                int cb = wn * 32 + ni * 8 + g;
                bf[ni][0] = f2tf32(Bs[s][(kk + t    ) * BSTR + cb]);
                bf[ni][1] = f2tf32(Bs[s][(kk + t + 4) * BSTR + cb]);
            }
            #pragma unroll
            for (int mi = 0; mi < 2; mi++)
                #pragma unroll
                for (int ni = 0; ni < 4; ni++)
                    asm volatile(
                        "mma.sync.aligned.m16n8k8.row.col.f32.tf32.tf32.f32 "
                        "{%0,%1,%2,%3}, {%4,%5,%6,%7}, {%8,%9}, {%0,%1,%2,%3};"
                        : "+f"(acc[mi][ni][0]), "+f"(acc[mi][ni][1]),
                          "+f"(acc[mi][ni][2]), "+f"(acc[mi][ni][3])
                        : "r"(af[mi][0]), "r"(af[mi][1]),
                          "r"(af[mi][2]), "r"(af[mi][3]),
                          "r"(bf[ni][0]), "r"(bf[ni][1]));
        }
        __syncthreads();
    }

    // ---- epilogue (M is always a multiple of 64; guard N only) ----
    #pragma unroll
    for (int mi = 0; mi < 2; mi++) {
        int rb = row0 + wm * 32 + mi * 16 + g;
        #pragma unroll
        for (int ni = 0; ni < 4; ni++) {
            int cb = col0 + wn * 32 + ni * 8 + t * 2;
            #pragma unroll
            for (int cj = 0; cj < 4; cj++) {
                int r = rb + ((cj >= 2) ? 8 : 0);
                int c = cb + (cj & 1);
                if (c < T.N) {
                    if (T.acc) T.C[(size_t)r * T.N + c] += acc[mi][ni][cj];
                    else       T.C[(size_t)r * T.N + c]  = acc[mi][ni][cj];
                }
            }
        }
    }
}

// ---------------- RMSNorm ----------------
__global__ void rmsnorm_kernel(const float* __restrict__ x, const float* __restrict__ w,
                               float* __restrict__ y, int D) {
    int row = blockIdx.x;
    const float* xr = x + (size_t)row * D;
    __shared__ float red[256];
    float s = 0.f;
    for (int i = threadIdx.x; i < D; i += 256) { float v = xr[i]; s += v * v; }
    red[threadIdx.x] = s; __syncthreads();
    for (int o = 128; o > 0; o >>= 1) {
        if (threadIdx.x < o) red[threadIdx.x] += red[threadIdx.x + o];
        __syncthreads();
    }
    float scale = rsqrtf(red[0] / D + 1e-5f);
    for (int i = threadIdx.x; i < D; i += 256)
        y[(size_t)row * D + i] = w[i] * xr[i] * scale;
}

// ---------------- RoPE in-place ----------------
__global__ void rope_kernel(float* __restrict__ x, const int* __restrict__ pos_ids,
                            int pos_off, int H) {
    int row = blockIdx.x;
    int h = blockIdx.y;
    int j = threadIdx.x;              // 0..31
    float pos = (float)pos_ids[pos_off + row];
    float ts = powf(10000.f, (float)j / 32.f);
    float rad = pos / ts;
    float sn = sinf(rad), cs = cosf(rad);
    float* p = x + (size_t)row * (H * 64) + h * 64;
    float x1 = p[j], x2 = p[j + 32];
    p[j]      = x1 * cs - x2 * sn;
    p[j + 32] = x2 * cs + x1 * sn;
}

// ---------------- Attention: one block per (query row, head) ----------------
__global__ void attn_kernel(const float* __restrict__ Q, const float* __restrict__ K,
                            const float* __restrict__ V, float* __restrict__ O,
                            int Lk, int qoff, int mode) {
    int q = blockIdx.x, h = blockIdx.y;
    int kvh = h / 3;
    int tid = threadIdx.x;            // 128 threads
    __shared__ float sc[SS];
    __shared__ float qd[64];
    __shared__ float red[128];
    const float* qp = Q + (size_t)q * QW + h * 64;
    if (tid < 64) qd[tid] = qp[tid];
    __syncthreads();
    int qg = qoff + q;
    for (int k = tid; k < Lk; k += 128) {
        bool ok = (mode == 0) || (k < PL) || (k <= qg);
        float d = 0.f;
        const float* kp = K + (size_t)k * KW + kvh * 64;
        #pragma unroll
        for (int i = 0; i < 64; i++) d += qd[i] * kp[i];
        sc[k] = ok ? d * 0.125f : -3.0e38f;
    }
    __syncthreads();
    float m = -3.0e38f;
    for (int k = tid; k < Lk; k += 128) m = fmaxf(m, sc[k]);
    red[tid] = m; __syncthreads();
    for (int o = 64; o > 0; o >>= 1) {
        if (tid < o) red[tid] = fmaxf(red[tid], red[tid + o]);
        __syncthreads();
    }
    m = red[0]; __syncthreads();
    float sum = 0.f;
    for (int k = tid; k < Lk; k += 128) {
        float e = expf(sc[k] - m);
        sc[k] = e; sum += e;
    }
    red[tid] = sum; __syncthreads();
    for (int o = 64; o > 0; o >>= 1) {
        if (tid < o) red[tid] += red[tid + o];
        __syncthreads();
    }
    float inv = 1.f / red[0];
    __syncthreads();
    // PV: 128 threads = 2 K-halves x 64 dims
    {
        int half = tid >> 6;          // 0 or 1
        int d = tid & 63;
        int Lk2 = Lk >> 1;
        int kb = half * Lk2, ke = kb + Lk2;
        float acc = 0.f;
        const float* vp = V + kvh * 64 + d;
        #pragma unroll 4
        for (int k = kb; k < ke; k++) acc += sc[k] * vp[(size_t)k * KW];
        red[tid] = acc;
    }
    __syncthreads();
    if (tid < 64)
        O[(size_t)q * QW + h * 64 + tid] = (red[tid] + red[tid + 64]) * inv;
}

// ---------------- u = silu(g) * u ----------------
__global__ void silu_mul_kernel(const float* __restrict__ g, float* __restrict__ u, int n) {
    int i = blockIdx.x * 256 + threadIdx.x;
    if (i < n) {
        float x = g[i];
        u[i] = (x / (1.f + expf(-x))) * u[i];
    }
}

// ---------------- host-side grouped-gemm builder ----------------
static inline void batch_init(GemmBatch& b, int& blk) { b.nt = 0; blk = 0; }
static inline void batch_add(GemmBatch& b, int& blk,
                             const float* A, const float* B, float* C,
                             int M, int N, int K, int acc) {
    GemmTask& T = b.t[b.nt++];
    T.A = A; T.B = B; T.C = C; T.M = M; T.N = N; T.K = K; T.acc = acc;
    T.nbn = (N + TBN - 1) / TBN;
    T.blk_start = blk;
    blk += T.nbn * ((M + TBM - 1) / TBM);
}
static inline void batch_go(GemmBatch& b, int blk) {
    gemm_grouped_kernel<<<blk, 128>>>(b);
}

extern "C" void kernel_launch(void* const* d_in, const int* in_sizes, int n_in,
                              void* d_out, int out_size) {
    const float* in_vlm      = (const float*)d_in[0];
    const float* in_exp      = (const float*)d_in[1];
    const float* w_vq        = (const float*)d_in[2];
    const float* w_vk        = (const float*)d_in[3];
    const float* w_vv        = (const float*)d_in[4];
    const float* w_vo        = (const float*)d_in[5];
    const float* w_vln1      = (const float*)d_in[6];
    const float* w_vln2      = (const float*)d_in[7];
    const float* w_vg        = (const float*)d_in[8];
    const float* w_vu        = (const float*)d_in[9];
    const float* w_vd        = (const float*)d_in[10];
    const float* w_vfn       = (const float*)d_in[11];
    const float* w_eq        = (const float*)d_in[12];
    const float* w_eks       = (const float*)d_in[13];
    const float* w_evs       = (const float*)d_in[14];
    const float* w_ekc       = (const float*)d_in[15];
    const float* w_evc       = (const float*)d_in[16];
    const float* w_eo        = (const float*)d_in[17];
    const float* w_eln1      = (const float*)d_in[18];
    const float* w_eln2      = (const float*)d_in[19];
    const float* w_eg        = (const float*)d_in[20];
    const float* w_eu        = (const float*)d_in[21];
    const float* w_ed        = (const float*)d_in[22];
    const float* w_efn       = (const float*)d_in[23];
    const int*   pos_ids     = (const int*)d_in[24];
    float* out = (float*)d_out;

    float *vlm, *exps, *hv, *he, *q, *k, *v, *ke, *ve, *att, *m1, *m2, *e1, *e2;
    cudaGetSymbolAddress((void**)&vlm,  g_vlm);
    cudaGetSymbolAddress((void**)&exps, g_exp);
    cudaGetSymbolAddress((void**)&hv,   g_hv);
    cudaGetSymbolAddress((void**)&he,   g_he);
    cudaGetSymbolAddress((void**)&q,    g_q);
    cudaGetSymbolAddress((void**)&k,    g_k);
    cudaGetSymbolAddress((void**)&v,    g_v);
    cudaGetSymbolAddress((void**)&ke,   g_ke);
    cudaGetSymbolAddress((void**)&ve,   g_ve);
    cudaGetSymbolAddress((void**)&att,  g_att);
    cudaGetSymbolAddress((void**)&m1,   g_m1);
    cudaGetSymbolAddress((void**)&m2,   g_m2);
    cudaGetSymbolAddress((void**)&e1,   g_e1);
    cudaGetSymbolAddress((void**)&e2,   g_e2);

    cudaMemcpyAsync(vlm,  in_vlm, (size_t)PL * TH * sizeof(float), cudaMemcpyDeviceToDevice);
    cudaMemcpyAsync(exps, in_exp, (size_t)EL * EH * sizeof(float), cudaMemcpyDeviceToDevice);

    GemmBatch b; int blk;

    for (int li = 0; li < L_LAYERS; li++) {
        const float* vq  = w_vq  + (size_t)li * TH * QW;
        const float* vk  = w_vk  + (size_t)li * TH * KW;
        const float* vv  = w_vv  + (size_t)li * TH * KW;
        const float* vo  = w_vo  + (size_t)li * QW * TH;
        const float* vg  = w_vg  + (size_t)li * TH * TI;
        const float* vu  = w_vu  + (size_t)li * TH * TI;
        const float* vd  = w_vd  + (size_t)li * TI * TH;
        const float* eq  = w_eq  + (size_t)li * EH * QW;
        const float* eo  = w_eo  + (size_t)li * QW * EH;
        const float* eg  = w_eg  + (size_t)li * EH * EI;
        const float* eu  = w_eu  + (size_t)li * EH * EI;
        const float* ed  = w_ed  + (size_t)li * EI * EH;

        // pre-norms
        rmsnorm_kernel<<<PL, 256>>>(vlm,  w_vln1 + (size_t)li * TH, hv, TH);
        rmsnorm_kernel<<<EL, 256>>>(exps, w_eln1 + (size_t)li * EH, he, EH);

        if (li % 2 == 0) {
            const float* eks = w_eks + (size_t)(li / 2) * EH * KW;
            const float* evs = w_evs + (size_t)(li / 2) * EH * KW;
            batch_init(b, blk);
            batch_add(b, blk, hv, vq,  q,                    PL, QW, TH, 0);
            batch_add(b, blk, hv, vk,  k,                    PL, KW, TH, 0);
            batch_add(b, blk, hv, vv,  v,                    PL, KW, TH, 0);
            batch_add(b, blk, he, eq,  q + (size_t)PL * QW,  EL, QW, EH, 0);
            batch_add(b, blk, he, eks, k + (size_t)PL * KW,  EL, KW, EH, 0);
            batch_add(b, blk, he, evs, v + (size_t)PL * KW,  EL, KW, EH, 0);
            batch_go(b, blk);
            rope_kernel<<<dim3(SS, NH),  32>>>(q, pos_ids, 0, NH);
            rope_kernel<<<dim3(SS, NKV), 32>>>(k, pos_ids, 0, NKV);
            attn_kernel<<<dim3(SS, NH), 128>>>(q, k, v, att, SS, 0, 1);
        } else {
            const float* ekc = w_ekc + (size_t)(li / 2) * KW * KW;
            const float* evc = w_evc + (size_t)(li / 2) * KW * KW;
            batch_init(b, blk);
            batch_add(b, blk, hv, vq, q,                   PL, QW, TH, 0);
            batch_add(b, blk, hv, vk, k,                   PL, KW, TH, 0);
            batch_add(b, blk, hv, vv, v,                   PL, KW, TH, 0);
            batch_add(b, blk, he, eq, q + (size_t)PL * QW, EL, QW, EH, 0);
            batch_go(b, blk);
            // rope q over all SS rows (expert positions == pos_ids[row]); k over PL
            rope_kernel<<<dim3(SS, NH),  32>>>(q, pos_ids, 0, NH);
            rope_kernel<<<dim3(PL, NKV), 32>>>(k, pos_ids, 0, NKV);
            // cross K from roped k, cross V from un-roped v
            batch_init(b, blk);
            batch_add(b, blk, k, ekc, ke, PL, KW, KW, 0);
            batch_add(b, blk, v, evc, ve, PL, KW, KW, 0);
            batch_go(b, blk);
            attn_kernel<<<dim3(PL, NH), 128>>>(q, k, v, att, PL, 0, 0);
            attn_kernel<<<dim3(EL, NH), 128>>>(q + (size_t)PL * QW, ke, ve,
                                               att + (size_t)PL * QW, PL, 0, 0);
        }

        // ---- wo (both towers, accumulate into residual) ----
        batch_init(b, blk);
        batch_add(b, blk, att,                    vo, vlm,  PL, TH, QW, 1);
        batch_add(b, blk, att + (size_t)PL * QW,  eo, exps, EL, EH, QW, 1);
        batch_go(b, blk);

        // ---- post-norms ----
        rmsnorm_kernel<<<PL, 256>>>(vlm,  w_vln2 + (size_t)li * TH, hv, TH);
        rmsnorm_kernel<<<EL, 256>>>(exps, w_eln2 + (size_t)li * EH, he, EH);

        // ---- gate + up (both towers) ----
        batch_init(b, blk);
        batch_add(b, blk, hv, vg, m1, PL, TI, TH, 0);
        batch_add(b, blk, hv, vu, m2, PL, TI, TH, 0);
        batch_add(b, blk, he, eg, e1, EL, EI, EH, 0);
        batch_add(b, blk, he, eu, e2, EL, EI, EH, 0);
        batch_go(b, blk);

        silu_mul_kernel<<<(PL * TI + 255) / 256, 256>>>(m1, m2, PL * TI);
        silu_mul_kernel<<<(EL * EI + 255) / 256, 256>>>(e1, e2, EL * EI);

        // ---- down (both towers, accumulate) ----
        batch_init(b, blk);
        batch_add(b, blk, m2, vd, vlm,  PL, TH, TI, 1);
        batch_add(b, blk, e2, ed, exps, EL, EH, EI, 1);
        batch_go(b, blk);
    }

    // final norms -> output (vlm first, then expert)
    rmsnorm_kernel<<<PL, 256>>>(vlm,  w_vfn, out, TH);
    rmsnorm_kernel<<<EL, 256>>>(exps, w_efn, out + (size_t)PL * TH, EH);
}

// round 4
// speedup vs baseline: 2.5970x; 1.0253x over previous
#include <cuda_runtime.h>
#include <math.h>
#include <stdint.h>

#define L_LAYERS 16
#define HD 64
#define NH 15
#define NKV 5
#define TH 960
#define TI 2560
#define EH 720
#define EI 2048
#define PL 512
#define EL 128
#define SS 640
#define QW (NH*HD)   // 960
#define KW (NKV*HD)  // 320

// ---------------- scratch (device globals; no allocation) ----------------
__device__ float g_vlm[PL*TH];
__device__ float g_exp[EL*EH];
__device__ float g_hv [PL*TH];
__device__ float g_he [EL*EH];
__device__ float g_q  [SS*QW];
__device__ float g_k  [SS*KW];
__device__ float g_v  [SS*KW];
__device__ float g_ke [PL*KW];
__device__ float g_ve [PL*KW];
__device__ float g_att[SS*QW];
__device__ float g_m1 [PL*TI];
__device__ float g_m2 [PL*TI];
__device__ float g_e1 [EL*EI];
__device__ float g_e2 [EL*EI];

// ---------------- grouped tf32 tensor-core GEMM, 4-stage cp.async ----------------
struct GemmTask {
    const float* A; const float* B; float* C;
    int M, N, K, acc;
    int blk_start, nbn;
};
struct GemmBatch { GemmTask t[8]; int nt; };

#define TBM 64
#define TBN 64
#define TBK 16
#define STAGES 4
#define ASTR 20   // pad 16 -> 20 floats (conflict-free frag reads)
#define BSTR 72   // pad 64 -> 72 floats

__device__ __forceinline__ uint32_t f2tf32(float x) {
    uint32_t r;
    asm("cvt.rna.tf32.f32 %0, %1;" : "=r"(r) : "f"(x));
    return r;
}
__device__ __forceinline__ void cpasync16(uint32_t s, const void* g, int sz) {
    asm volatile("cp.async.ca.shared.global [%0], [%1], 16, %2;" :: "r"(s), "l"(g), "r"(sz));
}
__device__ __forceinline__ void cp_commit() { asm volatile("cp.async.commit_group;"); }
__device__ __forceinline__ void cp_wait2()  { asm volatile("cp.async.wait_group 2;"); }

__global__ __launch_bounds__(128)
void gemm_grouped_kernel(GemmBatch batch) {
    __shared__ float As[STAGES][TBM * ASTR];
    __shared__ float Bs[STAGES][TBK * BSTR];

    int ti = 0;
    #pragma unroll
    for (int i = 1; i < 8; i++)
        if (i < batch.nt && (int)blockIdx.x >= batch.t[i].blk_start) ti = i;
    GemmTask T = batch.t[ti];
    int local = (int)blockIdx.x - T.blk_start;
    int bm = local / T.nbn, bn = local % T.nbn;
    int row0 = bm * TBM, col0 = bn * TBN;

    int tid  = threadIdx.x;
    int warp = tid >> 5, lane = tid & 31;
    int g = lane >> 2, t = lane & 3;
    int wm = warp & 1, wn = warp >> 1;   // 2x2 warps, warp tile 32x32

    // load lanes
    int ar = tid >> 2,  ac4 = (tid & 3) * 4;     // A: 2 float4/thread
    int br = tid >> 4,  bc4 = (tid & 15) * 4;    // B: 2 float4/thread
    int bvalid = (col0 + bc4 < T.N) ? 16 : 0;    // N is a multiple of 16

    float acc[2][4][4];
    #pragma unroll
    for (int mi = 0; mi < 2; mi++)
        #pragma unroll
        for (int ni = 0; ni < 4; ni++)
            #pragma unroll
            for (int c = 0; c < 4; c++) acc[mi][ni][c] = 0.f;

    int niter = T.K / TBK;

    // ---- prologue: issue stages 0..2 ----
    #pragma unroll
    for (int p = 0; p < STAGES - 1; p++) {
        if (p < niter) {
            int k0 = p * TBK;
            uint32_t sA = (uint32_t)__cvta_generic_to_shared(&As[p][0]);
            uint32_t sB = (uint32_t)__cvta_generic_to_shared(&Bs[p][0]);
            cpasync16(sA + (ar * ASTR + ac4) * 4,
                      T.A + (size_t)(row0 + ar) * T.K + k0 + ac4, 16);
            cpasync16(sA + ((ar + 32) * ASTR + ac4) * 4,
                      T.A + (size_t)(row0 + ar + 32) * T.K + k0 + ac4, 16);
            cpasync16(sB + (br * BSTR + bc4) * 4,
                      T.B + (size_t)(k0 + br) * T.N + col0 + bc4, bvalid);
            cpasync16(sB + ((br + 8) * BSTR + bc4) * 4,
                      T.B + (size_t)(k0 + br + 8) * T.N + col0 + bc4, bvalid);
        }
        cp_commit();
    }

    for (int it = 0; it < niter; it++) {
        int s = it & (STAGES - 1);
        cp_wait2();              // stage `it` resident (2 newer groups in flight)
        __syncthreads();

        // issue stage it+3 into slot (it+3)%4 (freed: computed at it-1)
        {
            int ip = it + STAGES - 1;
            if (ip < niter) {
                int ns = ip & (STAGES - 1);
                int k0 = ip * TBK;
                uint32_t sA = (uint32_t)__cvta_generic_to_shared(&As[ns][0]);
                uint32_t sB = (uint32_t)__cvta_generic_to_shared(&Bs[ns][0]);
                cpasync16(sA + (ar * ASTR + ac4) * 4,
                          T.A + (size_t)(row0 + ar) * T.K + k0 + ac4, 16);
                cpasync16(sA + ((ar + 32) * ASTR + ac4) * 4,
                          T.A + (size_t)(row0 + ar + 32) * T.K + k0 + ac4, 16);
                cpasync16(sB + (br * BSTR + bc4) * 4,
                          T.B + (size_t)(k0 + br) * T.N + col0 + bc4, bvalid);
                cpasync16(sB + ((br + 8) * BSTR + bc4) * 4,
                          T.B + (size_t)(k0 + br + 8) * T.N + col0 + bc4, bvalid);
            }
            cp_commit();         // always commit: constant group accounting
        }

        #pragma unroll
        for (int kk = 0; kk < TBK; kk += 8) {
            uint32_t af[2][4], bf[4][2];
            #pragma unroll
            for (int mi = 0; mi < 2; mi++) {
                int rb = wm * 32 + mi * 16;
                af[mi][0] = f2tf32(As[s][(rb + g    ) * ASTR + kk + t    ]);
                af[mi][1] = f2tf32(As[s][(rb + g + 8) * ASTR + kk + t    ]);
                af[mi][2] = f2tf32(As[s][(rb + g    ) * ASTR + kk + t + 4]);
                af[mi][3] = f2tf32(As[s][(rb + g + 8) * ASTR + kk + t + 4]);
            }
            #pragma unroll
            for (int ni = 0; ni < 4; ni++) {
                int cb = wn * 32 + ni * 8 + g;
                bf[ni][0] = f2tf32(Bs[s][(kk + t    ) * BSTR + cb]);
                bf[ni][1] = f2tf32(Bs[s][(kk + t + 4) * BSTR + cb]);
            }
            #pragma unroll
            for (int mi = 0; mi < 2; mi++)
                #pragma unroll
                for (int ni = 0; ni < 4; ni++)
                    asm volatile(
                        "mma.sync.aligned.m16n8k8.row.col.f32.tf32.tf32.f32 "
                        "{%0,%1,%2,%3}, {%4,%5,%6,%7}, {%8,%9}, {%0,%1,%2,%3};"
                        : "+f"(acc[mi][ni][0]), "+f"(acc[mi][ni][1]),
                          "+f"(acc[mi][ni][2]), "+f"(acc[mi][ni][3])
                        : "r"(af[mi][0]), "r"(af[mi][1]),
                          "r"(af[mi][2]), "r"(af[mi][3]),
                          "r"(bf[ni][0]), "r"(bf[ni][1]));
        }
        __syncthreads();
    }

    // ---- epilogue (M multiple of 64; guard N only) ----
    #pragma unroll
    for (int mi = 0; mi < 2; mi++) {
        int rb = row0 + wm * 32 + mi * 16 + g;
        #pragma unroll
        for (int ni = 0; ni < 4; ni++) {
            int cb = col0 + wn * 32 + ni * 8 + t * 2;
            #pragma unroll
            for (int cj = 0; cj < 4; cj++) {
                int r = rb + ((cj >= 2) ? 8 : 0);
                int c = cb + (cj & 1);
                if (c < T.N) {
                    if (T.acc) T.C[(size_t)r * T.N + c] += acc[mi][ni][cj];
                    else       T.C[(size_t)r * T.N + c]  = acc[mi][ni][cj];
                }
            }
        }
    }
}

// ---------------- RMSNorm ----------------
__global__ void rmsnorm_kernel(const float* __restrict__ x, const float* __restrict__ w,
                               float* __restrict__ y, int D) {
    int row = blockIdx.x;
    const float* xr = x + (size_t)row * D;
    __shared__ float red[256];
    float s = 0.f;
    for (int i = threadIdx.x; i < D; i += 256) { float v = xr[i]; s += v * v; }
    red[threadIdx.x] = s; __syncthreads();
    for (int o = 128; o > 0; o >>= 1) {
        if (threadIdx.x < o) red[threadIdx.x] += red[threadIdx.x + o];
        __syncthreads();
    }
    float scale = rsqrtf(red[0] / D + 1e-5f);
    for (int i = threadIdx.x; i < D; i += 256)
        y[(size_t)row * D + i] = w[i] * xr[i] * scale;
}

// ---------------- RoPE in-place ----------------
__global__ void rope_kernel(float* __restrict__ x, const int* __restrict__ pos_ids,
                            int pos_off, int H) {
    int row = blockIdx.x;
    int h = blockIdx.y;
    int j = threadIdx.x;              // 0..31
    float pos = (float)pos_ids[pos_off + row];
    float ts = powf(10000.f, (float)j / 32.f);
    float rad = pos / ts;
    float sn = sinf(rad), cs = cosf(rad);
    float* p = x + (size_t)row * (H * 64) + h * 64;
    float x1 = p[j], x2 = p[j + 32];
    p[j]      = x1 * cs - x2 * sn;
    p[j + 32] = x2 * cs + x1 * sn;
}

// ---------------- Attention: one block per (query row, head) ----------------
__global__ void attn_kernel(const float* __restrict__ Q, const float* __restrict__ K,
                            const float* __restrict__ V, float* __restrict__ O,
                            int Lk, int qoff, int mode) {
    int q = blockIdx.x, h = blockIdx.y;
    int kvh = h / 3;
    int tid = threadIdx.x;            // 128 threads
    __shared__ float sc[SS];
    __shared__ float qd[64];
    __shared__ float red[128];
    const float* qp = Q + (size_t)q * QW + h * 64;
    if (tid < 64) qd[tid] = qp[tid];
    __syncthreads();
    int qg = qoff + q;
    for (int k = tid; k < Lk; k += 128) {
        bool ok = (mode == 0) || (k < PL) || (k <= qg);
        float d = 0.f;
        const float* kp = K + (size_t)k * KW + kvh * 64;
        #pragma unroll
        for (int i = 0; i < 64; i++) d += qd[i] * kp[i];
        sc[k] = ok ? d * 0.125f : -3.0e38f;
    }
    __syncthreads();
    float m = -3.0e38f;
    for (int k = tid; k < Lk; k += 128) m = fmaxf(m, sc[k]);
    red[tid] = m; __syncthreads();
    for (int o = 64; o > 0; o >>= 1) {
        if (tid < o) red[tid] = fmaxf(red[tid], red[tid + o]);
        __syncthreads();
    }
    m = red[0]; __syncthreads();
    float sum = 0.f;
    for (int k = tid; k < Lk; k += 128) {
        float e = expf(sc[k] - m);
        sc[k] = e; sum += e;
    }
    red[tid] = sum; __syncthreads();
    for (int o = 64; o > 0; o >>= 1) {
        if (tid < o) red[tid] += red[tid + o];
        __syncthreads();
    }
    float inv = 1.f / red[0];
    __syncthreads();
    {
        int half = tid >> 6;
        int d = tid & 63;
        int Lk2 = Lk >> 1;
        int kb = half * Lk2, ke = kb + Lk2;
        float acc = 0.f;
        const float* vp = V + kvh * 64 + d;
        #pragma unroll 4
        for (int k = kb; k < ke; k++) acc += sc[k] * vp[(size_t)k * KW];
        red[tid] = acc;
    }
    __syncthreads();
    if (tid < 64)
        O[(size_t)q * QW + h * 64 + tid] = (red[tid] + red[tid + 64]) * inv;
}

// ---------------- u = silu(g) * u ----------------
__global__ void silu_mul_kernel(const float* __restrict__ g, float* __restrict__ u, int n) {
    int i = blockIdx.x * 256 + threadIdx.x;
    if (i < n) {
        float x = g[i];
        u[i] = (x / (1.f + expf(-x))) * u[i];
    }
}

// ---------------- host-side grouped-gemm builder ----------------
static inline void batch_init(GemmBatch& b, int& blk) { b.nt = 0; blk = 0; }
static inline void batch_add(GemmBatch& b, int& blk,
                             const float* A, const float* B, float* C,
                             int M, int N, int K, int acc) {
    GemmTask& T = b.t[b.nt++];
    T.A = A; T.B = B; T.C = C; T.M = M; T.N = N; T.K = K; T.acc = acc;
    T.nbn = (N + TBN - 1) / TBN;
    T.blk_start = blk;
    blk += T.nbn * ((M + TBM - 1) / TBM);
}
static inline void batch_go(GemmBatch& b, int blk) {
    gemm_grouped_kernel<<<blk, 128>>>(b);
}

extern "C" void kernel_launch(void* const* d_in, const int* in_sizes, int n_in,
                              void* d_out, int out_size) {
    const float* in_vlm      = (const float*)d_in[0];
    const float* in_exp      = (const float*)d_in[1];
    const float* w_vq        = (const float*)d_in[2];
    const float* w_vk        = (const float*)d_in[3];
    const float* w_vv        = (const float*)d_in[4];
    const float* w_vo        = (const float*)d_in[5];
    const float* w_vln1      = (const float*)d_in[6];
    const float* w_vln2      = (const float*)d_in[7];
    const float* w_vg        = (const float*)d_in[8];
    const float* w_vu        = (const float*)d_in[9];
    const float* w_vd        = (const float*)d_in[10];
    const float* w_vfn       = (const float*)d_in[11];
    const float* w_eq        = (const float*)d_in[12];
    const float* w_eks       = (const float*)d_in[13];
    const float* w_evs       = (const float*)d_in[14];
    const float* w_ekc       = (const float*)d_in[15];
    const float* w_evc       = (const float*)d_in[16];
    const float* w_eo        = (const float*)d_in[17];
    const float* w_eln1      = (const float*)d_in[18];
    const float* w_eln2      = (const float*)d_in[19];
    const float* w_eg        = (const float*)d_in[20];
    const float* w_eu        = (const float*)d_in[21];
    const float* w_ed        = (const float*)d_in[22];
    const float* w_efn       = (const float*)d_in[23];
    const int*   pos_ids     = (const int*)d_in[24];
    float* out = (float*)d_out;

    float *vlm, *exps, *hv, *he, *q, *k, *v, *ke, *ve, *att, *m1, *m2, *e1, *e2;
    cudaGetSymbolAddress((void**)&vlm,  g_vlm);
    cudaGetSymbolAddress((void**)&exps, g_exp);
    cudaGetSymbolAddress((void**)&hv,   g_hv);
    cudaGetSymbolAddress((void**)&he,   g_he);
    cudaGetSymbolAddress((void**)&q,    g_q);
    cudaGetSymbolAddress((void**)&k,    g_k);
    cudaGetSymbolAddress((void**)&v,    g_v);
    cudaGetSymbolAddress((void**)&ke,   g_ke);
    cudaGetSymbolAddress((void**)&ve,   g_ve);
    cudaGetSymbolAddress((void**)&att,  g_att);
    cudaGetSymbolAddress((void**)&m1,   g_m1);
    cudaGetSymbolAddress((void**)&m2,   g_m2);
    cudaGetSymbolAddress((void**)&e1,   g_e1);
    cudaGetSymbolAddress((void**)&e2,   g_e2);

    cudaMemcpyAsync(vlm,  in_vlm, (size_t)PL * TH * sizeof(float), cudaMemcpyDeviceToDevice);
    cudaMemcpyAsync(exps, in_exp, (size_t)EL * EH * sizeof(float), cudaMemcpyDeviceToDevice);

    GemmBatch b; int blk;

    for (int li = 0; li < L_LAYERS; li++) {
        const float* vq  = w_vq  + (size_t)li * TH * QW;
        const float* vk  = w_vk  + (size_t)li * TH * KW;
        const float* vv  = w_vv  + (size_t)li * TH * KW;
        const float* vo  = w_vo  + (size_t)li * QW * TH;
        const float* vg  = w_vg  + (size_t)li * TH * TI;
        const float* vu  = w_vu  + (size_t)li * TH * TI;
        const float* vd  = w_vd  + (size_t)li * TI * TH;
        const float* eq  = w_eq  + (size_t)li * EH * QW;
        const float* eo  = w_eo  + (size_t)li * QW * EH;
        const float* eg  = w_eg  + (size_t)li * EH * EI;
        const float* eu  = w_eu  + (size_t)li * EH * EI;
        const float* ed  = w_ed  + (size_t)li * EI * EH;

        // pre-norms
        rmsnorm_kernel<<<PL, 256>>>(vlm,  w_vln1 + (size_t)li * TH, hv, TH);
        rmsnorm_kernel<<<EL, 256>>>(exps, w_eln1 + (size_t)li * EH, he, EH);

        if (li % 2 == 0) {
            const float* eks = w_eks + (size_t)(li / 2) * EH * KW;
            const float* evs = w_evs + (size_t)(li / 2) * EH * KW;
            batch_init(b, blk);
            batch_add(b, blk, hv, vq,  q,                    PL, QW, TH, 0);
            batch_add(b, blk, hv, vk,  k,                    PL, KW, TH, 0);
            batch_add(b, blk, hv, vv,  v,                    PL, KW, TH, 0);
            batch_add(b, blk, he, eq,  q + (size_t)PL * QW,  EL, QW, EH, 0);
            batch_add(b, blk, he, eks, k + (size_t)PL * KW,  EL, KW, EH, 0);
            batch_add(b, blk, he, evs, v + (size_t)PL * KW,  EL, KW, EH, 0);
            batch_go(b, blk);
            rope_kernel<<<dim3(SS, NH),  32>>>(q, pos_ids, 0, NH);
            rope_kernel<<<dim3(SS, NKV), 32>>>(k, pos_ids, 0, NKV);
            attn_kernel<<<dim3(SS, NH), 128>>>(q, k, v, att, SS, 0, 1);
        } else {
            const float* ekc = w_ekc + (size_t)(li / 2) * KW * KW;
            const float* evc = w_evc + (size_t)(li / 2) * KW * KW;
            batch_init(b, blk);
            batch_add(b, blk, hv, vq, q,                   PL, QW, TH, 0);
            batch_add(b, blk, hv, vk, k,                   PL, KW, TH, 0);
            batch_add(b, blk, hv, vv, v,                   PL, KW, TH, 0);
            batch_add(b, blk, he, eq, q + (size_t)PL * QW, EL, QW, EH, 0);
            batch_go(b, blk);
            rope_kernel<<<dim3(SS, NH),  32>>>(q, pos_ids, 0, NH);
            rope_kernel<<<dim3(PL, NKV), 32>>>(k, pos_ids, 0, NKV);
            batch_init(b, blk);
            batch_add(b, blk, k, ekc, ke, PL, KW, KW, 0);
            batch_add(b, blk, v, evc, ve, PL, KW, KW, 0);
            batch_go(b, blk);
            attn_kernel<<<dim3(PL, NH), 128>>>(q, k, v, att, PL, 0, 0);
            attn_kernel<<<dim3(EL, NH), 128>>>(q + (size_t)PL * QW, ke, ve,
                                               att + (size_t)PL * QW, PL, 0, 0);
        }

        // ---- wo (both towers, accumulate into residual) ----
        batch_init(b, blk);
        batch_add(b, blk, att,                    vo, vlm,  PL, TH, QW, 1);
        batch_add(b, blk, att + (size_t)PL * QW,  eo, exps, EL, EH, QW, 1);
        batch_go(b, blk);

        // ---- post-norms ----
        rmsnorm_kernel<<<PL, 256>>>(vlm,  w_vln2 + (size_t)li * TH, hv, TH);
        rmsnorm_kernel<<<EL, 256>>>(exps, w_eln2 + (size_t)li * EH, he, EH);

        // ---- gate + up (both towers) ----
        batch_init(b, blk);
        batch_add(b, blk, hv, vg, m1, PL, TI, TH, 0);
        batch_add(b, blk, hv, vu, m2, PL, TI, TH, 0);
        batch_add(b, blk, he, eg, e1, EL, EI, EH, 0);
        batch_add(b, blk, he, eu, e2, EL, EI, EH, 0);
        batch_go(b, blk);

        silu_mul_kernel<<<(PL * TI + 255) / 256, 256>>>(m1, m2, PL * TI);
        silu_mul_kernel<<<(EL * EI + 255) / 256, 256>>>(e1, e2, EL * EI);

        // ---- down (both towers, accumulate) ----
        batch_init(b, blk);
        batch_add(b, blk, m2, vd, vlm,  PL, TH, TI, 1);
        batch_add(b, blk, e2, ed, exps, EL, EH, EI, 1);
        batch_go(b, blk);
    }

    // final norms -> output (vlm first, then expert)
    rmsnorm_kernel<<<PL, 256>>>(vlm,  w_vfn, out, TH);
    rmsnorm_kernel<<<EL, 256>>>(exps, w_efn, out + (size_t)PL * TH, EH);
}

// round 6
// speedup vs baseline: 8.3121x; 3.2006x over previous
#include <cuda_runtime.h>
#include <cuda_fp16.h>
#include <math.h>
#include <stdint.h>

#define L_LAYERS 16
#define HD 64
#define NH 15
#define NKV 5
#define TH 960
#define TI 2560
#define EH 720
#define EI 2048
#define PL 512
#define EL 128
#define SS 640
#define QW (NH*HD)   // 960
#define KW (NKV*HD)  // 320

// ---------------- weight half cache (converted once per launch) ----------------
#define N_VQ  ((size_t)L_LAYERS*TH*QW)
#define N_VK  ((size_t)L_LAYERS*TH*KW)
#define N_VV  ((size_t)L_LAYERS*TH*KW)
#define N_VO  ((size_t)L_LAYERS*QW*TH)
#define N_VG  ((size_t)L_LAYERS*TH*TI)
#define N_VU  ((size_t)L_LAYERS*TH*TI)
#define N_VD  ((size_t)L_LAYERS*TI*TH)
#define N_EQ  ((size_t)L_LAYERS*EH*QW)
#define N_EKS ((size_t)(L_LAYERS/2)*EH*KW)
#define N_EVS ((size_t)(L_LAYERS/2)*EH*KW)
#define N_EKC ((size_t)(L_LAYERS/2)*KW*KW)
#define N_EVC ((size_t)(L_LAYERS/2)*KW*KW)
#define N_EO  ((size_t)L_LAYERS*QW*EH)
#define N_EG  ((size_t)L_LAYERS*EH*EI)
#define N_EU  ((size_t)L_LAYERS*EH*EI)
#define N_ED  ((size_t)L_LAYERS*EI*EH)

#define O_VQ  ((size_t)0)
#define O_VK  (O_VQ + N_VQ)
#define O_VV  (O_VK + N_VK)
#define O_VO  (O_VV + N_VV)
#define O_VG  (O_VO + N_VO)
#define O_VU  (O_VG + N_VG)
#define O_VD  (O_VU + N_VU)
#define O_EQ  (O_VD + N_VD)
#define O_EKS (O_EQ + N_EQ)
#define O_EVS (O_EKS + N_EKS)
#define O_EKC (O_EVS + N_EVS)
#define O_EVC (O_EKC + N_EKC)
#define O_EO  (O_EVC + N_EVC)
#define O_EG  (O_EO + N_EO)
#define O_EU  (O_EG + N_EG)
#define O_ED  (O_EU + N_EU)
#define W_TOTAL (O_ED + N_ED)

__device__ __align__(128) __half g_wh[W_TOTAL];

// ---------------- activation / residual scratch ----------------
__device__ __align__(128) float  g_vlm[PL*TH];
__device__ __align__(128) float  g_exp[EL*EH];
__device__ __align__(128) float  g_m1 [PL*TI];
__device__ __align__(128) float  g_m2 [PL*TI];
__device__ __align__(128) float  g_e1 [EL*EI];
__device__ __align__(128) float  g_e2 [EL*EI];
__device__ __align__(128) __half h_hv [PL*TH];
__device__ __align__(128) __half h_he [EL*EH];
__device__ __align__(128) __half h_q  [SS*QW];
__device__ __align__(128) __half h_k  [SS*KW];
__device__ __align__(128) __half h_v  [SS*KW];
__device__ __align__(128) __half h_ke [PL*KW];
__device__ __align__(128) __half h_ve [PL*KW];
__device__ __align__(128) __half h_att[SS*QW];
__device__ __align__(128) __half h_m2 [PL*TI];
__device__ __align__(128) __half h_e2 [EL*EI];

// ---------------- PTX helpers ----------------
__device__ __forceinline__ uint32_t smem_u32(const void* p) {
    uint32_t a;
    asm("{ .reg .u64 t; cvta.to.shared.u64 t, %1; cvt.u32.u64 %0, t; }" : "=r"(a) : "l"(p));
    return a;
}
__device__ __forceinline__ void cpasync16(uint32_t s, const void* g, int sz) {
    asm volatile("cp.async.ca.shared.global [%0], [%1], 16, %2;" :: "r"(s), "l"(g), "r"(sz));
}
__device__ __forceinline__ void cp_commit() { asm volatile("cp.async.commit_group;"); }
__device__ __forceinline__ void cp_wait2()  { asm volatile("cp.async.wait_group 2;"); }

__device__ __forceinline__ void ldsm4(uint32_t& r0, uint32_t& r1, uint32_t& r2, uint32_t& r3,
                                      uint32_t a) {
    asm volatile("ldmatrix.sync.aligned.m8n8.x4.shared.b16 {%0,%1,%2,%3}, [%4];"
                 : "=r"(r0), "=r"(r1), "=r"(r2), "=r"(r3) : "r"(a));
}
__device__ __forceinline__ void ldsm4t(uint32_t& r0, uint32_t& r1, uint32_t& r2, uint32_t& r3,
                                       uint32_t a) {
    asm volatile("ldmatrix.sync.aligned.m8n8.x4.trans.shared.b16 {%0,%1,%2,%3}, [%4];"
                 : "=r"(r0), "=r"(r1), "=r"(r2), "=r"(r3) : "r"(a));
}
__device__ __forceinline__ void mma16816(float* c, const uint32_t* a, uint32_t b0, uint32_t b1) {
    asm volatile(
        "mma.sync.aligned.m16n8k16.row.col.f32.f16.f16.f32 "
        "{%0,%1,%2,%3}, {%4,%5,%6,%7}, {%8,%9}, {%0,%1,%2,%3};"
        : "+f"(c[0]), "+f"(c[1]), "+f"(c[2]), "+f"(c[3])
        : "r"(a[0]), "r"(a[1]), "r"(a[2]), "r"(a[3]), "r"(b0), "r"(b1));
}

// ---------------- grouped fp16 tensor-core GEMM ----------------
// C[M,N] (+)= A[M,K] @ B[K,N]; A,B half (row-major), C float or half.
// Tile 64x64, BK=32, 128 threads (2x2 warps, warp tile 32x32), 4-stage cp.async.
struct GemmTask {
    const __half* A; const __half* B; void* C;
    int N, K, acc, ohalf;
    int blk_start, nbn;
};
struct GemmBatch { GemmTask t[8]; int nt; };

#define ASTRB 80     // A smem row stride bytes (32 halves -> pad to 40)
#define BSTRB 144    // B smem row stride bytes (64 halves -> pad to 72)
#define A_SB  5120   // 64 * 80
#define B_SB  4608   // 32 * 144
#define STG   (A_SB + B_SB)     // 9728
#define SM_TOT (4 * STG)        // 38912

__global__ __launch_bounds__(128)
void gemm_h_kernel(GemmBatch batch) {
    extern __shared__ char smem[];
    uint32_t sbase = smem_u32(smem);
    int tid = threadIdx.x;
    int warp = tid >> 5, lane = tid & 31;
    int g = lane >> 2, t = lane & 3;
    int wm = warp & 1, wn = warp >> 1;

    int ti = 0;
    #pragma unroll
    for (int i = 1; i < 8; i++)
        if (i < batch.nt && (int)blockIdx.x >= batch.t[i].blk_start) ti = i;
    GemmTask T = batch.t[ti];
    int local = (int)blockIdx.x - T.blk_start;
    int bm = local / T.nbn, bn = local % T.nbn;
    int row0 = bm * 64, n0 = bn * 64;

    // loader lanes
    int a_row = tid >> 1;                 // 2 ops/thread: (a_row, u), (a_row, u+2)
    int a_u0  = (tid & 1) * 2;
    int b_row = tid >> 2;                 // 2 ops/thread: rows b_row, b_row+... 32 rows x 8 ops = 256
    // Actually map B ops: op o in [0,256): row=o>>3, u=o&7; thread handles o=tid, tid+128.

    float acc[2][4][4];
    #pragma unroll
    for (int mi = 0; mi < 2; mi++)
        #pragma unroll
        for (int ni = 0; ni < 4; ni++)
            #pragma unroll
            for (int c = 0; c < 4; c++) acc[mi][ni][c] = 0.f;

    int nch = (T.K + 31) / 32;

    auto load_stage = [&](int ic) {
        int s = ic & 3;
        int k0 = ic * 32;
        uint32_t sa = sbase + s * STG;
        uint32_t sb = sa + A_SB;
        // A: 64 rows x 32 halves; 4x16B per row
        #pragma unroll
        for (int i = 0; i < 2; i++) {
            int u = a_u0 + i;
            int sz = (k0 + u * 8 < T.K) ? 16 : 0;
            cpasync16(sa + a_row * ASTRB + u * 16,
                      T.A + (size_t)(row0 + a_row) * T.K + k0 + u * 8, sz);
        }
        // B: 32 rows x 64 halves; 8x16B per row
        #pragma unroll
        for (int i = 0; i < 2; i++) {
            int o = tid + i * 128;
            int r = o >> 3, u = o & 7;
            int sz = ((k0 + r < T.K) && (n0 + u * 8 < T.N)) ? 16 : 0;
            cpasync16(sb + r * BSTRB + u * 16,
                      T.B + (size_t)(k0 + r) * T.N + n0 + u * 8, sz);
        }
    };

    // lane offsets for ldmatrix
    uint32_t a_loff = (uint32_t)((wm * 32 + (lane & 15)) * ASTRB + (lane >> 4) * 16);
    uint32_t b_loff = (uint32_t)((lane & 15) * BSTRB + (wn * 32 + (lane >> 4) * 8) * 2);

    // prologue: stages 0..2
    #pragma unroll
    for (int p = 0; p < 3; p++) {
        if (p < nch) load_stage(p);
        cp_commit();
    }

    for (int it = 0; it < nch; it++) {
        int s = it & 3;
        cp_wait2();
        __syncthreads();
        if (it + 3 < nch) load_stage(it + 3);
        cp_commit();

        uint32_t sa = sbase + s * STG;
        uint32_t sb = sa + A_SB;
        #pragma unroll
        for (int kk = 0; kk < 2; kk++) {
            uint32_t af[2][4], bf[4], bg[4];
            ldsm4(af[0][0], af[0][1], af[0][2], af[0][3], sa + a_loff + kk * 32);
            ldsm4(af[1][0], af[1][1], af[1][2], af[1][3], sa + a_loff + 16 * ASTRB + kk * 32);
            ldsm4t(bf[0], bf[1], bf[2], bf[3], sb + b_loff + kk * (16 * BSTRB));
            ldsm4t(bg[0], bg[1], bg[2], bg[3], sb + b_loff + kk * (16 * BSTRB) + 32);
            #pragma unroll
            for (int mi = 0; mi < 2; mi++) {
                mma16816(acc[mi][0], af[mi], bf[0], bf[1]);
                mma16816(acc[mi][1], af[mi], bf[2], bf[3]);
                mma16816(acc[mi][2], af[mi], bg[0], bg[1]);
                mma16816(acc[mi][3], af[mi], bg[2], bg[3]);
            }
        }
        __syncthreads();
    }

    // ---- epilogue (M multiple of 64; guard N) ----
    #pragma unroll
    for (int mi = 0; mi < 2; mi++) {
        int r0 = row0 + wm * 32 + mi * 16 + g;
        #pragma unroll
        for (int ni = 0; ni < 4; ni++) {
            int cb = n0 + wn * 32 + ni * 8 + t * 2;
            if (cb >= T.N) continue;
            if (T.ohalf) {
                __half* C = (__half*)T.C;
                __half2 lo = __floats2half2_rn(acc[mi][ni][0], acc[mi][ni][1]);
                __half2 hi = __floats2half2_rn(acc[mi][ni][2], acc[mi][ni][3]);
                *(__half2*)(C + (size_t)r0 * T.N + cb) = lo;
                *(__half2*)(C + (size_t)(r0 + 8) * T.N + cb) = hi;
            } else {
                float* C = (float*)T.C;
                if (T.acc) {
                    C[(size_t)r0 * T.N + cb]           += acc[mi][ni][0];
                    C[(size_t)r0 * T.N + cb + 1]       += acc[mi][ni][1];
                    C[(size_t)(r0 + 8) * T.N + cb]     += acc[mi][ni][2];
                    C[(size_t)(r0 + 8) * T.N + cb + 1] += acc[mi][ni][3];
                } else {
                    C[(size_t)r0 * T.N + cb]           = acc[mi][ni][0];
                    C[(size_t)r0 * T.N + cb + 1]       = acc[mi][ni][1];
                    C[(size_t)(r0 + 8) * T.N + cb]     = acc[mi][ni][2];
                    C[(size_t)(r0 + 8) * T.N + cb + 1] = acc[mi][ni][3];
                }
            }
        }
    }
}

// ---------------- float -> half convert ----------------
__global__ void f2h_kernel(const float* __restrict__ s, __half* __restrict__ d, size_t n) {
    size_t i = (size_t)blockIdx.x * 256 + threadIdx.x;
    size_t stride = (size_t)gridDim.x * 256;
    for (; i < n; i += stride) d[i] = __float2half(s[i]);
}

// ---------------- RMSNorm ----------------
template<bool TOHALF>
__global__ void rmsnorm_kernel(const float* __restrict__ x, const float* __restrict__ w,
                               void* __restrict__ y, int D) {
    int row = blockIdx.x;
    const float* xr = x + (size_t)row * D;
    __shared__ float red[256];
    float s = 0.f;
    for (int i = threadIdx.x; i < D; i += 256) { float v = xr[i]; s += v * v; }
    red[threadIdx.x] = s; __syncthreads();
    for (int o = 128; o > 0; o >>= 1) {
        if (threadIdx.x < o) red[threadIdx.x] += red[threadIdx.x + o];
        __syncthreads();
    }
    float scale = rsqrtf(red[0] / D + 1e-5f);
    for (int i = threadIdx.x; i < D; i += 256) {
        float v = w[i] * xr[i] * scale;
        if (TOHALF) ((__half*)y)[(size_t)row * D + i] = __float2half(v);
        else        ((float*)y)[(size_t)row * D + i] = v;
    }
}

// ---------------- RoPE in-place on half ----------------
__global__ void rope_kernel(__half* __restrict__ x, const int* __restrict__ pos_ids,
                            int pos_off, int H) {
    int row = blockIdx.x;
    int h = blockIdx.y;
    int j = threadIdx.x;              // 0..31
    float pos = (float)pos_ids[pos_off + row];
    float ts = powf(10000.f, (float)j / 32.f);
    float rad = pos / ts;
    float sn = sinf(rad), cs = cosf(rad);
    __half* p = x + (size_t)row * (H * 64) + h * 64;
    float x1 = __half2float(p[j]), x2 = __half2float(p[j + 32]);
    p[j]      = __float2half(x1 * cs - x2 * sn);
    p[j + 32] = __float2half(x2 * cs + x1 * sn);
}

// ---------------- GQA-fused attention: block = (query row, kv head), 3 q-heads ----------------
__global__ void attn_kernel(const __half* __restrict__ Q, const __half* __restrict__ K,
                            const __half* __restrict__ V, __half* __restrict__ O,
                            int Lk, int mode) {
    int q = blockIdx.x, kvh = blockIdx.y;
    int tid = threadIdx.x;            // 128
    __shared__ float q3[192];
    __shared__ float sc[3][SS];
    __shared__ float red[128];
    __shared__ float mm[3], invs[3];
    __shared__ float pv[384];

    for (int i = tid; i < 192; i += 128) {
        int j = i >> 6, d = i & 63;
        q3[i] = __half2float(Q[(size_t)q * QW + (kvh * 3 + j) * 64 + d]);
    }
    __syncthreads();

    float pm0 = -3.0e38f, pm1 = -3.0e38f, pm2 = -3.0e38f;
    for (int k = tid; k < Lk; k += 128) {
        bool ok = (mode == 0) || (k < PL) || (k <= q);
        const __half2* kp = (const __half2*)(K + (size_t)k * KW + kvh * 64);
        float d0 = 0.f, d1 = 0.f, d2 = 0.f;
        #pragma unroll
        for (int i = 0; i < 32; i++) {
            float2 f = __half22float2(kp[i]);
            d0 += q3[2*i] * f.x + q3[2*i+1] * f.y;
            d1 += q3[64+2*i] * f.x + q3[64+2*i+1] * f.y;
            d2 += q3[128+2*i] * f.x + q3[128+2*i+1] * f.y;
        }
        float s0 = ok ? d0 * 0.125f : -3.0e38f;
        float s1 = ok ? d1 * 0.125f : -3.0e38f;
        float s2 = ok ? d2 * 0.125f : -3.0e38f;
        sc[0][k] = s0; sc[1][k] = s1; sc[2][k] = s2;
        pm0 = fmaxf(pm0, s0); pm1 = fmaxf(pm1, s1); pm2 = fmaxf(pm2, s2);
    }
    float pms[3] = {pm0, pm1, pm2};
    for (int j = 0; j < 3; j++) {
        __syncthreads();
        red[tid] = pms[j]; __syncthreads();
        for (int o = 64; o > 0; o >>= 1) {
            if (tid < o) red[tid] = fmaxf(red[tid], red[tid + o]);
            __syncthreads();
        }
        if (tid == 0) mm[j] = red[0];
    }
    __syncthreads();

    float ps0 = 0.f, ps1 = 0.f, ps2 = 0.f;
    float m0 = mm[0], m1 = mm[1], m2 = mm[2];
    for (int k = tid; k < Lk; k += 128) {
        float e0 = expf(sc[0][k] - m0); sc[0][k] = e0; ps0 += e0;
        float e1 = expf(sc[1][k] - m1); sc[1][k] = e1; ps1 += e1;
        float e2 = expf(sc[2][k] - m2); sc[2][k] = e2; ps2 += e2;
    }
    float pss[3] = {ps0, ps1, ps2};
    for (int j = 0; j < 3; j++) {
        __syncthreads();
        red[tid] = pss[j]; __syncthreads();
        for (int o = 64; o > 0; o >>= 1) {
            if (tid < o) red[tid] += red[tid + o];
            __syncthreads();
        }
        if (tid == 0) invs[j] = 1.f / red[0];
    }
    __syncthreads();

    // PV: 2 k-halves x 64 dims, 3 heads per thread
    {
        int half_ = tid >> 6, d = tid & 63;
        int Lk2 = Lk >> 1;
        int kb = half_ * Lk2, ke = kb + Lk2;
        float a0 = 0.f, a1 = 0.f, a2 = 0.f;
        const __half* vp = V + kvh * 64 + d;
        for (int k = kb; k < ke; k++) {
            float v = __half2float(vp[(size_t)k * KW]);
            a0 += sc[0][k] * v; a1 += sc[1][k] * v; a2 += sc[2][k] * v;
        }
        pv[tid] = a0; pv[128 + tid] = a1; pv[256 + tid] = a2;
    }
    __syncthreads();
    if (tid < 64) {
        #pragma unroll
        for (int j = 0; j < 3; j++) {
            float r = (pv[j * 128 + tid] + pv[j * 128 + tid + 64]) * invs[j];
            O[(size_t)q * QW + (kvh * 3 + j) * 64 + tid] = __float2half(r);
        }
    }
}

// ---------------- silu: o = half(silu(g) * u) ----------------
__global__ void silu_mul_kernel(const float* __restrict__ g, const float* __restrict__ u,
                                __half* __restrict__ o, int n) {
    int i = blockIdx.x * 256 + threadIdx.x;
    if (i < n) {
        float x = g[i];
        o[i] = __float2half((x / (1.f + expf(-x))) * u[i]);
    }
}

// ---------------- host-side grouped-gemm builder ----------------
static inline void batch_init(GemmBatch& b, int& blk) { b.nt = 0; blk = 0; }
static inline void batch_add(GemmBatch& b, int& blk,
                             const __half* A, const __half* B, void* C,
                             int M, int N, int K, int acc, int ohalf) {
    GemmTask& T = b.t[b.nt++];
    T.A = A; T.B = B; T.C = C; T.N = N; T.K = K; T.acc = acc; T.ohalf = ohalf;
    T.nbn = (N + 63) / 64;
    T.blk_start = blk;
    blk += T.nbn * (M / 64);
}
static inline void batch_go(GemmBatch& b, int blk) {
    gemm_h_kernel<<<blk, 128, SM_TOT>>>(b);
}

extern "C" void kernel_launch(void* const* d_in, const int* in_sizes, int n_in,
                              void* d_out, int out_size) {
    const float* in_vlm = (const float*)d_in[0];
    const float* in_exp = (const float*)d_in[1];
    const float* f_vq   = (const float*)d_in[2];
    const float* f_vk   = (const float*)d_in[3];
    const float* f_vv   = (const float*)d_in[4];
    const float* f_vo   = (const float*)d_in[5];
    const float* w_vln1 = (const float*)d_in[6];
    const float* w_vln2 = (const float*)d_in[7];
    const float* f_vg   = (const float*)d_in[8];
    const float* f_vu   = (const float*)d_in[9];
    const float* f_vd   = (const float*)d_in[10];
    const float* w_vfn  = (const float*)d_in[11];
    const float* f_eq   = (const float*)d_in[12];
    const float* f_eks  = (const float*)d_in[13];
    const float* f_evs  = (const float*)d_in[14];
    const float* f_ekc  = (const float*)d_in[15];
    const float* f_evc  = (const float*)d_in[16];
    const float* f_eo   = (const float*)d_in[17];
    const float* w_eln1 = (const float*)d_in[18];
    const float* w_eln2 = (const float*)d_in[19];
    const float* f_eg   = (const float*)d_in[20];
    const float* f_eu   = (const float*)d_in[21];
    const float* f_ed   = (const float*)d_in[22];
    const float* w_efn  = (const float*)d_in[23];
    const int*   pos_ids = (const int*)d_in[24];
    float* out = (float*)d_out;

    __half* wh;
    cudaGetSymbolAddress((void**)&wh, g_wh);
    float *vlm, *exps, *m1, *m2, *e1, *e2;
    __half *hv, *he, *q, *k, *v, *ke, *ve, *att, *m2h, *e2h;
    cudaGetSymbolAddress((void**)&vlm, g_vlm);
    cudaGetSymbolAddress((void**)&exps, g_exp);
    cudaGetSymbolAddress((void**)&m1, g_m1);
    cudaGetSymbolAddress((void**)&m2, g_m2);
    cudaGetSymbolAddress((void**)&e1, g_e1);
    cudaGetSymbolAddress((void**)&e2, g_e2);
    cudaGetSymbolAddress((void**)&hv, h_hv);
    cudaGetSymbolAddress((void**)&he, h_he);
    cudaGetSymbolAddress((void**)&q,  h_q);
    cudaGetSymbolAddress((void**)&k,  h_k);
    cudaGetSymbolAddress((void**)&v,  h_v);
    cudaGetSymbolAddress((void**)&ke, h_ke);
    cudaGetSymbolAddress((void**)&ve, h_ve);
    cudaGetSymbolAddress((void**)&att, h_att);
    cudaGetSymbolAddress((void**)&m2h, h_m2);
    cudaGetSymbolAddress((void**)&e2h, h_e2);

    // ---- convert weights to half (every launch; deterministic) ----
    f2h_kernel<<<2048, 256>>>(f_vq,  wh + O_VQ,  N_VQ);
    f2h_kernel<<<2048, 256>>>(f_vk,  wh + O_VK,  N_VK);
    f2h_kernel<<<2048, 256>>>(f_vv,  wh + O_VV,  N_VV);
    f2h_kernel<<<2048, 256>>>(f_vo,  wh + O_VO,  N_VO);
    f2h_kernel<<<2048, 256>>>(f_vg,  wh + O_VG,  N_VG);
    f2h_kernel<<<2048, 256>>>(f_vu,  wh + O_VU,  N_VU);
    f2h_kernel<<<2048, 256>>>(f_vd,  wh + O_VD,  N_VD);
    f2h_kernel<<<2048, 256>>>(f_eq,  wh + O_EQ,  N_EQ);
    f2h_kernel<<<2048, 256>>>(f_eks, wh + O_EKS, N_EKS);
    f2h_kernel<<<2048, 256>>>(f_evs, wh + O_EVS, N_EVS);
    f2h_kernel<<<2048, 256>>>(f_ekc, wh + O_EKC, N_EKC);
    f2h_kernel<<<2048, 256>>>(f_evc, wh + O_EVC, N_EVC);
    f2h_kernel<<<2048, 256>>>(f_eo,  wh + O_EO,  N_EO);
    f2h_kernel<<<2048, 256>>>(f_eg,  wh + O_EG,  N_EG);
    f2h_kernel<<<2048, 256>>>(f_eu,  wh + O_EU,  N_EU);
    f2h_kernel<<<2048, 256>>>(f_ed,  wh + O_ED,  N_ED);

    cudaMemcpyAsync(vlm,  in_vlm, (size_t)PL * TH * sizeof(float), cudaMemcpyDeviceToDevice);
    cudaMemcpyAsync(exps, in_exp, (size_t)EL * EH * sizeof(float), cudaMemcpyDeviceToDevice);

    GemmBatch b; int blk;

    for (int li = 0; li < L_LAYERS; li++) {
        const __half* vq  = wh + O_VQ  + (size_t)li * TH * QW;
        const __half* vk  = wh + O_VK  + (size_t)li * TH * KW;
        const __half* vv  = wh + O_VV  + (size_t)li * TH * KW;
        const __half* vo  = wh + O_VO  + (size_t)li * QW * TH;
        const __half* vg  = wh + O_VG  + (size_t)li * TH * TI;
        const __half* vu  = wh + O_VU  + (size_t)li * TH * TI;
        const __half* vd  = wh + O_VD  + (size_t)li * TI * TH;
        const __half* eq  = wh + O_EQ  + (size_t)li * EH * QW;
        const __half* eo  = wh + O_EO  + (size_t)li * QW * EH;
        const __half* eg  = wh + O_EG  + (size_t)li * EH * EI;
        const __half* eu  = wh + O_EU  + (size_t)li * EH * EI;
        const __half* ed  = wh + O_ED  + (size_t)li * EI * EH;

        // pre-norms -> half
        rmsnorm_kernel<true><<<PL, 256>>>(vlm,  w_vln1 + (size_t)li * TH, hv, TH);
        rmsnorm_kernel<true><<<EL, 256>>>(exps, w_eln1 + (size_t)li * EH, he, EH);

        if (li % 2 == 0) {
            const __half* eks = wh + O_EKS + (size_t)(li / 2) * EH * KW;
            const __half* evs = wh + O_EVS + (size_t)(li / 2) * EH * KW;
            batch_init(b, blk);
            batch_add(b, blk, hv, vq,  q,                    PL, QW, TH, 0, 1);
            batch_add(b, blk, hv, vk,  k,                    PL, KW, TH, 0, 1);
            batch_add(b, blk, hv, vv,  v,                    PL, KW, TH, 0, 1);
            batch_add(b, blk, he, eq,  q + (size_t)PL * QW,  EL, QW, EH, 0, 1);
            batch_add(b, blk, he, eks, k + (size_t)PL * KW,  EL, KW, EH, 0, 1);
            batch_add(b, blk, he, evs, v + (size_t)PL * KW,  EL, KW, EH, 0, 1);
            batch_go(b, blk);
            rope_kernel<<<dim3(SS, NH),  32>>>(q, pos_ids, 0, NH);
            rope_kernel<<<dim3(SS, NKV), 32>>>(k, pos_ids, 0, NKV);
            attn_kernel<<<dim3(SS, NKV), 128>>>(q, k, v, att, SS, 1);
        } else {
            const __half* ekc = wh + O_EKC + (size_t)(li / 2) * KW * KW;
            const __half* evc = wh + O_EVC + (size_t)(li / 2) * KW * KW;
            batch_init(b, blk);
            batch_add(b, blk, hv, vq, q,                   PL, QW, TH, 0, 1);
            batch_add(b, blk, hv, vk, k,                   PL, KW, TH, 0, 1);
            batch_add(b, blk, hv, vv, v,                   PL, KW, TH, 0, 1);
            batch_add(b, blk, he, eq, q + (size_t)PL * QW, EL, QW, EH, 0, 1);
            batch_go(b, blk);
            rope_kernel<<<dim3(SS, NH),  32>>>(q, pos_ids, 0, NH);
            rope_kernel<<<dim3(PL, NKV), 32>>>(k, pos_ids, 0, NKV);
            batch_init(b, blk);
            batch_add(b, blk, k, ekc, ke, PL, KW, KW, 0, 1);
            batch_add(b, blk, v, evc, ve, PL, KW, KW, 0, 1);
            batch_go(b, blk);
            attn_kernel<<<dim3(PL, NKV), 128>>>(q, k, v, att, PL, 0);
            attn_kernel<<<dim3(EL, NKV), 128>>>(q + (size_t)PL * QW, ke, ve,
                                                att + (size_t)PL * QW, PL, 0);
        }

        // ---- wo (both towers, accumulate into residual) ----
        batch_init(b, blk);
        batch_add(b, blk, att,                    vo, vlm,  PL, TH, QW, 1, 0);
        batch_add(b, blk, att + (size_t)PL * QW,  eo, exps, EL, EH, QW, 1, 0);
        batch_go(b, blk);

        // ---- post-norms ----
        rmsnorm_kernel<true><<<PL, 256>>>(vlm,  w_vln2 + (size_t)li * TH, hv, TH);
        rmsnorm_kernel<true><<<EL, 256>>>(exps, w_eln2 + (size_t)li * EH, he, EH);

        // ---- gate + up (fp32 out) ----
        batch_init(b, blk);
        batch_add(b, blk, hv, vg, m1, PL, TI, TH, 0, 0);
        batch_add(b, blk, hv, vu, m2, PL, TI, TH, 0, 0);
        batch_add(b, blk, he, eg, e1, EL, EI, EH, 0, 0);
        batch_add(b, blk, he, eu, e2, EL, EI, EH, 0, 0);
        batch_go(b, blk);

        silu_mul_kernel<<<(PL * TI + 255) / 256, 256>>>(m1, m2, m2h, PL * TI);
        silu_mul_kernel<<<(EL * EI + 255) / 256, 256>>>(e1, e2, e2h, EL * EI);

        // ---- down (both towers, accumulate) ----
        batch_init(b, blk);
        batch_add(b, blk, m2h, vd, vlm,  PL, TH, TI, 1, 0);
        batch_add(b, blk, e2h, ed, exps, EL, EH, EI, 1, 0);
        batch_go(b, blk);
    }

    // final norms -> fp32 output (vlm first, then expert)
    rmsnorm_kernel<false><<<PL, 256>>>(vlm,  w_vfn, out, TH);
    rmsnorm_kernel<false><<<EL, 256>>>(exps, w_efn, out + (size_t)PL * TH, EH);
}

// round 7
// speedup vs baseline: 8.8504x; 1.0648x over previous
#include <cuda_runtime.h>
#include <cuda_fp16.h>
#include <math.h>
#include <stdint.h>

#define L_LAYERS 16
#define HD 64
#define NH 15
#define NKV 5
#define TH 960
#define TI 2560
#define EH 720
#define EI 2048
#define PL 512
#define EL 128
#define SS 640
#define QW (NH*HD)   // 960
#define KW (NKV*HD)  // 320

// ---------------- weight half cache ----------------
#define N_VQ  ((size_t)L_LAYERS*TH*QW)
#define N_VK  ((size_t)L_LAYERS*TH*KW)
#define N_VV  ((size_t)L_LAYERS*TH*KW)
#define N_VO  ((size_t)L_LAYERS*QW*TH)
#define N_VG  ((size_t)L_LAYERS*TH*TI)
#define N_VU  ((size_t)L_LAYERS*TH*TI)
#define N_VD  ((size_t)L_LAYERS*TI*TH)
#define N_EQ  ((size_t)L_LAYERS*EH*QW)
#define N_EKS ((size_t)(L_LAYERS/2)*EH*KW)
#define N_EVS ((size_t)(L_LAYERS/2)*EH*KW)
#define N_EKC ((size_t)(L_LAYERS/2)*KW*KW)
#define N_EVC ((size_t)(L_LAYERS/2)*KW*KW)
#define N_EO  ((size_t)L_LAYERS*QW*EH)
#define N_EG  ((size_t)L_LAYERS*EH*EI)
#define N_EU  ((size_t)L_LAYERS*EH*EI)
#define N_ED  ((size_t)L_LAYERS*EI*EH)

#define O_VQ  ((size_t)0)
#define O_VK  (O_VQ + N_VQ)
#define O_VV  (O_VK + N_VK)
#define O_VO  (O_VV + N_VV)
#define O_VG  (O_VO + N_VO)
#define O_VU  (O_VG + N_VG)
#define O_VD  (O_VU + N_VU)
#define O_EQ  (O_VD + N_VD)
#define O_EKS (O_EQ + N_EQ)
#define O_EVS (O_EKS + N_EKS)
#define O_EKC (O_EVS + N_EVS)
#define O_EVC (O_EKC + N_EKC)
#define O_EO  (O_EVC + N_EVC)
#define O_EG  (O_EO + N_EO)
#define O_EU  (O_EG + N_EG)
#define O_ED  (O_EU + N_EU)
#define W_TOTAL (O_ED + N_ED)

__device__ __align__(128) __half g_wh[W_TOTAL];

// ---------------- activation / residual scratch ----------------
__device__ __align__(128) float  g_vlm[PL*TH];
__device__ __align__(128) float  g_exp[EL*EH];
__device__ __align__(128) float  g_m1 [PL*TI];
__device__ __align__(128) float  g_m2 [PL*TI];
__device__ __align__(128) float  g_e1 [EL*EI];
__device__ __align__(128) float  g_e2 [EL*EI];
__device__ __align__(128) __half h_hv [PL*TH];
__device__ __align__(128) __half h_he [EL*EH];
__device__ __align__(128) __half h_q  [SS*QW];
__device__ __align__(128) __half h_k  [SS*KW];
__device__ __align__(128) __half h_v  [SS*KW];
__device__ __align__(128) __half h_ke [PL*KW];
__device__ __align__(128) __half h_ve [PL*KW];
__device__ __align__(128) __half h_att[SS*QW];
__device__ __align__(128) __half h_m2 [PL*TI];
__device__ __align__(128) __half h_e2 [EL*EI];

// ---------------- PTX helpers ----------------
__device__ __forceinline__ uint32_t smem_u32(const void* p) {
    uint32_t a;
    asm("{ .reg .u64 t; cvta.to.shared.u64 t, %1; cvt.u32.u64 %0, t; }" : "=r"(a) : "l"(p));
    return a;
}
__device__ __forceinline__ void cpasync16(uint32_t s, const void* g, int sz) {
    asm volatile("cp.async.ca.shared.global [%0], [%1], 16, %2;" :: "r"(s), "l"(g), "r"(sz));
}
__device__ __forceinline__ void cp_commit() { asm volatile("cp.async.commit_group;"); }
__device__ __forceinline__ void cp_wait2()  { asm volatile("cp.async.wait_group 2;"); }

__device__ __forceinline__ void ldsm4(uint32_t& r0, uint32_t& r1, uint32_t& r2, uint32_t& r3,
                                      uint32_t a) {
    asm volatile("ldmatrix.sync.aligned.m8n8.x4.shared.b16 {%0,%1,%2,%3}, [%4];"
                 : "=r"(r0), "=r"(r1), "=r"(r2), "=r"(r3) : "r"(a));
}
__device__ __forceinline__ void ldsm4t(uint32_t& r0, uint32_t& r1, uint32_t& r2, uint32_t& r3,
                                       uint32_t a) {
    asm volatile("ldmatrix.sync.aligned.m8n8.x4.trans.shared.b16 {%0,%1,%2,%3}, [%4];"
                 : "=r"(r0), "=r"(r1), "=r"(r2), "=r"(r3) : "r"(a));
}
__device__ __forceinline__ void mma16816(float* c, const uint32_t* a, uint32_t b0, uint32_t b1) {
    asm volatile(
        "mma.sync.aligned.m16n8k16.row.col.f32.f16.f16.f32 "
        "{%0,%1,%2,%3}, {%4,%5,%6,%7}, {%8,%9}, {%0,%1,%2,%3};"
        : "+f"(c[0]), "+f"(c[1]), "+f"(c[2]), "+f"(c[3])
        : "r"(a[0]), "r"(a[1]), "r"(a[2]), "r"(a[3]), "r"(b0), "r"(b1));
}

// ---------------- grouped fp16 tensor-core GEMM ----------------
// C[M,N] (+)= A[M,K] @ B[K,N]; A,B half row-major; C float or half.
// Tile 128x64, BK=32, 128 threads (2x2 warps, warp tile 64x32), 4-stage cp.async.
struct GemmTask {
    const __half* A; const __half* B; void* C;
    int N, K, acc, ohalf;
    int blk_start, nbn;
};
struct GemmBatch { GemmTask t[8]; int nt; };

#define ASTRB 80      // 32 halves -> 64B, pad to 80
#define BSTRB 144     // 64 halves -> 128B, pad to 144
#define A_SB  10240   // 128 * 80
#define B_SB  4608    // 32 * 144
#define STG   (A_SB + B_SB)     // 14848
#define SM_TOT (4 * STG)        // 59392

__global__ __launch_bounds__(128)
void gemm_h_kernel(GemmBatch batch) {
    extern __shared__ char smem[];
    uint32_t sbase = smem_u32(smem);
    int tid = threadIdx.x;
    int warp = tid >> 5, lane = tid & 31;
    int g = lane >> 2, t = lane & 3;
    int wm = warp & 1, wn = warp >> 1;

    int ti = 0;
    #pragma unroll
    for (int i = 1; i < 8; i++)
        if (i < batch.nt && (int)blockIdx.x >= batch.t[i].blk_start) ti = i;
    GemmTask T = batch.t[ti];
    int local = (int)blockIdx.x - T.blk_start;
    int bm = local / T.nbn, bn = local % T.nbn;
    int row0 = bm * 128, n0 = bn * 64;

    float acc[4][4][4];
    #pragma unroll
    for (int mi = 0; mi < 4; mi++)
        #pragma unroll
        for (int ni = 0; ni < 4; ni++)
            #pragma unroll
            for (int c = 0; c < 4; c++) acc[mi][ni][c] = 0.f;

    int nch = (T.K + 31) / 32;

    auto load_stage = [&](int ic) {
        int s = ic & 3;
        int k0 = ic * 32;
        uint32_t sa = sbase + s * STG;
        uint32_t sb = sa + A_SB;
        // A: 128 rows x 32 halves, 4x16B per row; thread -> row tid, u=0..3
        #pragma unroll
        for (int u = 0; u < 4; u++) {
            int sz = (k0 + u * 8 < T.K) ? 16 : 0;
            cpasync16(sa + tid * ASTRB + u * 16,
                      T.A + (size_t)(row0 + tid) * T.K + k0 + u * 8, sz);
        }
        // B: 32 rows x 64 halves, 8x16B per row; 2 ops/thread
        #pragma unroll
        for (int i = 0; i < 2; i++) {
            int o = tid + i * 128;
            int r = o >> 3, u = o & 7;
            int sz = ((k0 + r < T.K) && (n0 + u * 8 < T.N)) ? 16 : 0;
            cpasync16(sb + r * BSTRB + u * 16,
                      T.B + (size_t)(k0 + r) * T.N + n0 + u * 8, sz);
        }
    };

    uint32_t a_loff = (uint32_t)((wm * 64 + (lane & 15)) * ASTRB + (lane >> 4) * 16);
    uint32_t b_loff = (uint32_t)((lane & 15) * BSTRB + (wn * 32 + (lane >> 4) * 8) * 2);

    #pragma unroll
    for (int p = 0; p < 3; p++) {
        if (p < nch) load_stage(p);
        cp_commit();
    }

    for (int it = 0; it < nch; it++) {
        int s = it & 3;
        cp_wait2();
        __syncthreads();
        if (it + 3 < nch) load_stage(it + 3);
        cp_commit();

        uint32_t sa = sbase + s * STG;
        uint32_t sb = sa + A_SB;
        #pragma unroll
        for (int kk = 0; kk < 2; kk++) {
            uint32_t af[4][4], bf[2][4];
            #pragma unroll
            for (int mi = 0; mi < 4; mi++)
                ldsm4(af[mi][0], af[mi][1], af[mi][2], af[mi][3],
                      sa + a_loff + mi * (16 * ASTRB) + kk * 32);
            ldsm4t(bf[0][0], bf[0][1], bf[0][2], bf[0][3], sb + b_loff + kk * (16 * BSTRB));
            ldsm4t(bf[1][0], bf[1][1], bf[1][2], bf[1][3], sb + b_loff + kk * (16 * BSTRB) + 32);
            #pragma unroll
            for (int mi = 0; mi < 4; mi++) {
                mma16816(acc[mi][0], af[mi], bf[0][0], bf[0][1]);
                mma16816(acc[mi][1], af[mi], bf[0][2], bf[0][3]);
                mma16816(acc[mi][2], af[mi], bf[1][0], bf[1][1]);
                mma16816(acc[mi][3], af[mi], bf[1][2], bf[1][3]);
            }
        }
        __syncthreads();
    }

    // ---- epilogue (M multiple of 128; guard N) ----
    #pragma unroll
    for (int mi = 0; mi < 4; mi++) {
        int r0 = row0 + wm * 64 + mi * 16 + g;
        #pragma unroll
        for (int ni = 0; ni < 4; ni++) {
            int cb = n0 + wn * 32 + ni * 8 + t * 2;
            if (cb >= T.N) continue;
            if (T.ohalf) {
                __half* C = (__half*)T.C;
                *(__half2*)(C + (size_t)r0 * T.N + cb) =
                    __floats2half2_rn(acc[mi][ni][0], acc[mi][ni][1]);
                *(__half2*)(C + (size_t)(r0 + 8) * T.N + cb) =
                    __floats2half2_rn(acc[mi][ni][2], acc[mi][ni][3]);
            } else {
                float* C = (float*)T.C;
                if (T.acc) {
                    C[(size_t)r0 * T.N + cb]           += acc[mi][ni][0];
                    C[(size_t)r0 * T.N + cb + 1]       += acc[mi][ni][1];
                    C[(size_t)(r0 + 8) * T.N + cb]     += acc[mi][ni][2];
                    C[(size_t)(r0 + 8) * T.N + cb + 1] += acc[mi][ni][3];
                } else {
                    C[(size_t)r0 * T.N + cb]           = acc[mi][ni][0];
                    C[(size_t)r0 * T.N + cb + 1]       = acc[mi][ni][1];
                    C[(size_t)(r0 + 8) * T.N + cb]     = acc[mi][ni][2];
                    C[(size_t)(r0 + 8) * T.N + cb + 1] = acc[mi][ni][3];
                }
            }
        }
    }
}

// ---------------- vectorized float -> half ----------------
__global__ void f2h_kernel(const float4* __restrict__ s, uint2* __restrict__ d, size_t n4) {
    size_t i = (size_t)blockIdx.x * 256 + threadIdx.x;
    size_t stride = (size_t)gridDim.x * 256;
    for (; i < n4; i += stride) {
        float4 v = s[i];
        __half2 a = __floats2half2_rn(v.x, v.y);
        __half2 b = __floats2half2_rn(v.z, v.w);
        uint2 o;
        o.x = *(uint32_t*)&a;
        o.y = *(uint32_t*)&b;
        d[i] = o;
    }
}

// ---------------- merged RMSNorm (two tensors, one launch) ----------------
template<bool TOHALF>
__global__ void rms2_kernel(const float* __restrict__ x1, const float* __restrict__ w1,
                            void* __restrict__ y1, int D1, int rows1,
                            const float* __restrict__ x2, const float* __restrict__ w2,
                            void* __restrict__ y2, int D2) {
    int row = blockIdx.x;
    const float* x; const float* w; void* y; int D;
    if (row < rows1) { x = x1 + (size_t)row * D1; w = w1; y = y1; D = D1; }
    else { row -= rows1; x = x2 + (size_t)row * D2; w = w2; y = y2; D = D2; }
    __shared__ float red[256];
    float s = 0.f;
    for (int i = threadIdx.x; i < D; i += 256) { float v = x[i]; s += v * v; }
    red[threadIdx.x] = s; __syncthreads();
    for (int o = 128; o > 0; o >>= 1) {
        if (threadIdx.x < o) red[threadIdx.x] += red[threadIdx.x + o];
        __syncthreads();
    }
    float scale = rsqrtf(red[0] / D + 1e-5f);
    for (int i = threadIdx.x; i < D; i += 256) {
        float v = w[i] * x[i] * scale;
        if (TOHALF) ((__half*)y)[(size_t)row * D + i] = __float2half(v);
        else        ((float*)y)[(size_t)row * D + i] = v;
    }
}

// ---------------- merged RoPE (q + k, one launch) ----------------
__global__ void rope2_kernel(__half* __restrict__ qb, __half* __restrict__ kb,
                             const int* __restrict__ pos_ids, int kRows) {
    int row = blockIdx.x;
    int h = blockIdx.y;
    int j = threadIdx.x;
    __half* p;
    if (h < NH) p = qb + (size_t)row * QW + h * 64;
    else {
        if (row >= kRows) return;
        p = kb + (size_t)row * KW + (h - NH) * 64;
    }
    float pos = (float)pos_ids[row];
    float ts = powf(10000.f, (float)j / 32.f);
    float rad = pos / ts;
    float sn = sinf(rad), cs = cosf(rad);
    float x1 = __half2float(p[j]), x2 = __half2float(p[j + 32]);
    p[j]      = __float2half(x1 * cs - x2 * sn);
    p[j + 32] = __float2half(x2 * cs + x1 * sn);
}

// ---------------- GQA-fused attention ----------------
__global__ void attn_kernel(const __half* __restrict__ Q, const __half* __restrict__ K,
                            const __half* __restrict__ V, __half* __restrict__ O,
                            int Lk, int mode) {
    int q = blockIdx.x, kvh = blockIdx.y;
    int tid = threadIdx.x;            // 128
    __shared__ float q3[192];
    __shared__ float sc[3][SS];
    __shared__ float red[128];
    __shared__ float mm[3], invs[3];
    __shared__ float pv[128][6];

    for (int i = tid; i < 192; i += 128) {
        int j = i >> 6, d = i & 63;
        q3[i] = __half2float(Q[(size_t)q * QW + (kvh * 3 + j) * 64 + d]);
    }
    __syncthreads();

    float pm0 = -3.0e38f, pm1 = -3.0e38f, pm2 = -3.0e38f;
    for (int k = tid; k < Lk; k += 128) {
        bool ok = (mode == 0) || (k < PL) || (k <= q);
        const __half2* kp = (const __half2*)(K + (size_t)k * KW + kvh * 64);
        float d0 = 0.f, d1 = 0.f, d2 = 0.f;
        #pragma unroll
        for (int i = 0; i < 32; i++) {
            float2 f = __half22float2(kp[i]);
            d0 += q3[2*i] * f.x + q3[2*i+1] * f.y;
            d1 += q3[64+2*i] * f.x + q3[64+2*i+1] * f.y;
            d2 += q3[128+2*i] * f.x + q3[128+2*i+1] * f.y;
        }
        float s0 = ok ? d0 * 0.125f : -3.0e38f;
        float s1 = ok ? d1 * 0.125f : -3.0e38f;
        float s2 = ok ? d2 * 0.125f : -3.0e38f;
        sc[0][k] = s0; sc[1][k] = s1; sc[2][k] = s2;
        pm0 = fmaxf(pm0, s0); pm1 = fmaxf(pm1, s1); pm2 = fmaxf(pm2, s2);
    }
    float pms[3] = {pm0, pm1, pm2};
    for (int j = 0; j < 3; j++) {
        __syncthreads();
        red[tid] = pms[j]; __syncthreads();
        for (int o = 64; o > 0; o >>= 1) {
            if (tid < o) red[tid] = fmaxf(red[tid], red[tid + o]);
            __syncthreads();
        }
        if (tid == 0) mm[j] = red[0];
    }
    __syncthreads();

    float ps0 = 0.f, ps1 = 0.f, ps2 = 0.f;
    float m0 = mm[0], m1 = mm[1], m2 = mm[2];
    for (int k = tid; k < Lk; k += 128) {
        float e0 = expf(sc[0][k] - m0); sc[0][k] = e0; ps0 += e0;
        float e1 = expf(sc[1][k] - m1); sc[1][k] = e1; ps1 += e1;
        float e2 = expf(sc[2][k] - m2); sc[2][k] = e2; ps2 += e2;
    }
    float pss[3] = {ps0, ps1, ps2};
    for (int j = 0; j < 3; j++) {
        __syncthreads();
        red[tid] = pss[j]; __syncthreads();
        for (int o = 64; o > 0; o >>= 1) {
            if (tid < o) red[tid] += red[tid + o];
            __syncthreads();
        }
        if (tid == 0) invs[j] = 1.f / red[0];
    }
    __syncthreads();

    // PV: 4 k-quarters x 32 half2 dims, 3 heads
    {
        int quar = tid >> 5, h2 = tid & 31;
        int Lq = Lk >> 2;
        int kb = quar * Lq, kend = kb + Lq;
        float a0x = 0.f, a0y = 0.f, a1x = 0.f, a1y = 0.f, a2x = 0.f, a2y = 0.f;
        const __half2* vp = (const __half2*)(V + kvh * 64) + h2;
        for (int k = kb; k < kend; k++) {
            float2 f = __half22float2(vp[(size_t)k * (KW / 2)]);
            float s0 = sc[0][k], s1 = sc[1][k], s2 = sc[2][k];
            a0x += s0 * f.x; a0y += s0 * f.y;
            a1x += s1 * f.x; a1y += s1 * f.y;
            a2x += s2 * f.x; a2y += s2 * f.y;
        }
        pv[tid][0] = a0x; pv[tid][1] = a0y;
        pv[tid][2] = a1x; pv[tid][3] = a1y;
        pv[tid][4] = a2x; pv[tid][5] = a2y;
    }
    __syncthreads();
    if (tid < 32) {
        #pragma unroll
        for (int j = 0; j < 3; j++) {
            float rx = 0.f, ry = 0.f;
            #pragma unroll
            for (int qq = 0; qq < 4; qq++) {
                rx += pv[qq * 32 + tid][j * 2];
                ry += pv[qq * 32 + tid][j * 2 + 1];
            }
            __half2* op = (__half2*)(O + (size_t)q * QW + (kvh * 3 + j) * 64);
            op[tid] = __floats2half2_rn(rx * invs[j], ry * invs[j]);
        }
    }
}

// ---------------- merged silu (two tensors) ----------------
__global__ void silu2_kernel(const float* __restrict__ g1, const float* __restrict__ u1,
                             __half* __restrict__ o1, int n1,
                             const float* __restrict__ g2, const float* __restrict__ u2,
                             __half* __restrict__ o2, int n2) {
    int i = blockIdx.x * 256 + threadIdx.x;
    if (i < n1) {
        float x = g1[i];
        o1[i] = __float2half((x / (1.f + expf(-x))) * u1[i]);
    } else if (i - n1 < n2) {
        int j = i - n1;
        float x = g2[j];
        o2[j] = __float2half((x / (1.f + expf(-x))) * u2[j]);
    }
}

// ---------------- host-side grouped-gemm builder ----------------
static inline void batch_init(GemmBatch& b, int& blk) { b.nt = 0; blk = 0; }
static inline void batch_add(GemmBatch& b, int& blk,
                             const __half* A, const __half* B, void* C,
                             int M, int N, int K, int acc, int ohalf) {
    GemmTask& T = b.t[b.nt++];
    T.A = A; T.B = B; T.C = C; T.N = N; T.K = K; T.acc = acc; T.ohalf = ohalf;
    T.nbn = (N + 63) / 64;
    T.blk_start = blk;
    blk += T.nbn * (M / 128);
}
static inline void batch_go(GemmBatch& b, int blk) {
    gemm_h_kernel<<<blk, 128, SM_TOT>>>(b);
}

extern "C" void kernel_launch(void* const* d_in, const int* in_sizes, int n_in,
                              void* d_out, int out_size) {
    const float* in_vlm = (const float*)d_in[0];
    const float* in_exp = (const float*)d_in[1];
    const float* f_vq   = (const float*)d_in[2];
    const float* f_vk   = (const float*)d_in[3];
    const float* f_vv   = (const float*)d_in[4];
    const float* f_vo   = (const float*)d_in[5];
    const float* w_vln1 = (const float*)d_in[6];
    const float* w_vln2 = (const float*)d_in[7];
    const float* f_vg   = (const float*)d_in[8];
    const float* f_vu   = (const float*)d_in[9];
    const float* f_vd   = (const float*)d_in[10];
    const float* w_vfn  = (const float*)d_in[11];
    const float* f_eq   = (const float*)d_in[12];
    const float* f_eks  = (const float*)d_in[13];
    const float* f_evs  = (const float*)d_in[14];
    const float* f_ekc  = (const float*)d_in[15];
    const float* f_evc  = (const float*)d_in[16];
    const float* f_eo   = (const float*)d_in[17];
    const float* w_eln1 = (const float*)d_in[18];
    const float* w_eln2 = (const float*)d_in[19];
    const float* f_eg   = (const float*)d_in[20];
    const float* f_eu   = (const float*)d_in[21];
    const float* f_ed   = (const float*)d_in[22];
    const float* w_efn  = (const float*)d_in[23];
    const int*   pos_ids = (const int*)d_in[24];
    float* out = (float*)d_out;

    cudaFuncSetAttribute(gemm_h_kernel,
                         cudaFuncAttributeMaxDynamicSharedMemorySize, SM_TOT);

    __half* wh;
    cudaGetSymbolAddress((void**)&wh, g_wh);
    float *vlm, *exps, *m1, *m2, *e1, *e2;
    __half *hv, *he, *q, *k, *v, *ke, *ve, *att, *m2h, *e2h;
    cudaGetSymbolAddress((void**)&vlm, g_vlm);
    cudaGetSymbolAddress((void**)&exps, g_exp);
    cudaGetSymbolAddress((void**)&m1, g_m1);
    cudaGetSymbolAddress((void**)&m2, g_m2);
    cudaGetSymbolAddress((void**)&e1, g_e1);
    cudaGetSymbolAddress((void**)&e2, g_e2);
    cudaGetSymbolAddress((void**)&hv, h_hv);
    cudaGetSymbolAddress((void**)&he, h_he);
    cudaGetSymbolAddress((void**)&q,  h_q);
    cudaGetSymbolAddress((void**)&k,  h_k);
    cudaGetSymbolAddress((void**)&v,  h_v);
    cudaGetSymbolAddress((void**)&ke, h_ke);
    cudaGetSymbolAddress((void**)&ve, h_ve);
    cudaGetSymbolAddress((void**)&att, h_att);
    cudaGetSymbolAddress((void**)&m2h, h_m2);
    cudaGetSymbolAddress((void**)&e2h, h_e2);

    // ---- convert weights to half ----
    #define CVT(src, off, n) f2h_kernel<<<1024, 256>>>((const float4*)(src), (uint2*)(wh + off), (n) / 4)
    CVT(f_vq,  O_VQ,  N_VQ);  CVT(f_vk,  O_VK,  N_VK);  CVT(f_vv,  O_VV,  N_VV);
    CVT(f_vo,  O_VO,  N_VO);  CVT(f_vg,  O_VG,  N_VG);  CVT(f_vu,  O_VU,  N_VU);
    CVT(f_vd,  O_VD,  N_VD);  CVT(f_eq,  O_EQ,  N_EQ);  CVT(f_eks, O_EKS, N_EKS);
    CVT(f_evs, O_EVS, N_EVS); CVT(f_ekc, O_EKC, N_EKC); CVT(f_evc, O_EVC, N_EVC);
    CVT(f_eo,  O_EO,  N_EO);  CVT(f_eg,  O_EG,  N_EG);  CVT(f_eu,  O_EU,  N_EU);
    CVT(f_ed,  O_ED,  N_ED);
    #undef CVT

    cudaMemcpyAsync(vlm,  in_vlm, (size_t)PL * TH * sizeof(float), cudaMemcpyDeviceToDevice);
    cudaMemcpyAsync(exps, in_exp, (size_t)EL * EH * sizeof(float), cudaMemcpyDeviceToDevice);

    GemmBatch b; int blk;

    for (int li = 0; li < L_LAYERS; li++) {
        const __half* vq  = wh + O_VQ  + (size_t)li * TH * QW;
        const __half* vk  = wh + O_VK  + (size_t)li * TH * KW;
        const __half* vv  = wh + O_VV  + (size_t)li * TH * KW;
        const __half* vo  = wh + O_VO  + (size_t)li * QW * TH;
        const __half* vg  = wh + O_VG  + (size_t)li * TH * TI;
        const __half* vu  = wh + O_VU  + (size_t)li * TH * TI;
        const __half* vd  = wh + O_VD  + (size_t)li * TI * TH;
        const __half* eq  = wh + O_EQ  + (size_t)li * EH * QW;
        const __half* eo  = wh + O_EO  + (size_t)li * QW * EH;
        const __half* eg  = wh + O_EG  + (size_t)li * EH * EI;
        const __half* eu  = wh + O_EU  + (size_t)li * EH * EI;
        const __half* ed  = wh + O_ED  + (size_t)li * EI * EH;

        // pre-norms -> half (merged)
        rms2_kernel<true><<<PL + EL, 256>>>(vlm, w_vln1 + (size_t)li * TH, hv, TH, PL,
                                            exps, w_eln1 + (size_t)li * EH, he, EH);

        if (li % 2 == 0) {
            const __half* eks = wh + O_EKS + (size_t)(li / 2) * EH * KW;
            const __half* evs = wh + O_EVS + (size_t)(li / 2) * EH * KW;
            batch_init(b, blk);
            batch_add(b, blk, hv, vq,  q,                    PL, QW, TH, 0, 1);
            batch_add(b, blk, hv, vk,  k,                    PL, KW, TH, 0, 1);
            batch_add(b, blk, hv, vv,  v,                    PL, KW, TH, 0, 1);
            batch_add(b, blk, he, eq,  q + (size_t)PL * QW,  EL, QW, EH, 0, 1);
            batch_add(b, blk, he, eks, k + (size_t)PL * KW,  EL, KW, EH, 0, 1);
            batch_add(b, blk, he, evs, v + (size_t)PL * KW,  EL, KW, EH, 0, 1);
            batch_go(b, blk);
            rope2_kernel<<<dim3(SS, NH + NKV), 32>>>(q, k, pos_ids, SS);
            attn_kernel<<<dim3(SS, NKV), 128>>>(q, k, v, att, SS, 1);
        } else {
            const __half* ekc = wh + O_EKC + (size_t)(li / 2) * KW * KW;
            const __half* evc = wh + O_EVC + (size_t)(li / 2) * KW * KW;
            batch_init(b, blk);
            batch_add(b, blk, hv, vq, q,                   PL, QW, TH, 0, 1);
            batch_add(b, blk, hv, vk, k,                   PL, KW, TH, 0, 1);
            batch_add(b, blk, hv, vv, v,                   PL, KW, TH, 0, 1);
            batch_add(b, blk, he, eq, q + (size_t)PL * QW, EL, QW, EH, 0, 1);
            batch_go(b, blk);
            rope2_kernel<<<dim3(SS, NH + NKV), 32>>>(q, k, pos_ids, PL);
            batch_init(b, blk);
            batch_add(b, blk, k, ekc, ke, PL, KW, KW, 0, 1);
            batch_add(b, blk, v, evc, ve, PL, KW, KW, 0, 1);
            batch_go(b, blk);
            attn_kernel<<<dim3(PL, NKV), 128>>>(q, k, v, att, PL, 0);
            attn_kernel<<<dim3(EL, NKV), 128>>>(q + (size_t)PL * QW, ke, ve,
                                                att + (size_t)PL * QW, PL, 0);
        }

        // ---- wo (accumulate into residual) ----
        batch_init(b, blk);
        batch_add(b, blk, att,                    vo, vlm,  PL, TH, QW, 1, 0);
        batch_add(b, blk, att + (size_t)PL * QW,  eo, exps, EL, EH, QW, 1, 0);
        batch_go(b, blk);

        // ---- post-norms (merged) ----
        rms2_kernel<true><<<PL + EL, 256>>>(vlm, w_vln2 + (size_t)li * TH, hv, TH, PL,
                                            exps, w_eln2 + (size_t)li * EH, he, EH);

        // ---- gate + up ----
        batch_init(b, blk);
        batch_add(b, blk, hv, vg, m1, PL, TI, TH, 0, 0);
        batch_add(b, blk, hv, vu, m2, PL, TI, TH, 0, 0);
        batch_add(b, blk, he, eg, e1, EL, EI, EH, 0, 0);
        batch_add(b, blk, he, eu, e2, EL, EI, EH, 0, 0);
        batch_go(b, blk);

        silu2_kernel<<<(PL * TI + EL * EI + 255) / 256, 256>>>(
            m1, m2, m2h, PL * TI, e1, e2, e2h, EL * EI);

        // ---- down (accumulate) ----
        batch_init(b, blk);
        batch_add(b, blk, m2h, vd, vlm,  PL, TH, TI, 1, 0);
        batch_add(b, blk, e2h, ed, exps, EL, EH, EI, 1, 0);
        batch_go(b, blk);
    }

    // final norms -> fp32 output (merged)
    rms2_kernel<false><<<PL + EL, 256>>>(vlm, w_vfn, out, TH, PL,
                                         exps, w_efn, out + (size_t)PL * TH, EH);
}

// round 10
// speedup vs baseline: 10.0967x; 1.1408x over previous
// R10: third submission of the R8 design (two broker-side container failures,
// no harness output — treated as infra flake, not a kernel property).
#include <cuda_runtime.h>
#include <cuda_fp16.h>
#include <math.h>
#include <stdint.h>

#define L_LAYERS 16
#define HD 64
#define NH 15
#define NKV 5
#define TH 960
#define TI 2560
#define EH 720
#define EI 2048
#define PL 512
#define EL 128
#define SS 640
#define QW (NH*HD)   // 960
#define KW (NKV*HD)  // 320

// ---------------- weight half cache ----------------
#define N_VQ  ((size_t)L_LAYERS*TH*QW)
#define N_VK  ((size_t)L_LAYERS*TH*KW)
#define N_VV  ((size_t)L_LAYERS*TH*KW)
#define N_VO  ((size_t)L_LAYERS*QW*TH)
#define N_VG  ((size_t)L_LAYERS*TH*TI)
#define N_VU  ((size_t)L_LAYERS*TH*TI)
#define N_VD  ((size_t)L_LAYERS*TI*TH)
#define N_EQ  ((size_t)L_LAYERS*EH*QW)
#define N_EKS ((size_t)(L_LAYERS/2)*EH*KW)
#define N_EVS ((size_t)(L_LAYERS/2)*EH*KW)
#define N_EKC ((size_t)(L_LAYERS/2)*KW*KW)
#define N_EVC ((size_t)(L_LAYERS/2)*KW*KW)
#define N_EO  ((size_t)L_LAYERS*QW*EH)
#define N_EG  ((size_t)L_LAYERS*EH*EI)
#define N_EU  ((size_t)L_LAYERS*EH*EI)
#define N_ED  ((size_t)L_LAYERS*EI*EH)

#define O_VQ  ((size_t)0)
#define O_VK  (O_VQ + N_VQ)
#define O_VV  (O_VK + N_VK)
#define O_VO  (O_VV + N_VV)
#define O_VG  (O_VO + N_VO)
#define O_VU  (O_VG + N_VG)
#define O_VD  (O_VU + N_VU)
#define O_EQ  (O_VD + N_VD)
#define O_EKS (O_EQ + N_EQ)
#define O_EVS (O_EKS + N_EKS)
#define O_EKC (O_EVS + N_EVS)
#define O_EVC (O_EKC + N_EKC)
#define O_EO  (O_EVC + N_EVC)
#define O_EG  (O_EO + N_EO)
#define O_EU  (O_EG + N_EG)
#define O_ED  (O_EU + N_EU)
#define W_TOTAL (O_ED + N_ED)

__device__ __align__(128) __half g_wh[W_TOTAL];

// ---------------- activation / residual scratch ----------------
__device__ __align__(128) float  g_vlm[PL*TH];
__device__ __align__(128) float  g_exp[EL*EH];
__device__ __align__(128) float  g_m1 [PL*TI];
__device__ __align__(128) float  g_m2 [PL*TI];
__device__ __align__(128) float  g_e1 [EL*EI];
__device__ __align__(128) float  g_e2 [EL*EI];
__device__ __align__(128) __half h_hv [PL*TH];
__device__ __align__(128) __half h_he [EL*EH];
__device__ __align__(128) __half h_q  [SS*QW];
__device__ __align__(128) __half h_k  [SS*KW];
__device__ __align__(128) __half h_v  [SS*KW];
__device__ __align__(128) __half h_ke [PL*KW];
__device__ __align__(128) __half h_ve [PL*KW];
__device__ __align__(128) __half h_att[SS*QW];
__device__ __align__(128) __half h_m2 [PL*TI];
__device__ __align__(128) __half h_e2 [EL*EI];

// ---------------- PTX helpers ----------------
__device__ __forceinline__ uint32_t smem_u32(const void* p) {
    uint32_t a;
    asm("{ .reg .u64 t; cvta.to.shared.u64 t, %1; cvt.u32.u64 %0, t; }" : "=r"(a) : "l"(p));
    return a;
}
__device__ __forceinline__ void cpasync16(uint32_t s, const void* g, int sz) {
    asm volatile("cp.async.ca.shared.global [%0], [%1], 16, %2;" :: "r"(s), "l"(g), "r"(sz));
}
__device__ __forceinline__ void cp_commit() { asm volatile("cp.async.commit_group;"); }
__device__ __forceinline__ void cp_wait2()  { asm volatile("cp.async.wait_group 2;"); }

__device__ __forceinline__ void ldsm4(uint32_t& r0, uint32_t& r1, uint32_t& r2, uint32_t& r3,
                                      uint32_t a) {
    asm volatile("ldmatrix.sync.aligned.m8n8.x4.shared.b16 {%0,%1,%2,%3}, [%4];"
                 : "=r"(r0), "=r"(r1), "=r"(r2), "=r"(r3) : "r"(a));
}
__device__ __forceinline__ void ldsm4t(uint32_t& r0, uint32_t& r1, uint32_t& r2, uint32_t& r3,
                                       uint32_t a) {
    asm volatile("ldmatrix.sync.aligned.m8n8.x4.trans.shared.b16 {%0,%1,%2,%3}, [%4];"
                 : "=r"(r0), "=r"(r1), "=r"(r2), "=r"(r3) : "r"(a));
}
__device__ __forceinline__ void mma16816(float* c, const uint32_t* a, uint32_t b0, uint32_t b1) {
    asm volatile(
        "mma.sync.aligned.m16n8k16.row.col.f32.f16.f16.f32 "
        "{%0,%1,%2,%3}, {%4,%5,%6,%7}, {%8,%9}, {%0,%1,%2,%3};"
        : "+f"(c[0]), "+f"(c[1]), "+f"(c[2]), "+f"(c[3])
        : "r"(a[0]), "r"(a[1]), "r"(a[2]), "r"(a[3]), "r"(b0), "r"(b1));
}

// ---------------- grouped fp16 tensor-core GEMM (with split-K) ----------------
struct GemmTask {
    const __half* A; const __half* B; void* C;
    int N, K, acc, ohalf;
    int blk_start, nbn, nbm, split;
};
struct GemmBatch { GemmTask t[8]; int nt; };

#define ASTRB 80      // 32 halves -> 64B, pad to 80
#define BSTRB 144     // 64 halves -> 128B, pad to 144
#define A_SB  10240   // 128 * 80
#define B_SB  4608    // 32 * 144
#define STG   (A_SB + B_SB)     // 14848
#define SM_TOT (4 * STG)        // 59392

__global__ __launch_bounds__(128)
void gemm_h_kernel(GemmBatch batch) {
    extern __shared__ char smem[];
    uint32_t sbase = smem_u32(smem);
    int tid = threadIdx.x;
    int warp = tid >> 5, lane = tid & 31;
    int g = lane >> 2, t = lane & 3;
    int wm = warp & 1, wn = warp >> 1;

    int ti = 0;
    #pragma unroll
    for (int i = 1; i < 8; i++)
        if (i < batch.nt && (int)blockIdx.x >= batch.t[i].blk_start) ti = i;
    GemmTask T = batch.t[ti];
    int local = (int)blockIdx.x - T.blk_start;
    int per = T.nbm * T.nbn;
    int ks = local / per;
    int r2 = local % per;
    int bm = r2 / T.nbn, bn = r2 % T.nbn;
    int row0 = bm * 128, n0 = bn * 64;

    int nchTot = (T.K + 31) / 32;
    int cpers = (nchTot + T.split - 1) / T.split;
    int cb = ks * cpers;
    int ce = cb + cpers; if (ce > nchTot) ce = nchTot;
    if (cb >= ce) return;
    int ke_el = T.K;

    float acc[4][4][4];
    #pragma unroll
    for (int mi = 0; mi < 4; mi++)
        #pragma unroll
        for (int ni = 0; ni < 4; ni++)
            #pragma unroll
            for (int c = 0; c < 4; c++) acc[mi][ni][c] = 0.f;

    auto load_stage = [&](int ic) {
        int s = (ic - cb) & 3;
        int k0 = ic * 32;
        uint32_t sa = sbase + s * STG;
        uint32_t sb = sa + A_SB;
        #pragma unroll
        for (int u = 0; u < 4; u++) {
            int sz = (k0 + u * 8 < ke_el) ? 16 : 0;
            cpasync16(sa + tid * ASTRB + u * 16,
                      T.A + (size_t)(row0 + tid) * T.K + k0 + u * 8, sz);
        }
        #pragma unroll
        for (int i = 0; i < 2; i++) {
            int o = tid + i * 128;
            int r = o >> 3, u = o & 7;
            int sz = ((k0 + r < ke_el) && (n0 + u * 8 < T.N)) ? 16 : 0;
            cpasync16(sb + r * BSTRB + u * 16,
                      T.B + (size_t)(k0 + r) * T.N + n0 + u * 8, sz);
        }
    };

    uint32_t a_loff = (uint32_t)((wm * 64 + (lane & 15)) * ASTRB + (lane >> 4) * 16);
    uint32_t b_loff = (uint32_t)((lane & 15) * BSTRB + (wn * 32 + (lane >> 4) * 8) * 2);

    #pragma unroll
    for (int p = 0; p < 3; p++) {
        if (cb + p < ce) load_stage(cb + p);
        cp_commit();
    }

    for (int it = cb; it < ce; it++) {
        int s = (it - cb) & 3;
        cp_wait2();
        __syncthreads();
        if (it + 3 < ce) load_stage(it + 3);
        cp_commit();

        uint32_t sa = sbase + s * STG;
        uint32_t sb = sa + A_SB;
        #pragma unroll
        for (int kk = 0; kk < 2; kk++) {
            uint32_t af[4][4], bf[2][4];
            #pragma unroll
            for (int mi = 0; mi < 4; mi++)
                ldsm4(af[mi][0], af[mi][1], af[mi][2], af[mi][3],
                      sa + a_loff + mi * (16 * ASTRB) + kk * 32);
            ldsm4t(bf[0][0], bf[0][1], bf[0][2], bf[0][3], sb + b_loff + kk * (16 * BSTRB));
            ldsm4t(bf[1][0], bf[1][1], bf[1][2], bf[1][3], sb + b_loff + kk * (16 * BSTRB) + 32);
            #pragma unroll
            for (int mi = 0; mi < 4; mi++) {
                mma16816(acc[mi][0], af[mi], bf[0][0], bf[0][1]);
                mma16816(acc[mi][1], af[mi], bf[0][2], bf[0][3]);
                mma16816(acc[mi][2], af[mi], bf[1][0], bf[1][1]);
                mma16816(acc[mi][3], af[mi], bf[1][2], bf[1][3]);
            }
        }
        __syncthreads();
    }

    // ---- epilogue ----
    #pragma unroll
    for (int mi = 0; mi < 4; mi++) {
        int r0 = row0 + wm * 64 + mi * 16 + g;
        #pragma unroll
        for (int ni = 0; ni < 4; ni++) {
            int cb2 = n0 + wn * 32 + ni * 8 + t * 2;
            if (cb2 >= T.N) continue;
            if (T.ohalf) {
                __half* C = (__half*)T.C;
                *(__half2*)(C + (size_t)r0 * T.N + cb2) =
                    __floats2half2_rn(acc[mi][ni][0], acc[mi][ni][1]);
                *(__half2*)(C + (size_t)(r0 + 8) * T.N + cb2) =
                    __floats2half2_rn(acc[mi][ni][2], acc[mi][ni][3]);
            } else if (T.split > 1) {
                float* C = (float*)T.C;
                atomicAdd(&C[(size_t)r0 * T.N + cb2],           acc[mi][ni][0]);
                atomicAdd(&C[(size_t)r0 * T.N + cb2 + 1],       acc[mi][ni][1]);
                atomicAdd(&C[(size_t)(r0 + 8) * T.N + cb2],     acc[mi][ni][2]);
                atomicAdd(&C[(size_t)(r0 + 8) * T.N + cb2 + 1], acc[mi][ni][3]);
            } else {
                float* C = (float*)T.C;
                if (T.acc) {
                    C[(size_t)r0 * T.N + cb2]           += acc[mi][ni][0];
                    C[(size_t)r0 * T.N + cb2 + 1]       += acc[mi][ni][1];
                    C[(size_t)(r0 + 8) * T.N + cb2]     += acc[mi][ni][2];
                    C[(size_t)(r0 + 8) * T.N + cb2 + 1] += acc[mi][ni][3];
                } else {
                    C[(size_t)r0 * T.N + cb2]           = acc[mi][ni][0];
                    C[(size_t)r0 * T.N + cb2 + 1]       = acc[mi][ni][1];
                    C[(size_t)(r0 + 8) * T.N + cb2]     = acc[mi][ni][2];
                    C[(size_t)(r0 + 8) * T.N + cb2 + 1] = acc[mi][ni][3];
                }
            }
        }
    }
}

// ---------------- fused weight conversion (all 16 tensors, one launch) ----------------
struct CvtBatch {
    const float4* s[16];
    uint2* d[16];
    size_t n4[16];
};
__global__ void cvt_all_kernel(CvtBatch cb) {
    int tsk = blockIdx.y;
    const float4* s = cb.s[tsk];
    uint2* d = cb.d[tsk];
    size_t n4 = cb.n4[tsk];
    size_t i = (size_t)blockIdx.x * 256 + threadIdx.x;
    size_t stride = (size_t)gridDim.x * 256;
    for (; i < n4; i += stride) {
        float4 v = s[i];
        __half2 a = __floats2half2_rn(v.x, v.y);
        __half2 b = __floats2half2_rn(v.z, v.w);
        uint2 o;
        o.x = *(uint32_t*)&a;
        o.y = *(uint32_t*)&b;
        d[i] = o;
    }
}

// ---------------- merged RMSNorm (two tensors, one launch) ----------------
template<bool TOHALF>
__global__ void rms2_kernel(const float* __restrict__ x1, const float* __restrict__ w1,
                            void* __restrict__ y1, int D1, int rows1,
                            const float* __restrict__ x2, const float* __restrict__ w2,
                            void* __restrict__ y2, int D2) {
    int row = blockIdx.x;
    const float* x; const float* w; void* y; int D;
    if (row < rows1) { x = x1 + (size_t)row * D1; w = w1; y = y1; D = D1; }
    else { row -= rows1; x = x2 + (size_t)row * D2; w = w2; y = y2; D = D2; }
    __shared__ float red[256];
    float s = 0.f;
    for (int i = threadIdx.x; i < D; i += 256) { float v = x[i]; s += v * v; }
    red[threadIdx.x] = s; __syncthreads();
    for (int o = 128; o > 0; o >>= 1) {
        if (threadIdx.x < o) red[threadIdx.x] += red[threadIdx.x + o];
        __syncthreads();
    }
    float scale = rsqrtf(red[0] / D + 1e-5f);
    for (int i = threadIdx.x; i < D; i += 256) {
        float v = w[i] * x[i] * scale;
        if (TOHALF) ((__half*)y)[(size_t)row * D + i] = __float2half(v);
        else        ((float*)y)[(size_t)row * D + i] = v;
    }
}

// ---------------- merged RoPE (q + k, one launch) ----------------
__global__ void rope2_kernel(__half* __restrict__ qb, __half* __restrict__ kb,
                             const int* __restrict__ pos_ids, int kRows) {
    int row = blockIdx.x;
    int h = blockIdx.y;
    int j = threadIdx.x;
    __half* p;
    if (h < NH) p = qb + (size_t)row * QW + h * 64;
    else {
        if (row >= kRows) return;
        p = kb + (size_t)row * KW + (h - NH) * 64;
    }
    float pos = (float)pos_ids[row];
    float ts = powf(10000.f, (float)j / 32.f);
    float rad = pos / ts;
    float sn = sinf(rad), cs = cosf(rad);
    float x1 = __half2float(p[j]), x2 = __half2float(p[j + 32]);
    p[j]      = __float2half(x1 * cs - x2 * sn);
    p[j + 32] = __float2half(x2 * cs + x1 * sn);
}

// ---------------- GQA-fused attention (ragged key bound) ----------------
__global__ void attn_kernel(const __half* __restrict__ Q, const __half* __restrict__ K,
                            const __half* __restrict__ V, __half* __restrict__ O,
                            int Lk, int mode) {
    int q = blockIdx.x, kvh = blockIdx.y;
    int tid = threadIdx.x;            // 128
    __shared__ float q3[192];
    __shared__ float sc[3][SS];
    __shared__ float red[128];
    __shared__ float mm[3], invs[3];
    __shared__ float pv[128][6];

    int kmax = (mode == 1) ? ((q < PL) ? PL : (q + 1)) : Lk;

    for (int i = tid; i < 192; i += 128) {
        int j = i >> 6, d = i & 63;
        q3[i] = __half2float(Q[(size_t)q * QW + (kvh * 3 + j) * 64 + d]);
    }
    __syncthreads();

    float pm0 = -3.0e38f, pm1 = -3.0e38f, pm2 = -3.0e38f;
    for (int k = tid; k < kmax; k += 128) {
        const __half2* kp = (const __half2*)(K + (size_t)k * KW + kvh * 64);
        float d0 = 0.f, d1 = 0.f, d2 = 0.f;
        #pragma unroll
        for (int i = 0; i < 32; i++) {
            float2 f = __half22float2(kp[i]);
            d0 += q3[2*i] * f.x + q3[2*i+1] * f.y;
            d1 += q3[64+2*i] * f.x + q3[64+2*i+1] * f.y;
            d2 += q3[128+2*i] * f.x + q3[128+2*i+1] * f.y;
        }
        float s0 = d0 * 0.125f, s1 = d1 * 0.125f, s2 = d2 * 0.125f;
        sc[0][k] = s0; sc[1][k] = s1; sc[2][k] = s2;
        pm0 = fmaxf(pm0, s0); pm1 = fmaxf(pm1, s1); pm2 = fmaxf(pm2, s2);
    }
    float pms[3] = {pm0, pm1, pm2};
    for (int j = 0; j < 3; j++) {
        __syncthreads();
        red[tid] = pms[j]; __syncthreads();
        for (int o = 64; o > 0; o >>= 1) {
            if (tid < o) red[tid] = fmaxf(red[tid], red[tid + o]);
            __syncthreads();
        }
        if (tid == 0) mm[j] = red[0];
    }
    __syncthreads();

    float ps0 = 0.f, ps1 = 0.f, ps2 = 0.f;
    float m0 = mm[0], m1 = mm[1], m2 = mm[2];
    for (int k = tid; k < kmax; k += 128) {
        float e0 = __expf(sc[0][k] - m0); sc[0][k] = e0; ps0 += e0;
        float e1 = __expf(sc[1][k] - m1); sc[1][k] = e1; ps1 += e1;
        float e2 = __expf(sc[2][k] - m2); sc[2][k] = e2; ps2 += e2;
    }
    float pss[3] = {ps0, ps1, ps2};
    for (int j = 0; j < 3; j++) {
        __syncthreads();
        red[tid] = pss[j]; __syncthreads();
        for (int o = 64; o > 0; o >>= 1) {
            if (tid < o) red[tid] += red[tid + o];
            __syncthreads();
        }
        if (tid == 0) invs[j] = 1.f / red[0];
    }
    __syncthreads();

    {
        int quar = tid >> 5, h2 = tid & 31;
        int Lq = kmax >> 2;
        int kb = quar * Lq;
        int kend = (quar == 3) ? kmax : (kb + Lq);
        float a0x = 0.f, a0y = 0.f, a1x = 0.f, a1y = 0.f, a2x = 0.f, a2y = 0.f;
        const __half2* vp = (const __half2*)(V + kvh * 64) + h2;
        for (int k = kb; k < kend; k++) {
            float2 f = __half22float2(vp[(size_t)k * (KW / 2)]);
            float s0 = sc[0][k], s1 = sc[1][k], s2 = sc[2][k];
            a0x += s0 * f.x; a0y += s0 * f.y;
            a1x += s1 * f.x; a1y += s1 * f.y;
            a2x += s2 * f.x; a2y += s2 * f.y;
        }
        pv[tid][0] = a0x; pv[tid][1] = a0y;
        pv[tid][2] = a1x; pv[tid][3] = a1y;
        pv[tid][4] = a2x; pv[tid][5] = a2y;
    }
    __syncthreads();
    if (tid < 32) {
        #pragma unroll
        for (int j = 0; j < 3; j++) {
            float rx = 0.f, ry = 0.f;
            #pragma unroll
            for (int qq = 0; qq < 4; qq++) {
                rx += pv[qq * 32 + tid][j * 2];
                ry += pv[qq * 32 + tid][j * 2 + 1];
            }
            __half2* op = (__half2*)(O + (size_t)q * QW + (kvh * 3 + j) * 64);
            op[tid] = __floats2half2_rn(rx * invs[j], ry * invs[j]);
        }
    }
}

// ---------------- merged silu (two tensors) ----------------
__global__ void silu2_kernel(const float* __restrict__ g1, const float* __restrict__ u1,
                             __half* __restrict__ o1, int n1,
                             const float* __restrict__ g2, const float* __restrict__ u2,
                             __half* __restrict__ o2, int n2) {
    int i = blockIdx.x * 256 + threadIdx.x;
    if (i < n1) {
        float x = g1[i];
        o1[i] = __float2half((x / (1.f + __expf(-x))) * u1[i]);
    } else if (i - n1 < n2) {
        int j = i - n1;
        float x = g2[j];
        o2[j] = __float2half((x / (1.f + __expf(-x))) * u2[j]);
    }
}

// ---------------- host-side grouped-gemm builder ----------------
static inline void batch_init(GemmBatch& b, int& blk) { b.nt = 0; blk = 0; }
static inline void batch_add(GemmBatch& b, int& blk,
                             const __half* A, const __half* B, void* C,
                             int M, int N, int K, int acc, int ohalf, int split = 1) {
    GemmTask& T = b.t[b.nt++];
    T.A = A; T.B = B; T.C = C; T.N = N; T.K = K; T.acc = acc; T.ohalf = ohalf;
    T.nbn = (N + 63) / 64;
    T.nbm = M / 128;
    T.split = split;
    T.blk_start = blk;
    blk += T.nbn * T.nbm * split;
}
static inline void batch_go(GemmBatch& b, int blk) {
    gemm_h_kernel<<<blk, 128, SM_TOT>>>(b);
}

extern "C" void kernel_launch(void* const* d_in, const int* in_sizes, int n_in,
                              void* d_out, int out_size) {
    const float* in_vlm = (const float*)d_in[0];
    const float* in_exp = (const float*)d_in[1];
    const float* f_vq   = (const float*)d_in[2];
    const float* f_vk   = (const float*)d_in[3];
    const float* f_vv   = (const float*)d_in[4];
    const float* f_vo   = (const float*)d_in[5];
    const float* w_vln1 = (const float*)d_in[6];
    const float* w_vln2 = (const float*)d_in[7];
    const float* f_vg   = (const float*)d_in[8];
    const float* f_vu   = (const float*)d_in[9];
    const float* f_vd   = (const float*)d_in[10];
    const float* w_vfn  = (const float*)d_in[11];
    const float* f_eq   = (const float*)d_in[12];
    const float* f_eks  = (const float*)d_in[13];
    const float* f_evs  = (const float*)d_in[14];
    const float* f_ekc  = (const float*)d_in[15];
    const float* f_evc  = (const float*)d_in[16];
    const float* f_eo   = (const float*)d_in[17];
    const float* w_eln1 = (const float*)d_in[18];
    const float* w_eln2 = (const float*)d_in[19];
    const float* f_eg   = (const float*)d_in[20];
    const float* f_eu   = (const float*)d_in[21];
    const float* f_ed   = (const float*)d_in[22];
    const float* w_efn  = (const float*)d_in[23];
    const int*   pos_ids = (const int*)d_in[24];
    float* out = (float*)d_out;

    cudaFuncSetAttribute(gemm_h_kernel,
                         cudaFuncAttributeMaxDynamicSharedMemorySize, SM_TOT);

    __half* wh;
    cudaGetSymbolAddress((void**)&wh, g_wh);
    float *vlm, *exps, *m1, *m2, *e1, *e2;
    __half *hv, *he, *q, *k, *v, *ke, *ve, *att, *m2h, *e2h;
    cudaGetSymbolAddress((void**)&vlm, g_vlm);
    cudaGetSymbolAddress((void**)&exps, g_exp);
    cudaGetSymbolAddress((void**)&m1, g_m1);
    cudaGetSymbolAddress((void**)&m2, g_m2);
    cudaGetSymbolAddress((void**)&e1, g_e1);
    cudaGetSymbolAddress((void**)&e2, g_e2);
    cudaGetSymbolAddress((void**)&hv, h_hv);
    cudaGetSymbolAddress((void**)&he, h_he);
    cudaGetSymbolAddress((void**)&q,  h_q);
    cudaGetSymbolAddress((void**)&k,  h_k);
    cudaGetSymbolAddress((void**)&v,  h_v);
    cudaGetSymbolAddress((void**)&ke, h_ke);
    cudaGetSymbolAddress((void**)&ve, h_ve);
    cudaGetSymbolAddress((void**)&att, h_att);
    cudaGetSymbolAddress((void**)&m2h, h_m2);
    cudaGetSymbolAddress((void**)&e2h, h_e2);

    // ---- convert all weights to half in ONE launch ----
    {
        CvtBatch cb;
        const float* srcs[16] = {f_vq, f_vk, f_vv, f_vo, f_vg, f_vu, f_vd, f_eq,
                                 f_eks, f_evs, f_ekc, f_evc, f_eo, f_eg, f_eu, f_ed};
        size_t offs[16] = {O_VQ, O_VK, O_VV, O_VO, O_VG, O_VU, O_VD, O_EQ,
                           O_EKS, O_EVS, O_EKC, O_EVC, O_EO, O_EG, O_EU, O_ED};
        size_t ns[16] = {N_VQ, N_VK, N_VV, N_VO, N_VG, N_VU, N_VD, N_EQ,
                         N_EKS, N_EVS, N_EKC, N_EVC, N_EO, N_EG, N_EU, N_ED};
        for (int i = 0; i < 16; i++) {
            cb.s[i] = (const float4*)srcs[i];
            cb.d[i] = (uint2*)(wh + offs[i]);
            cb.n4[i] = ns[i] / 4;
        }
        cvt_all_kernel<<<dim3(160, 16), 256>>>(cb);
    }

    cudaMemcpyAsync(vlm,  in_vlm, (size_t)PL * TH * sizeof(float), cudaMemcpyDeviceToDevice);
    cudaMemcpyAsync(exps, in_exp, (size_t)EL * EH * sizeof(float), cudaMemcpyDeviceToDevice);

    GemmBatch b; int blk;

    for (int li = 0; li < L_LAYERS; li++) {
        const __half* vq  = wh + O_VQ  + (size_t)li * TH * QW;
        const __half* vk  = wh + O_VK  + (size_t)li * TH * KW;
        const __half* vv  = wh + O_VV  + (size_t)li * TH * KW;
        const __half* vo  = wh + O_VO  + (size_t)li * QW * TH;
        const __half* vg  = wh + O_VG  + (size_t)li * TH * TI;
        const __half* vu  = wh + O_VU  + (size_t)li * TH * TI;
        const __half* vd  = wh + O_VD  + (size_t)li * TI * TH;
        const __half* eq  = wh + O_EQ  + (size_t)li * EH * QW;
        const __half* eo  = wh + O_EO  + (size_t)li * QW * EH;
        const __half* eg  = wh + O_EG  + (size_t)li * EH * EI;
        const __half* eu  = wh + O_EU  + (size_t)li * EH * EI;
        const __half* ed  = wh + O_ED  + (size_t)li * EI * EH;

        rms2_kernel<true><<<PL + EL, 256>>>(vlm, w_vln1 + (size_t)li * TH, hv, TH, PL,
                                            exps, w_eln1 + (size_t)li * EH, he, EH);

        if (li % 2 == 0) {
            const __half* eks = wh + O_EKS + (size_t)(li / 2) * EH * KW;
            const __half* evs = wh + O_EVS + (size_t)(li / 2) * EH * KW;
            batch_init(b, blk);
            batch_add(b, blk, hv, vq,  q,                    PL, QW, TH, 0, 1);
            batch_add(b, blk, hv, vk,  k,                    PL, KW, TH, 0, 1);
            batch_add(b, blk, hv, vv,  v,                    PL, KW, TH, 0, 1);
            batch_add(b, blk, he, eq,  q + (size_t)PL * QW,  EL, QW, EH, 0, 1);
            batch_add(b, blk, he, eks, k + (size_t)PL * KW,  EL, KW, EH, 0, 1);
            batch_add(b, blk, he, evs, v + (size_t)PL * KW,  EL, KW, EH, 0, 1);
            batch_go(b, blk);
            rope2_kernel<<<dim3(SS, NH + NKV), 32>>>(q, k, pos_ids, SS);
            attn_kernel<<<dim3(SS, NKV), 128>>>(q, k, v, att, SS, 1);
        } else {
            const __half* ekc = wh + O_EKC + (size_t)(li / 2) * KW * KW;
            const __half* evc = wh + O_EVC + (size_t)(li / 2) * KW * KW;
            batch_init(b, blk);
            batch_add(b, blk, hv, vq, q,                   PL, QW, TH, 0, 1);
            batch_add(b, blk, hv, vk, k,                   PL, KW, TH, 0, 1);
            batch_add(b, blk, hv, vv, v,                   PL, KW, TH, 0, 1);
            batch_add(b, blk, he, eq, q + (size_t)PL * QW, EL, QW, EH, 0, 1);
            batch_go(b, blk);
            rope2_kernel<<<dim3(SS, NH + NKV), 32>>>(q, k, pos_ids, PL);
            batch_init(b, blk);
            batch_add(b, blk, k, ekc, ke, PL, KW, KW, 0, 1);
            batch_add(b, blk, v, evc, ve, PL, KW, KW, 0, 1);
            batch_go(b, blk);
            attn_kernel<<<dim3(PL, NKV), 128>>>(q, k, v, att, PL, 0);
            attn_kernel<<<dim3(EL, NKV), 128>>>(q + (size_t)PL * QW, ke, ve,
                                                att + (size_t)PL * QW, PL, 0);
        }

        // ---- wo (split-K, atomic accumulate into residual) ----
        batch_init(b, blk);
        batch_add(b, blk, att,                    vo, vlm,  PL, TH, QW, 1, 0, 2);
        batch_add(b, blk, att + (size_t)PL * QW,  eo, exps, EL, EH, QW, 1, 0, 4);
        batch_go(b, blk);

        rms2_kernel<true><<<PL + EL, 256>>>(vlm, w_vln2 + (size_t)li * TH, hv, TH, PL,
                                            exps, w_eln2 + (size_t)li * EH, he, EH);

        // ---- gate + up ----
        batch_init(b, blk);
        batch_add(b, blk, hv, vg, m1, PL, TI, TH, 0, 0);
        batch_add(b, blk, hv, vu, m2, PL, TI, TH, 0, 0);
        batch_add(b, blk, he, eg, e1, EL, EI, EH, 0, 0);
        batch_add(b, blk, he, eu, e2, EL, EI, EH, 0, 0);
        batch_go(b, blk);

        silu2_kernel<<<(PL * TI + EL * EI + 255) / 256, 256>>>(
            m1, m2, m2h, PL * TI, e1, e2, e2h, EL * EI);

        // ---- down (split-K, atomic accumulate) ----
        batch_init(b, blk);
        batch_add(b, blk, m2h, vd, vlm,  PL, TH, TI, 1, 0, 4);
        batch_add(b, blk, e2h, ed, exps, EL, EH, EI, 1, 0, 4);
        batch_go(b, blk);
    }

    // final norms -> fp32 output (merged)
    rms2_kernel<false><<<PL + EL, 256>>>(vlm, w_vfn, out, TH, PL,
                                         exps, w_efn, out + (size_t)PL * TH, EH);
}

// round 11
// speedup vs baseline: 10.3101x; 1.0211x over previous
// R11: 3-stage pipeline + single-barrier mainloop, 4 blocks/SM; coarsened rope; wo split 3.
#include <cuda_runtime.h>
#include <cuda_fp16.h>
#include <math.h>
#include <stdint.h>

#define L_LAYERS 16
#define HD 64
#define NH 15
#define NKV 5
#define TH 960
#define TI 2560
#define EH 720
#define EI 2048
#define PL 512
#define EL 128
#define SS 640
#define QW (NH*HD)   // 960
#define KW (NKV*HD)  // 320

// ---------------- weight half cache ----------------
#define N_VQ  ((size_t)L_LAYERS*TH*QW)
#define N_VK  ((size_t)L_LAYERS*TH*KW)
#define N_VV  ((size_t)L_LAYERS*TH*KW)
#define N_VO  ((size_t)L_LAYERS*QW*TH)
#define N_VG  ((size_t)L_LAYERS*TH*TI)
#define N_VU  ((size_t)L_LAYERS*TH*TI)
#define N_VD  ((size_t)L_LAYERS*TI*TH)
#define N_EQ  ((size_t)L_LAYERS*EH*QW)
#define N_EKS ((size_t)(L_LAYERS/2)*EH*KW)
#define N_EVS ((size_t)(L_LAYERS/2)*EH*KW)
#define N_EKC ((size_t)(L_LAYERS/2)*KW*KW)
#define N_EVC ((size_t)(L_LAYERS/2)*KW*KW)
#define N_EO  ((size_t)L_LAYERS*QW*EH)
#define N_EG  ((size_t)L_LAYERS*EH*EI)
#define N_EU  ((size_t)L_LAYERS*EH*EI)
#define N_ED  ((size_t)L_LAYERS*EI*EH)

#define O_VQ  ((size_t)0)
#define O_VK  (O_VQ + N_VQ)
#define O_VV  (O_VK + N_VK)
#define O_VO  (O_VV + N_VV)
#define O_VG  (O_VO + N_VO)
#define O_VU  (O_VG + N_VG)
#define O_VD  (O_VU + N_VU)
#define O_EQ  (O_VD + N_VD)
#define O_EKS (O_EQ + N_EQ)
#define O_EVS (O_EKS + N_EKS)
#define O_EKC (O_EVS + N_EVS)
#define O_EVC (O_EKC + N_EKC)
#define O_EO  (O_EVC + N_EVC)
#define O_EG  (O_EO + N_EO)
#define O_EU  (O_EG + N_EG)
#define O_ED  (O_EU + N_EU)
#define W_TOTAL (O_ED + N_ED)

__device__ __align__(128) __half g_wh[W_TOTAL];

// ---------------- activation / residual scratch ----------------
__device__ __align__(128) float  g_vlm[PL*TH];
__device__ __align__(128) float  g_exp[EL*EH];
__device__ __align__(128) float  g_m1 [PL*TI];
__device__ __align__(128) float  g_m2 [PL*TI];
__device__ __align__(128) float  g_e1 [EL*EI];
__device__ __align__(128) float  g_e2 [EL*EI];
__device__ __align__(128) __half h_hv [PL*TH];
__device__ __align__(128) __half h_he [EL*EH];
__device__ __align__(128) __half h_q  [SS*QW];
__device__ __align__(128) __half h_k  [SS*KW];
__device__ __align__(128) __half h_v  [SS*KW];
__device__ __align__(128) __half h_ke [PL*KW];
__device__ __align__(128) __half h_ve [PL*KW];
__device__ __align__(128) __half h_att[SS*QW];
__device__ __align__(128) __half h_m2 [PL*TI];
__device__ __align__(128) __half h_e2 [EL*EI];

// ---------------- PTX helpers ----------------
__device__ __forceinline__ uint32_t smem_u32(const void* p) {
    uint32_t a;
    asm("{ .reg .u64 t; cvta.to.shared.u64 t, %1; cvt.u32.u64 %0, t; }" : "=r"(a) : "l"(p));
    return a;
}
__device__ __forceinline__ void cpasync16(uint32_t s, const void* g, int sz) {
    asm volatile("cp.async.ca.shared.global [%0], [%1], 16, %2;" :: "r"(s), "l"(g), "r"(sz));
}
__device__ __forceinline__ void cp_commit() { asm volatile("cp.async.commit_group;"); }
__device__ __forceinline__ void cp_wait1()  { asm volatile("cp.async.wait_group 1;"); }

__device__ __forceinline__ void ldsm4(uint32_t& r0, uint32_t& r1, uint32_t& r2, uint32_t& r3,
                                      uint32_t a) {
    asm volatile("ldmatrix.sync.aligned.m8n8.x4.shared.b16 {%0,%1,%2,%3}, [%4];"
                 : "=r"(r0), "=r"(r1), "=r"(r2), "=r"(r3) : "r"(a));
}
__device__ __forceinline__ void ldsm4t(uint32_t& r0, uint32_t& r1, uint32_t& r2, uint32_t& r3,
                                       uint32_t a) {
    asm volatile("ldmatrix.sync.aligned.m8n8.x4.trans.shared.b16 {%0,%1,%2,%3}, [%4];"
                 : "=r"(r0), "=r"(r1), "=r"(r2), "=r"(r3) : "r"(a));
}
__device__ __forceinline__ void mma16816(float* c, const uint32_t* a, uint32_t b0, uint32_t b1) {
    asm volatile(
        "mma.sync.aligned.m16n8k16.row.col.f32.f16.f16.f32 "
        "{%0,%1,%2,%3}, {%4,%5,%6,%7}, {%8,%9}, {%0,%1,%2,%3};"
        : "+f"(c[0]), "+f"(c[1]), "+f"(c[2]), "+f"(c[3])
        : "r"(a[0]), "r"(a[1]), "r"(a[2]), "r"(a[3]), "r"(b0), "r"(b1));
}

// ---------------- grouped fp16 tensor-core GEMM (split-K, 3-stage, 1 barrier/chunk) ----------------
struct GemmTask {
    const __half* A; const __half* B; void* C;
    int N, K, acc, ohalf;
    int blk_start, nbn, nbm, split;
};
struct GemmBatch { GemmTask t[8]; int nt; };

#define ASTRB 80      // 32 halves -> 64B, pad to 80
#define BSTRB 144     // 64 halves -> 128B, pad to 144
#define A_SB  10240   // 128 * 80
#define B_SB  4608    // 32 * 144
#define STG   (A_SB + B_SB)     // 14848
#define SM_TOT (3 * STG)        // 44544

__global__ __launch_bounds__(128)
void gemm_h_kernel(GemmBatch batch) {
    extern __shared__ char smem[];
    uint32_t sbase = smem_u32(smem);
    int tid = threadIdx.x;
    int warp = tid >> 5, lane = tid & 31;
    int g = lane >> 2, t = lane & 3;
    int wm = warp & 1, wn = warp >> 1;

    int ti = 0;
    #pragma unroll
    for (int i = 1; i < 8; i++)
        if (i < batch.nt && (int)blockIdx.x >= batch.t[i].blk_start) ti = i;
    GemmTask T = batch.t[ti];
    int local = (int)blockIdx.x - T.blk_start;
    int per = T.nbm * T.nbn;
    int ks = local / per;
    int r2 = local % per;
    int bm = r2 / T.nbn, bn = r2 % T.nbn;
    int row0 = bm * 128, n0 = bn * 64;

    int nchTot = (T.K + 31) / 32;
    int cpers = (nchTot + T.split - 1) / T.split;
    int cb = ks * cpers;
    int ce = cb + cpers; if (ce > nchTot) ce = nchTot;
    if (cb >= ce) return;
    int ke_el = T.K;

    float acc[4][4][4];
    #pragma unroll
    for (int mi = 0; mi < 4; mi++)
        #pragma unroll
        for (int ni = 0; ni < 4; ni++)
            #pragma unroll
            for (int c = 0; c < 4; c++) acc[mi][ni][c] = 0.f;

    // slot for chunk index ic (relative): (ic - cb) % 3
    auto load_stage = [&](int ic) {
        int rel = ic - cb;
        int s = rel - (rel / 3) * 3;
        int k0 = ic * 32;
        uint32_t sa = sbase + s * STG;
        uint32_t sb = sa + A_SB;
        #pragma unroll
        for (int u = 0; u < 4; u++) {
            int sz = (k0 + u * 8 < ke_el) ? 16 : 0;
            cpasync16(sa + tid * ASTRB + u * 16,
                      T.A + (size_t)(row0 + tid) * T.K + k0 + u * 8, sz);
        }
        #pragma unroll
        for (int i = 0; i < 2; i++) {
            int o = tid + i * 128;
            int r = o >> 3, u = o & 7;
            int sz = ((k0 + r < ke_el) && (n0 + u * 8 < T.N)) ? 16 : 0;
            cpasync16(sb + r * BSTRB + u * 16,
                      T.B + (size_t)(k0 + r) * T.N + n0 + u * 8, sz);
        }
    };

    uint32_t a_loff = (uint32_t)((wm * 64 + (lane & 15)) * ASTRB + (lane >> 4) * 16);
    uint32_t b_loff = (uint32_t)((lane & 15) * BSTRB + (wn * 32 + (lane >> 4) * 8) * 2);

    // prologue: stages 0,1
    #pragma unroll
    for (int p = 0; p < 2; p++) {
        if (cb + p < ce) load_stage(cb + p);
        cp_commit();
    }

    for (int it = cb; it < ce; it++) {
        int rel = it - cb;
        int s = rel - (rel / 3) * 3;
        cp_wait1();            // chunk `it` resident (<=1 newer group in flight)
        __syncthreads();       // single barrier: cross-thread cp.async visibility
                               // AND write-after-read guard for slot (it+2)%3 == (it-1)%3
        if (it + 2 < ce) load_stage(it + 2);
        cp_commit();

        uint32_t sa = sbase + s * STG;
        uint32_t sb = sa + A_SB;
        #pragma unroll
        for (int kk = 0; kk < 2; kk++) {
            uint32_t af[4][4], bf[2][4];
            #pragma unroll
            for (int mi = 0; mi < 4; mi++)
                ldsm4(af[mi][0], af[mi][1], af[mi][2], af[mi][3],
                      sa + a_loff + mi * (16 * ASTRB) + kk * 32);
            ldsm4t(bf[0][0], bf[0][1], bf[0][2], bf[0][3], sb + b_loff + kk * (16 * BSTRB));
            ldsm4t(bf[1][0], bf[1][1], bf[1][2], bf[1][3], sb + b_loff + kk * (16 * BSTRB) + 32);
            #pragma unroll
            for (int mi = 0; mi < 4; mi++) {
                mma16816(acc[mi][0], af[mi], bf[0][0], bf[0][1]);
                mma16816(acc[mi][1], af[mi], bf[0][2], bf[0][3]);
                mma16816(acc[mi][2], af[mi], bf[1][0], bf[1][1]);
                mma16816(acc[mi][3], af[mi], bf[1][2], bf[1][3]);
            }
        }
        // no trailing barrier: next iteration's top barrier provides the WAR guard
    }

    // ---- epilogue ----
    #pragma unroll
    for (int mi = 0; mi < 4; mi++) {
        int r0 = row0 + wm * 64 + mi * 16 + g;
        #pragma unroll
        for (int ni = 0; ni < 4; ni++) {
            int cb2 = n0 + wn * 32 + ni * 8 + t * 2;
            if (cb2 >= T.N) continue;
            if (T.ohalf) {
                __half* C = (__half*)T.C;
                *(__half2*)(C + (size_t)r0 * T.N + cb2) =
                    __floats2half2_rn(acc[mi][ni][0], acc[mi][ni][1]);
                *(__half2*)(C + (size_t)(r0 + 8) * T.N + cb2) =
                    __floats2half2_rn(acc[mi][ni][2], acc[mi][ni][3]);
            } else if (T.split > 1) {
                float* C = (float*)T.C;
                atomicAdd(&C[(size_t)r0 * T.N + cb2],           acc[mi][ni][0]);
                atomicAdd(&C[(size_t)r0 * T.N + cb2 + 1],       acc[mi][ni][1]);
                atomicAdd(&C[(size_t)(r0 + 8) * T.N + cb2],     acc[mi][ni][2]);
                atomicAdd(&C[(size_t)(r0 + 8) * T.N + cb2 + 1], acc[mi][ni][3]);
            } else {
                float* C = (float*)T.C;
                if (T.acc) {
                    C[(size_t)r0 * T.N + cb2]           += acc[mi][ni][0];
                    C[(size_t)r0 * T.N + cb2 + 1]       += acc[mi][ni][1];
                    C[(size_t)(r0 + 8) * T.N + cb2]     += acc[mi][ni][2];
                    C[(size_t)(r0 + 8) * T.N + cb2 + 1] += acc[mi][ni][3];
                } else {
                    C[(size_t)r0 * T.N + cb2]           = acc[mi][ni][0];
                    C[(size_t)r0 * T.N + cb2 + 1]       = acc[mi][ni][1];
                    C[(size_t)(r0 + 8) * T.N + cb2]     = acc[mi][ni][2];
                    C[(size_t)(r0 + 8) * T.N + cb2 + 1] = acc[mi][ni][3];
                }
            }
        }
    }
}

// ---------------- fused weight conversion ----------------
struct CvtBatch {
    const float4* s[16];
    uint2* d[16];
    size_t n4[16];
};
__global__ void cvt_all_kernel(CvtBatch cb) {
    int tsk = blockIdx.y;
    const float4* s = cb.s[tsk];
    uint2* d = cb.d[tsk];
    size_t n4 = cb.n4[tsk];
    size_t i = (size_t)blockIdx.x * 256 + threadIdx.x;
    size_t stride = (size_t)gridDim.x * 256;
    for (; i < n4; i += stride) {
        float4 v = s[i];
        __half2 a = __floats2half2_rn(v.x, v.y);
        __half2 b = __floats2half2_rn(v.z, v.w);
        uint2 o;
        o.x = *(uint32_t*)&a;
        o.y = *(uint32_t*)&b;
        d[i] = o;
    }
}

// ---------------- merged RMSNorm ----------------
template<bool TOHALF>
__global__ void rms2_kernel(const float* __restrict__ x1, const float* __restrict__ w1,
                            void* __restrict__ y1, int D1, int rows1,
                            const float* __restrict__ x2, const float* __restrict__ w2,
                            void* __restrict__ y2, int D2) {
    int row = blockIdx.x;
    const float* x; const float* w; void* y; int D;
    if (row < rows1) { x = x1 + (size_t)row * D1; w = w1; y = y1; D = D1; }
    else { row -= rows1; x = x2 + (size_t)row * D2; w = w2; y = y2; D = D2; }
    __shared__ float red[256];
    float s = 0.f;
    for (int i = threadIdx.x; i < D; i += 256) { float v = x[i]; s += v * v; }
    red[threadIdx.x] = s; __syncthreads();
    for (int o = 128; o > 0; o >>= 1) {
        if (threadIdx.x < o) red[threadIdx.x] += red[threadIdx.x + o];
        __syncthreads();
    }
    float scale = rsqrtf(red[0] / D + 1e-5f);
    for (int i = threadIdx.x; i < D; i += 256) {
        float v = w[i] * x[i] * scale;
        if (TOHALF) ((__half*)y)[(size_t)row * D + i] = __float2half(v);
        else        ((float*)y)[(size_t)row * D + i] = v;
    }
}

// ---------------- coarsened RoPE (4 (row,head) pairs per 128-thread block) ----------------
#define RP_HEADS (NH + NKV)     // 20
__global__ void rope2_kernel(__half* __restrict__ qb, __half* __restrict__ kb,
                             const int* __restrict__ pos_ids, int kRows) {
    int pair = blockIdx.x * 4 + (threadIdx.x >> 5);
    if (pair >= SS * RP_HEADS) return;
    int row = pair / RP_HEADS;
    int h = pair - row * RP_HEADS;
    int j = threadIdx.x & 31;
    __half* p;
    if (h < NH) p = qb + (size_t)row * QW + h * 64;
    else {
        if (row >= kRows) return;
        p = kb + (size_t)row * KW + (h - NH) * 64;
    }
    float pos = (float)pos_ids[row];
    float ts = powf(10000.f, (float)j / 32.f);
    float rad = pos / ts;
    float sn = sinf(rad), cs = cosf(rad);
    float x1 = __half2float(p[j]), x2 = __half2float(p[j + 32]);
    p[j]      = __float2half(x1 * cs - x2 * sn);
    p[j + 32] = __float2half(x2 * cs + x1 * sn);
}

// ---------------- GQA-fused attention (ragged key bound) ----------------
__global__ void attn_kernel(const __half* __restrict__ Q, const __half* __restrict__ K,
                            const __half* __restrict__ V, __half* __restrict__ O,
                            int Lk, int mode) {
    int q = blockIdx.x, kvh = blockIdx.y;
    int tid = threadIdx.x;            // 128
    __shared__ float q3[192];
    __shared__ float sc[3][SS];
    __shared__ float red[128];
    __shared__ float mm[3], invs[3];
    __shared__ float pv[128][6];

    int kmax = (mode == 1) ? ((q < PL) ? PL : (q + 1)) : Lk;

    for (int i = tid; i < 192; i += 128) {
        int j = i >> 6, d = i & 63;
        q3[i] = __half2float(Q[(size_t)q * QW + (kvh * 3 + j) * 64 + d]);
    }
    __syncthreads();

    float pm0 = -3.0e38f, pm1 = -3.0e38f, pm2 = -3.0e38f;
    for (int k = tid; k < kmax; k += 128) {
        const __half2* kp = (const __half2*)(K + (size_t)k * KW + kvh * 64);
        float d0 = 0.f, d1 = 0.f, d2 = 0.f;
        #pragma unroll
        for (int i = 0; i < 32; i++) {
            float2 f = __half22float2(kp[i]);
            d0 += q3[2*i] * f.x + q3[2*i+1] * f.y;
            d1 += q3[64+2*i] * f.x + q3[64+2*i+1] * f.y;
            d2 += q3[128+2*i] * f.x + q3[128+2*i+1] * f.y;
        }
        float s0 = d0 * 0.125f, s1 = d1 * 0.125f, s2 = d2 * 0.125f;
        sc[0][k] = s0; sc[1][k] = s1; sc[2][k] = s2;
        pm0 = fmaxf(pm0, s0); pm1 = fmaxf(pm1, s1); pm2 = fmaxf(pm2, s2);
    }
    float pms[3] = {pm0, pm1, pm2};
    for (int j = 0; j < 3; j++) {
        __syncthreads();
        red[tid] = pms[j]; __syncthreads();
        for (int o = 64; o > 0; o >>= 1) {
            if (tid < o) red[tid] = fmaxf(red[tid], red[tid + o]);
            __syncthreads();
        }
        if (tid == 0) mm[j] = red[0];
    }
    __syncthreads();

    float ps0 = 0.f, ps1 = 0.f, ps2 = 0.f;
    float m0 = mm[0], m1 = mm[1], m2 = mm[2];
    for (int k = tid; k < kmax; k += 128) {
        float e0 = __expf(sc[0][k] - m0); sc[0][k] = e0; ps0 += e0;
        float e1 = __expf(sc[1][k] - m1); sc[1][k] = e1; ps1 += e1;
        float e2 = __expf(sc[2][k] - m2); sc[2][k] = e2; ps2 += e2;
    }
    float pss[3] = {ps0, ps1, ps2};
    for (int j = 0; j < 3; j++) {
        __syncthreads();
        red[tid] = pss[j]; __syncthreads();
        for (int o = 64; o > 0; o >>= 1) {
            if (tid < o) red[tid] += red[tid + o];
            __syncthreads();
        }
        if (tid == 0) invs[j] = 1.f / red[0];
    }
    __syncthreads();

    {
        int quar = tid >> 5, h2 = tid & 31;
        int Lq = kmax >> 2;
        int kb = quar * Lq;
        int kend = (quar == 3) ? kmax : (kb + Lq);
        float a0x = 0.f, a0y = 0.f, a1x = 0.f, a1y = 0.f, a2x = 0.f, a2y = 0.f;
        const __half2* vp = (const __half2*)(V + kvh * 64) + h2;
        for (int k = kb; k < kend; k++) {
            float2 f = __half22float2(vp[(size_t)k * (KW / 2)]);
            float s0 = sc[0][k], s1 = sc[1][k], s2 = sc[2][k];
            a0x += s0 * f.x; a0y += s0 * f.y;
            a1x += s1 * f.x; a1y += s1 * f.y;
            a2x += s2 * f.x; a2y += s2 * f.y;
        }
        pv[tid][0] = a0x; pv[tid][1] = a0y;
        pv[tid][2] = a1x; pv[tid][3] = a1y;
        pv[tid][4] = a2x; pv[tid][5] = a2y;
    }
    __syncthreads();
    if (tid < 32) {
        #pragma unroll
        for (int j = 0; j < 3; j++) {
            float rx = 0.f, ry = 0.f;
            #pragma unroll
            for (int qq = 0; qq < 4; qq++) {
                rx += pv[qq * 32 + tid][j * 2];
                ry += pv[qq * 32 + tid][j * 2 + 1];
            }
            __half2* op = (__half2*)(O + (size_t)q * QW + (kvh * 3 + j) * 64);
            op[tid] = __floats2half2_rn(rx * invs[j], ry * invs[j]);
        }
    }
}

// ---------------- merged silu ----------------
__global__ void silu2_kernel(const float* __restrict__ g1, const float* __restrict__ u1,
                             __half* __restrict__ o1, int n1,
                             const float* __restrict__ g2, const float* __restrict__ u2,
                             __half* __restrict__ o2, int n2) {
    int i = blockIdx.x * 256 + threadIdx.x;
    if (i < n1) {
        float x = g1[i];
        o1[i] = __float2half((x / (1.f + __expf(-x))) * u1[i]);
    } else if (i - n1 < n2) {
        int j = i - n1;
        float x = g2[j];
        o2[j] = __float2half((x / (1.f + __expf(-x))) * u2[j]);
    }
}

// ---------------- host-side grouped-gemm builder ----------------
static inline void batch_init(GemmBatch& b, int& blk) { b.nt = 0; blk = 0; }
static inline void batch_add(GemmBatch& b, int& blk,
                             const __half* A, const __half* B, void* C,
                             int M, int N, int K, int acc, int ohalf, int split = 1) {
    GemmTask& T = b.t[b.nt++];
    T.A = A; T.B = B; T.C = C; T.N = N; T.K = K; T.acc = acc; T.ohalf = ohalf;
    T.nbn = (N + 63) / 64;
    T.nbm = M / 128;
    T.split = split;
    T.blk_start = blk;
    blk += T.nbn * T.nbm * split;
}
static inline void batch_go(GemmBatch& b, int blk) {
    gemm_h_kernel<<<blk, 128, SM_TOT>>>(b);
}

extern "C" void kernel_launch(void* const* d_in, const int* in_sizes, int n_in,
                              void* d_out, int out_size) {
    const float* in_vlm = (const float*)d_in[0];
    const float* in_exp = (const float*)d_in[1];
    const float* f_vq   = (const float*)d_in[2];
    const float* f_vk   = (const float*)d_in[3];
    const float* f_vv   = (const float*)d_in[4];
    const float* f_vo   = (const float*)d_in[5];
    const float* w_vln1 = (const float*)d_in[6];
    const float* w_vln2 = (const float*)d_in[7];
    const float* f_vg   = (const float*)d_in[8];
    const float* f_vu   = (const float*)d_in[9];
    const float* f_vd   = (const float*)d_in[10];
    const float* w_vfn  = (const float*)d_in[11];
    const float* f_eq   = (const float*)d_in[12];
    const float* f_eks  = (const float*)d_in[13];
    const float* f_evs  = (const float*)d_in[14];
    const float* f_ekc  = (const float*)d_in[15];
    const float* f_evc  = (const float*)d_in[16];
    const float* f_eo   = (const float*)d_in[17];
    const float* w_eln1 = (const float*)d_in[18];
    const float* w_eln2 = (const float*)d_in[19];
    const float* f_eg   = (const float*)d_in[20];
    const float* f_eu   = (const float*)d_in[21];
    const float* f_ed   = (const float*)d_in[22];
    const float* w_efn  = (const float*)d_in[23];
    const int*   pos_ids = (const int*)d_in[24];
    float* out = (float*)d_out;

    cudaFuncSetAttribute(gemm_h_kernel,
                         cudaFuncAttributeMaxDynamicSharedMemorySize, SM_TOT);

    __half* wh;
    cudaGetSymbolAddress((void**)&wh, g_wh);
    float *vlm, *exps, *m1, *m2, *e1, *e2;
    __half *hv, *he, *q, *k, *v, *ke, *ve, *att, *m2h, *e2h;
    cudaGetSymbolAddress((void**)&vlm, g_vlm);
    cudaGetSymbolAddress((void**)&exps, g_exp);
    cudaGetSymbolAddress((void**)&m1, g_m1);
    cudaGetSymbolAddress((void**)&m2, g_m2);
    cudaGetSymbolAddress((void**)&e1, g_e1);
    cudaGetSymbolAddress((void**)&e2, g_e2);
    cudaGetSymbolAddress((void**)&hv, h_hv);
    cudaGetSymbolAddress((void**)&he, h_he);
    cudaGetSymbolAddress((void**)&q,  h_q);
    cudaGetSymbolAddress((void**)&k,  h_k);
    cudaGetSymbolAddress((void**)&v,  h_v);
    cudaGetSymbolAddress((void**)&ke, h_ke);
    cudaGetSymbolAddress((void**)&ve, h_ve);
    cudaGetSymbolAddress((void**)&att, h_att);
    cudaGetSymbolAddress((void**)&m2h, h_m2);
    cudaGetSymbolAddress((void**)&e2h, h_e2);

    // ---- convert all weights to half in ONE launch ----
    {
        CvtBatch cb;
        const float* srcs[16] = {f_vq, f_vk, f_vv, f_vo, f_vg, f_vu, f_vd, f_eq,
                                 f_eks, f_evs, f_ekc, f_evc, f_eo, f_eg, f_eu, f_ed};
        size_t offs[16] = {O_VQ, O_VK, O_VV, O_VO, O_VG, O_VU, O_VD, O_EQ,
                           O_EKS, O_EVS, O_EKC, O_EVC, O_EO, O_EG, O_EU, O_ED};
        size_t ns[16] = {N_VQ, N_VK, N_VV, N_VO, N_VG, N_VU, N_VD, N_EQ,
                         N_EKS, N_EVS, N_EKC, N_EVC, N_EO, N_EG, N_EU, N_ED};
        for (int i = 0; i < 16; i++) {
            cb.s[i] = (const float4*)srcs[i];
            cb.d[i] = (uint2*)(wh + offs[i]);
            cb.n4[i] = ns[i] / 4;
        }
        cvt_all_kernel<<<dim3(160, 16), 256>>>(cb);
    }

    cudaMemcpyAsync(vlm,  in_vlm, (size_t)PL * TH * sizeof(float), cudaMemcpyDeviceToDevice);
    cudaMemcpyAsync(exps, in_exp, (size_t)EL * EH * sizeof(float), cudaMemcpyDeviceToDevice);

    GemmBatch b; int blk;
    const int ropeBlocks = (SS * RP_HEADS + 3) / 4;   // 3200

    for (int li = 0; li < L_LAYERS; li++) {
        const __half* vq  = wh + O_VQ  + (size_t)li * TH * QW;
        const __half* vk  = wh + O_VK  + (size_t)li * TH * KW;
        const __half* vv  = wh + O_VV  + (size_t)li * TH * KW;
        const __half* vo  = wh + O_VO  + (size_t)li * QW * TH;
        const __half* vg  = wh + O_VG  + (size_t)li * TH * TI;
        const __half* vu  = wh + O_VU  + (size_t)li * TH * TI;
        const __half* vd  = wh + O_VD  + (size_t)li * TI * TH;
        const __half* eq  = wh + O_EQ  + (size_t)li * EH * QW;
        const __half* eo  = wh + O_EO  + (size_t)li * QW * EH;
        const __half* eg  = wh + O_EG  + (size_t)li * EH * EI;
        const __half* eu  = wh + O_EU  + (size_t)li * EH * EI;
        const __half* ed  = wh + O_ED  + (size_t)li * EI * EH;

        rms2_kernel<true><<<PL + EL, 256>>>(vlm, w_vln1 + (size_t)li * TH, hv, TH, PL,
                                            exps, w_eln1 + (size_t)li * EH, he, EH);

        if (li % 2 == 0) {
            const __half* eks = wh + O_EKS + (size_t)(li / 2) * EH * KW;
            const __half* evs = wh + O_EVS + (size_t)(li / 2) * EH * KW;
            batch_init(b, blk);
            batch_add(b, blk, hv, vq,  q,                    PL, QW, TH, 0, 1);
            batch_add(b, blk, hv, vk,  k,                    PL, KW, TH, 0, 1);
            batch_add(b, blk, hv, vv,  v,                    PL, KW, TH, 0, 1);
            batch_add(b, blk, he, eq,  q + (size_t)PL * QW,  EL, QW, EH, 0, 1);
            batch_add(b, blk, he, eks, k + (size_t)PL * KW,  EL, KW, EH, 0, 1);
            batch_add(b, blk, he, evs, v + (size_t)PL * KW,  EL, KW, EH, 0, 1);
            batch_go(b, blk);
            rope2_kernel<<<ropeBlocks, 128>>>(q, k, pos_ids, SS);
            attn_kernel<<<dim3(SS, NKV), 128>>>(q, k, v, att, SS, 1);
        } else {
            const __half* ekc = wh + O_EKC + (size_t)(li / 2) * KW * KW;
            const __half* evc = wh + O_EVC + (size_t)(li / 2) * KW * KW;
            batch_init(b, blk);
            batch_add(b, blk, hv, vq, q,                   PL, QW, TH, 0, 1);
            batch_add(b, blk, hv, vk, k,                   PL, KW, TH, 0, 1);
            batch_add(b, blk, hv, vv, v,                   PL, KW, TH, 0, 1);
            batch_add(b, blk, he, eq, q + (size_t)PL * QW, EL, QW, EH, 0, 1);
            batch_go(b, blk);
            rope2_kernel<<<ropeBlocks, 128>>>(q, k, pos_ids, PL);
            batch_init(b, blk);
            batch_add(b, blk, k, ekc, ke, PL, KW, KW, 0, 1);
            batch_add(b, blk, v, evc, ve, PL, KW, KW, 0, 1);
            batch_go(b, blk);
            attn_kernel<<<dim3(PL, NKV), 128>>>(q, k, v, att, PL, 0);
            attn_kernel<<<dim3(EL, NKV), 128>>>(q + (size_t)PL * QW, ke, ve,
                                                att + (size_t)PL * QW, PL, 0);
        }

        // ---- wo (split-K, atomic accumulate into residual) ----
        batch_init(b, blk);
        batch_add(b, blk, att,                    vo, vlm,  PL, TH, QW, 1, 0, 3);
        batch_add(b, blk, att + (size_t)PL * QW,  eo, exps, EL, EH, QW, 1, 0, 4);
        batch_go(b, blk);

        rms2_kernel<true><<<PL + EL, 256>>>(vlm, w_vln2 + (size_t)li * TH, hv, TH, PL,
                                            exps, w_eln2 + (size_t)li * EH, he, EH);

        // ---- gate + up ----
        batch_init(b, blk);
        batch_add(b, blk, hv, vg, m1, PL, TI, TH, 0, 0);
        batch_add(b, blk, hv, vu, m2, PL, TI, TH, 0, 0);
        batch_add(b, blk, he, eg, e1, EL, EI, EH, 0, 0);
        batch_add(b, blk, he, eu, e2, EL, EI, EH, 0, 0);
        batch_go(b, blk);

        silu2_kernel<<<(PL * TI + EL * EI + 255) / 256, 256>>>(
            m1, m2, m2h, PL * TI, e1, e2, e2h, EL * EI);

        // ---- down (split-K, atomic accumulate) ----
        batch_init(b, blk);
        batch_add(b, blk, m2h, vd, vlm,  PL, TH, TI, 1, 0, 4);
        batch_add(b, blk, e2h, ed, exps, EL, EH, EI, 1, 0, 4);
        batch_go(b, blk);
    }

    // final norms -> fp32 output (merged)
    rms2_kernel<false><<<PL + EL, 256>>>(vlm, w_vfn, out, TH, PL,
                                         exps, w_efn, out + (size_t)PL * TH, EH);
}

// round 12
// speedup vs baseline: 10.4875x; 1.0172x over previous
// R12: per-task tile-M (128/64) + retuned split-K for ~1-wave launches.
#include <cuda_runtime.h>
#include <cuda_fp16.h>
#include <math.h>
#include <stdint.h>

#define L_LAYERS 16
#define HD 64
#define NH 15
#define NKV 5
#define TH 960
#define TI 2560
#define EH 720
#define EI 2048
#define PL 512
#define EL 128
#define SS 640
#define QW (NH*HD)   // 960
#define KW (NKV*HD)  // 320

// ---------------- weight half cache ----------------
#define N_VQ  ((size_t)L_LAYERS*TH*QW)
#define N_VK  ((size_t)L_LAYERS*TH*KW)
#define N_VV  ((size_t)L_LAYERS*TH*KW)
#define N_VO  ((size_t)L_LAYERS*QW*TH)
#define N_VG  ((size_t)L_LAYERS*TH*TI)
#define N_VU  ((size_t)L_LAYERS*TH*TI)
#define N_VD  ((size_t)L_LAYERS*TI*TH)
#define N_EQ  ((size_t)L_LAYERS*EH*QW)
#define N_EKS ((size_t)(L_LAYERS/2)*EH*KW)
#define N_EVS ((size_t)(L_LAYERS/2)*EH*KW)
#define N_EKC ((size_t)(L_LAYERS/2)*KW*KW)
#define N_EVC ((size_t)(L_LAYERS/2)*KW*KW)
#define N_EO  ((size_t)L_LAYERS*QW*EH)
#define N_EG  ((size_t)L_LAYERS*EH*EI)
#define N_EU  ((size_t)L_LAYERS*EH*EI)
#define N_ED  ((size_t)L_LAYERS*EI*EH)

#define O_VQ  ((size_t)0)
#define O_VK  (O_VQ + N_VQ)
#define O_VV  (O_VK + N_VK)
#define O_VO  (O_VV + N_VV)
#define O_VG  (O_VO + N_VO)
#define O_VU  (O_VG + N_VG)
#define O_VD  (O_VU + N_VU)
#define O_EQ  (O_VD + N_VD)
#define O_EKS (O_EQ + N_EQ)
#define O_EVS (O_EKS + N_EKS)
#define O_EKC (O_EVS + N_EVS)
#define O_EVC (O_EKC + N_EKC)
#define O_EO  (O_EVC + N_EVC)
#define O_EG  (O_EO + N_EO)
#define O_EU  (O_EG + N_EG)
#define O_ED  (O_EU + N_EU)
#define W_TOTAL (O_ED + N_ED)

__device__ __align__(128) __half g_wh[W_TOTAL];

// ---------------- activation / residual scratch ----------------
__device__ __align__(128) float  g_vlm[PL*TH];
__device__ __align__(128) float  g_exp[EL*EH];
__device__ __align__(128) float  g_m1 [PL*TI];
__device__ __align__(128) float  g_m2 [PL*TI];
__device__ __align__(128) float  g_e1 [EL*EI];
__device__ __align__(128) float  g_e2 [EL*EI];
__device__ __align__(128) __half h_hv [PL*TH];
__device__ __align__(128) __half h_he [EL*EH];
__device__ __align__(128) __half h_q  [SS*QW];
__device__ __align__(128) __half h_k  [SS*KW];
__device__ __align__(128) __half h_v  [SS*KW];
__device__ __align__(128) __half h_ke [PL*KW];
__device__ __align__(128) __half h_ve [PL*KW];
__device__ __align__(128) __half h_att[SS*QW];
__device__ __align__(128) __half h_m2 [PL*TI];
__device__ __align__(128) __half h_e2 [EL*EI];

// ---------------- PTX helpers ----------------
__device__ __forceinline__ uint32_t smem_u32(const void* p) {
    uint32_t a;
    asm("{ .reg .u64 t; cvta.to.shared.u64 t, %1; cvt.u32.u64 %0, t; }" : "=r"(a) : "l"(p));
    return a;
}
__device__ __forceinline__ void cpasync16(uint32_t s, const void* g, int sz) {
    asm volatile("cp.async.ca.shared.global [%0], [%1], 16, %2;" :: "r"(s), "l"(g), "r"(sz));
}
__device__ __forceinline__ void cp_commit() { asm volatile("cp.async.commit_group;"); }
__device__ __forceinline__ void cp_wait1()  { asm volatile("cp.async.wait_group 1;"); }

__device__ __forceinline__ void ldsm4(uint32_t& r0, uint32_t& r1, uint32_t& r2, uint32_t& r3,
                                      uint32_t a) {
    asm volatile("ldmatrix.sync.aligned.m8n8.x4.shared.b16 {%0,%1,%2,%3}, [%4];"
                 : "=r"(r0), "=r"(r1), "=r"(r2), "=r"(r3) : "r"(a));
}
__device__ __forceinline__ void ldsm4t(uint32_t& r0, uint32_t& r1, uint32_t& r2, uint32_t& r3,
                                       uint32_t a) {
    asm volatile("ldmatrix.sync.aligned.m8n8.x4.trans.shared.b16 {%0,%1,%2,%3}, [%4];"
                 : "=r"(r0), "=r"(r1), "=r"(r2), "=r"(r3) : "r"(a));
}
__device__ __forceinline__ void mma16816(float* c, const uint32_t* a, uint32_t b0, uint32_t b1) {
    asm volatile(
        "mma.sync.aligned.m16n8k16.row.col.f32.f16.f16.f32 "
        "{%0,%1,%2,%3}, {%4,%5,%6,%7}, {%8,%9}, {%0,%1,%2,%3};"
        : "+f"(c[0]), "+f"(c[1]), "+f"(c[2]), "+f"(c[3])
        : "r"(a[0]), "r"(a[1]), "r"(a[2]), "r"(a[3]), "r"(b0), "r"(b1));
}

// ---------------- grouped fp16 GEMM: per-task tile-M (128/64), split-K, 3-stage ----------------
struct GemmTask {
    const __half* A; const __half* B; void* C;
    int N, K, acc, ohalf;
    int blk_start, nbn, nbm, split, tm64;
};
struct GemmBatch { GemmTask t[8]; int nt; };

#define ASTRB 80      // 32 halves -> 64B, pad to 80
#define BSTRB 144     // 64 halves -> 128B, pad to 144
#define A_SB  10240   // 128 * 80 (M64 uses first half)
#define B_SB  4608    // 32 * 144
#define STG   (A_SB + B_SB)     // 14848
#define SM_TOT (3 * STG)        // 44544

__global__ __launch_bounds__(128)
void gemm_h_kernel(GemmBatch batch) {
    extern __shared__ char smem[];
    uint32_t sbase = smem_u32(smem);
    int tid = threadIdx.x;
    int warp = tid >> 5, lane = tid & 31;
    int g = lane >> 2, t = lane & 3;
    int wm = warp & 1, wn = warp >> 1;

    int ti = 0;
    #pragma unroll
    for (int i = 1; i < 8; i++)
        if (i < batch.nt && (int)blockIdx.x >= batch.t[i].blk_start) ti = i;
    GemmTask T = batch.t[ti];
    int local = (int)blockIdx.x - T.blk_start;
    int per = T.nbm * T.nbn;
    int ks = local / per;
    int r2 = local % per;
    int bm = r2 / T.nbn, bn = r2 % T.nbn;
    int tm = T.tm64 ? 64 : 128;
    int row0 = bm * tm, n0 = bn * 64;

    int nchTot = (T.K + 31) / 32;
    int cpers = (nchTot + T.split - 1) / T.split;
    int cb = ks * cpers;
    int ce = cb + cpers; if (ce > nchTot) ce = nchTot;
    if (cb >= ce) return;
    int ke_el = T.K;
    int MI = T.tm64 ? 2 : 4;

    float acc[4][4][4];
    #pragma unroll
    for (int mi = 0; mi < 4; mi++)
        #pragma unroll
        for (int ni = 0; ni < 4; ni++)
            #pragma unroll
            for (int c = 0; c < 4; c++) acc[mi][ni][c] = 0.f;

    auto load_stage = [&](int ic) {
        int rel = ic - cb;
        int s = rel - (rel / 3) * 3;
        int k0 = ic * 32;
        uint32_t sa = sbase + s * STG;
        uint32_t sb = sa + A_SB;
        if (T.tm64) {
            // 64 rows x 32 halves: 2x16B per thread
            int ar = tid >> 1, u0 = (tid & 1) * 2;
            #pragma unroll
            for (int i = 0; i < 2; i++) {
                int u = u0 + i;
                int sz = (k0 + u * 8 < ke_el) ? 16 : 0;
                cpasync16(sa + ar * ASTRB + u * 16,
                          T.A + (size_t)(row0 + ar) * T.K + k0 + u * 8, sz);
            }
        } else {
            // 128 rows x 32 halves: 4x16B per thread (row tid)
            #pragma unroll
            for (int u = 0; u < 4; u++) {
                int sz = (k0 + u * 8 < ke_el) ? 16 : 0;
                cpasync16(sa + tid * ASTRB + u * 16,
                          T.A + (size_t)(row0 + tid) * T.K + k0 + u * 8, sz);
            }
        }
        #pragma unroll
        for (int i = 0; i < 2; i++) {
            int o = tid + i * 128;
            int r = o >> 3, u = o & 7;
            int sz = ((k0 + r < ke_el) && (n0 + u * 8 < T.N)) ? 16 : 0;
            cpasync16(sb + r * BSTRB + u * 16,
                      T.B + (size_t)(k0 + r) * T.N + n0 + u * 8, sz);
        }
    };

    int wmBase = wm * (T.tm64 ? 32 : 64);
    uint32_t a_loff = (uint32_t)((wmBase + (lane & 15)) * ASTRB + (lane >> 4) * 16);
    uint32_t b_loff = (uint32_t)((lane & 15) * BSTRB + (wn * 32 + (lane >> 4) * 8) * 2);

    #pragma unroll
    for (int p = 0; p < 2; p++) {
        if (cb + p < ce) load_stage(cb + p);
        cp_commit();
    }

    for (int it = cb; it < ce; it++) {
        int rel = it - cb;
        int s = rel - (rel / 3) * 3;
        cp_wait1();
        __syncthreads();
        if (it + 2 < ce) load_stage(it + 2);
        cp_commit();

        uint32_t sa = sbase + s * STG;
        uint32_t sb = sa + A_SB;
        if (T.tm64) {
            #pragma unroll
            for (int kk = 0; kk < 2; kk++) {
                uint32_t af[2][4], bf[2][4];
                #pragma unroll
                for (int mi = 0; mi < 2; mi++)
                    ldsm4(af[mi][0], af[mi][1], af[mi][2], af[mi][3],
                          sa + a_loff + mi * (16 * ASTRB) + kk * 32);
                ldsm4t(bf[0][0], bf[0][1], bf[0][2], bf[0][3], sb + b_loff + kk * (16 * BSTRB));
                ldsm4t(bf[1][0], bf[1][1], bf[1][2], bf[1][3], sb + b_loff + kk * (16 * BSTRB) + 32);
                #pragma unroll
                for (int mi = 0; mi < 2; mi++) {
                    mma16816(acc[mi][0], af[mi], bf[0][0], bf[0][1]);
                    mma16816(acc[mi][1], af[mi], bf[0][2], bf[0][3]);
                    mma16816(acc[mi][2], af[mi], bf[1][0], bf[1][1]);
                    mma16816(acc[mi][3], af[mi], bf[1][2], bf[1][3]);
                }
            }
        } else {
            #pragma unroll
            for (int kk = 0; kk < 2; kk++) {
                uint32_t af[4][4], bf[2][4];
                #pragma unroll
                for (int mi = 0; mi < 4; mi++)
                    ldsm4(af[mi][0], af[mi][1], af[mi][2], af[mi][3],
                          sa + a_loff + mi * (16 * ASTRB) + kk * 32);
                ldsm4t(bf[0][0], bf[0][1], bf[0][2], bf[0][3], sb + b_loff + kk * (16 * BSTRB));
                ldsm4t(bf[1][0], bf[1][1], bf[1][2], bf[1][3], sb + b_loff + kk * (16 * BSTRB) + 32);
                #pragma unroll
                for (int mi = 0; mi < 4; mi++) {
                    mma16816(acc[mi][0], af[mi], bf[0][0], bf[0][1]);
                    mma16816(acc[mi][1], af[mi], bf[0][2], bf[0][3]);
                    mma16816(acc[mi][2], af[mi], bf[1][0], bf[1][1]);
                    mma16816(acc[mi][3], af[mi], bf[1][2], bf[1][3]);
                }
            }
        }
    }

    // ---- epilogue ----
    for (int mi = 0; mi < MI; mi++) {
        int r0 = row0 + wmBase + mi * 16 + g;
        #pragma unroll
        for (int ni = 0; ni < 4; ni++) {
            int cb2 = n0 + wn * 32 + ni * 8 + t * 2;
            if (cb2 >= T.N) continue;
            if (T.ohalf) {
                __half* C = (__half*)T.C;
                *(__half2*)(C + (size_t)r0 * T.N + cb2) =
                    __floats2half2_rn(acc[mi][ni][0], acc[mi][ni][1]);
                *(__half2*)(C + (size_t)(r0 + 8) * T.N + cb2) =
                    __floats2half2_rn(acc[mi][ni][2], acc[mi][ni][3]);
            } else if (T.split > 1) {
                float* C = (float*)T.C;
                atomicAdd(&C[(size_t)r0 * T.N + cb2],           acc[mi][ni][0]);
                atomicAdd(&C[(size_t)r0 * T.N + cb2 + 1],       acc[mi][ni][1]);
                atomicAdd(&C[(size_t)(r0 + 8) * T.N + cb2],     acc[mi][ni][2]);
                atomicAdd(&C[(size_t)(r0 + 8) * T.N + cb2 + 1], acc[mi][ni][3]);
            } else {
                float* C = (float*)T.C;
                if (T.acc) {
                    C[(size_t)r0 * T.N + cb2]           += acc[mi][ni][0];
                    C[(size_t)r0 * T.N + cb2 + 1]       += acc[mi][ni][1];
                    C[(size_t)(r0 + 8) * T.N + cb2]     += acc[mi][ni][2];
                    C[(size_t)(r0 + 8) * T.N + cb2 + 1] += acc[mi][ni][3];
                } else {
                    C[(size_t)r0 * T.N + cb2]           = acc[mi][ni][0];
                    C[(size_t)r0 * T.N + cb2 + 1]       = acc[mi][ni][1];
                    C[(size_t)(r0 + 8) * T.N + cb2]     = acc[mi][ni][2];
                    C[(size_t)(r0 + 8) * T.N + cb2 + 1] = acc[mi][ni][3];
                }
            }
        }
    }
}

// ---------------- fused weight conversion ----------------
struct CvtBatch {
    const float4* s[16];
    uint2* d[16];
    size_t n4[16];
};
__global__ void cvt_all_kernel(CvtBatch cb) {
    int tsk = blockIdx.y;
    const float4* s = cb.s[tsk];
    uint2* d = cb.d[tsk];
    size_t n4 = cb.n4[tsk];
    size_t i = (size_t)blockIdx.x * 256 + threadIdx.x;
    size_t stride = (size_t)gridDim.x * 256;
    for (; i < n4; i += stride) {
        float4 v = s[i];
        __half2 a = __floats2half2_rn(v.x, v.y);
        __half2 b = __floats2half2_rn(v.z, v.w);
        uint2 o;
        o.x = *(uint32_t*)&a;
        o.y = *(uint32_t*)&b;
        d[i] = o;
    }
}

// ---------------- merged RMSNorm ----------------
template<bool TOHALF>
__global__ void rms2_kernel(const float* __restrict__ x1, const float* __restrict__ w1,
                            void* __restrict__ y1, int D1, int rows1,
                            const float* __restrict__ x2, const float* __restrict__ w2,
                            void* __restrict__ y2, int D2) {
    int row = blockIdx.x;
    const float* x; const float* w; void* y; int D;
    if (row < rows1) { x = x1 + (size_t)row * D1; w = w1; y = y1; D = D1; }
    else { row -= rows1; x = x2 + (size_t)row * D2; w = w2; y = y2; D = D2; }
    __shared__ float red[256];
    float s = 0.f;
    for (int i = threadIdx.x; i < D; i += 256) { float v = x[i]; s += v * v; }
    red[threadIdx.x] = s; __syncthreads();
    for (int o = 128; o > 0; o >>= 1) {
        if (threadIdx.x < o) red[threadIdx.x] += red[threadIdx.x + o];
        __syncthreads();
    }
    float scale = rsqrtf(red[0] / D + 1e-5f);
    for (int i = threadIdx.x; i < D; i += 256) {
        float v = w[i] * x[i] * scale;
        if (TOHALF) ((__half*)y)[(size_t)row * D + i] = __float2half(v);
        else        ((float*)y)[(size_t)row * D + i] = v;
    }
}

// ---------------- coarsened RoPE ----------------
#define RP_HEADS (NH + NKV)     // 20
__global__ void rope2_kernel(__half* __restrict__ qb, __half* __restrict__ kb,
                             const int* __restrict__ pos_ids, int kRows) {
    int pair = blockIdx.x * 4 + (threadIdx.x >> 5);
    if (pair >= SS * RP_HEADS) return;
    int row = pair / RP_HEADS;
    int h = pair - row * RP_HEADS;
    int j = threadIdx.x & 31;
    __half* p;
    if (h < NH) p = qb + (size_t)row * QW + h * 64;
    else {
        if (row >= kRows) return;
        p = kb + (size_t)row * KW + (h - NH) * 64;
    }
    float pos = (float)pos_ids[row];
    float ts = powf(10000.f, (float)j / 32.f);
    float rad = pos / ts;
    float sn = sinf(rad), cs = cosf(rad);
    float x1 = __half2float(p[j]), x2 = __half2float(p[j + 32]);
    p[j]      = __float2half(x1 * cs - x2 * sn);
    p[j + 32] = __float2half(x2 * cs + x1 * sn);
}

// ---------------- GQA-fused attention (ragged key bound) ----------------
__global__ void attn_kernel(const __half* __restrict__ Q, const __half* __restrict__ K,
                            const __half* __restrict__ V, __half* __restrict__ O,
                            int Lk, int mode) {
    int q = blockIdx.x, kvh = blockIdx.y;
    int tid = threadIdx.x;            // 128
    __shared__ float q3[192];
    __shared__ float sc[3][SS];
    __shared__ float red[128];
    __shared__ float mm[3], invs[3];
    __shared__ float pv[128][6];

    int kmax = (mode == 1) ? ((q < PL) ? PL : (q + 1)) : Lk;

    for (int i = tid; i < 192; i += 128) {
        int j = i >> 6, d = i & 63;
        q3[i] = __half2float(Q[(size_t)q * QW + (kvh * 3 + j) * 64 + d]);
    }
    __syncthreads();

    float pm0 = -3.0e38f, pm1 = -3.0e38f, pm2 = -3.0e38f;
    for (int k = tid; k < kmax; k += 128) {
        const __half2* kp = (const __half2*)(K + (size_t)k * KW + kvh * 64);
        float d0 = 0.f, d1 = 0.f, d2 = 0.f;
        #pragma unroll
        for (int i = 0; i < 32; i++) {
            float2 f = __half22float2(kp[i]);
            d0 += q3[2*i] * f.x + q3[2*i+1] * f.y;
            d1 += q3[64+2*i] * f.x + q3[64+2*i+1] * f.y;
            d2 += q3[128+2*i] * f.x + q3[128+2*i+1] * f.y;
        }
        float s0 = d0 * 0.125f, s1 = d1 * 0.125f, s2 = d2 * 0.125f;
        sc[0][k] = s0; sc[1][k] = s1; sc[2][k] = s2;
        pm0 = fmaxf(pm0, s0); pm1 = fmaxf(pm1, s1); pm2 = fmaxf(pm2, s2);
    }
    float pms[3] = {pm0, pm1, pm2};
    for (int j = 0; j < 3; j++) {
        __syncthreads();
        red[tid] = pms[j]; __syncthreads();
        for (int o = 64; o > 0; o >>= 1) {
            if (tid < o) red[tid] = fmaxf(red[tid], red[tid + o]);
            __syncthreads();
        }
        if (tid == 0) mm[j] = red[0];
    }
    __syncthreads();

    float ps0 = 0.f, ps1 = 0.f, ps2 = 0.f;
    float m0 = mm[0], m1 = mm[1], m2 = mm[2];
    for (int k = tid; k < kmax; k += 128) {
        float e0 = __expf(sc[0][k] - m0); sc[0][k] = e0; ps0 += e0;
        float e1 = __expf(sc[1][k] - m1); sc[1][k] = e1; ps1 += e1;
        float e2 = __expf(sc[2][k] - m2); sc[2][k] = e2; ps2 += e2;
    }
    float pss[3] = {ps0, ps1, ps2};
    for (int j = 0; j < 3; j++) {
        __syncthreads();
        red[tid] = pss[j]; __syncthreads();
        for (int o = 64; o > 0; o >>= 1) {
            if (tid < o) red[tid] += red[tid + o];
            __syncthreads();
        }
        if (tid == 0) invs[j] = 1.f / red[0];
    }
    __syncthreads();

    {
        int quar = tid >> 5, h2 = tid & 31;
        int Lq = kmax >> 2;
        int kb = quar * Lq;
        int kend = (quar == 3) ? kmax : (kb + Lq);
        float a0x = 0.f, a0y = 0.f, a1x = 0.f, a1y = 0.f, a2x = 0.f, a2y = 0.f;
        const __half2* vp = (const __half2*)(V + kvh * 64) + h2;
        for (int k = kb; k < kend; k++) {
            float2 f = __half22float2(vp[(size_t)k * (KW / 2)]);
            float s0 = sc[0][k], s1 = sc[1][k], s2 = sc[2][k];
            a0x += s0 * f.x; a0y += s0 * f.y;
            a1x += s1 * f.x; a1y += s1 * f.y;
            a2x += s2 * f.x; a2y += s2 * f.y;
        }
        pv[tid][0] = a0x; pv[tid][1] = a0y;
        pv[tid][2] = a1x; pv[tid][3] = a1y;
        pv[tid][4] = a2x; pv[tid][5] = a2y;
    }
    __syncthreads();
    if (tid < 32) {
        #pragma unroll
        for (int j = 0; j < 3; j++) {
            float rx = 0.f, ry = 0.f;
            #pragma unroll
            for (int qq = 0; qq < 4; qq++) {
                rx += pv[qq * 32 + tid][j * 2];
                ry += pv[qq * 32 + tid][j * 2 + 1];
            }
            __half2* op = (__half2*)(O + (size_t)q * QW + (kvh * 3 + j) * 64);
            op[tid] = __floats2half2_rn(rx * invs[j], ry * invs[j]);
        }
    }
}

// ---------------- merged silu ----------------
__global__ void silu2_kernel(const float* __restrict__ g1, const float* __restrict__ u1,
                             __half* __restrict__ o1, int n1,
                             const float* __restrict__ g2, const float* __restrict__ u2,
                             __half* __restrict__ o2, int n2) {
    int i = blockIdx.x * 256 + threadIdx.x;
    if (i < n1) {
        float x = g1[i];
        o1[i] = __float2half((x / (1.f + __expf(-x))) * u1[i]);
    } else if (i - n1 < n2) {
        int j = i - n1;
        float x = g2[j];
        o2[j] = __float2half((x / (1.f + __expf(-x))) * u2[j]);
    }
}

// ---------------- host-side grouped-gemm builder ----------------
static inline void batch_init(GemmBatch& b, int& blk) { b.nt = 0; blk = 0; }
static inline void batch_add(GemmBatch& b, int& blk,
                             const __half* A, const __half* B, void* C,
                             int M, int N, int K, int acc, int ohalf,
                             int split = 1, int tm64 = 0) {
    GemmTask& T = b.t[b.nt++];
    T.A = A; T.B = B; T.C = C; T.N = N; T.K = K; T.acc = acc; T.ohalf = ohalf;
    T.tm64 = tm64;
    T.nbn = (N + 63) / 64;
    T.nbm = M / (tm64 ? 64 : 128);
    T.split = split;
    T.blk_start = blk;
    blk += T.nbn * T.nbm * split;
}
static inline void batch_go(GemmBatch& b, int blk) {
    gemm_h_kernel<<<blk, 128, SM_TOT>>>(b);
}

extern "C" void kernel_launch(void* const* d_in, const int* in_sizes, int n_in,
                              void* d_out, int out_size) {
    const float* in_vlm = (const float*)d_in[0];
    const float* in_exp = (const float*)d_in[1];
    const float* f_vq   = (const float*)d_in[2];
    const float* f_vk   = (const float*)d_in[3];
    const float* f_vv   = (const float*)d_in[4];
    const float* f_vo   = (const float*)d_in[5];
    const float* w_vln1 = (const float*)d_in[6];
    const float* w_vln2 = (const float*)d_in[7];
    const float* f_vg   = (const float*)d_in[8];
    const float* f_vu   = (const float*)d_in[9];
    const float* f_vd   = (const float*)d_in[10];
    const float* w_vfn  = (const float*)d_in[11];
    const float* f_eq   = (const float*)d_in[12];
    const float* f_eks  = (const float*)d_in[13];
    const float* f_evs  = (const float*)d_in[14];
    const float* f_ekc  = (const float*)d_in[15];
    const float* f_evc  = (const float*)d_in[16];
    const float* f_eo   = (const float*)d_in[17];
    const float* w_eln1 = (const float*)d_in[18];
    const float* w_eln2 = (const float*)d_in[19];
    const float* f_eg   = (const float*)d_in[20];
    const float* f_eu   = (const float*)d_in[21];
    const float* f_ed   = (const float*)d_in[22];
    const float* w_efn  = (const float*)d_in[23];
    const int*   pos_ids = (const int*)d_in[24];
    float* out = (float*)d_out;

    cudaFuncSetAttribute(gemm_h_kernel,
                         cudaFuncAttributeMaxDynamicSharedMemorySize, SM_TOT);

    __half* wh;
    cudaGetSymbolAddress((void**)&wh, g_wh);
    float *vlm, *exps, *m1, *m2, *e1, *e2;
    __half *hv, *he, *q, *k, *v, *ke, *ve, *att, *m2h, *e2h;
    cudaGetSymbolAddress((void**)&vlm, g_vlm);
    cudaGetSymbolAddress((void**)&exps, g_exp);
    cudaGetSymbolAddress((void**)&m1, g_m1);
    cudaGetSymbolAddress((void**)&m2, g_m2);
    cudaGetSymbolAddress((void**)&e1, g_e1);
    cudaGetSymbolAddress((void**)&e2, g_e2);
    cudaGetSymbolAddress((void**)&hv, h_hv);
    cudaGetSymbolAddress((void**)&he, h_he);
    cudaGetSymbolAddress((void**)&q,  h_q);
    cudaGetSymbolAddress((void**)&k,  h_k);
    cudaGetSymbolAddress((void**)&v,  h_v);
    cudaGetSymbolAddress((void**)&ke, h_ke);
    cudaGetSymbolAddress((void**)&ve, h_ve);
    cudaGetSymbolAddress((void**)&att, h_att);
    cudaGetSymbolAddress((void**)&m2h, h_m2);
    cudaGetSymbolAddress((void**)&e2h, h_e2);

    // ---- convert all weights to half in ONE launch ----
    {
        CvtBatch cb;
        const float* srcs[16] = {f_vq, f_vk, f_vv, f_vo, f_vg, f_vu, f_vd, f_eq,
                                 f_eks, f_evs, f_ekc, f_evc, f_eo, f_eg, f_eu, f_ed};
        size_t offs[16] = {O_VQ, O_VK, O_VV, O_VO, O_VG, O_VU, O_VD, O_EQ,
                           O_EKS, O_EVS, O_EKC, O_EVC, O_EO, O_EG, O_EU, O_ED};
        size_t ns[16] = {N_VQ, N_VK, N_VV, N_VO, N_VG, N_VU, N_VD, N_EQ,
                         N_EKS, N_EVS, N_EKC, N_EVC, N_EO, N_EG, N_EU, N_ED};
        for (int i = 0; i < 16; i++) {
            cb.s[i] = (const float4*)srcs[i];
            cb.d[i] = (uint2*)(wh + offs[i]);
            cb.n4[i] = ns[i] / 4;
        }
        cvt_all_kernel<<<dim3(160, 16), 256>>>(cb);
    }

    cudaMemcpyAsync(vlm,  in_vlm, (size_t)PL * TH * sizeof(float), cudaMemcpyDeviceToDevice);
    cudaMemcpyAsync(exps, in_exp, (size_t)EL * EH * sizeof(float), cudaMemcpyDeviceToDevice);

    GemmBatch b; int blk;
    const int ropeBlocks = (SS * RP_HEADS + 3) / 4;

    for (int li = 0; li < L_LAYERS; li++) {
        const __half* vq  = wh + O_VQ  + (size_t)li * TH * QW;
        const __half* vk  = wh + O_VK  + (size_t)li * TH * KW;
        const __half* vv  = wh + O_VV  + (size_t)li * TH * KW;
        const __half* vo  = wh + O_VO  + (size_t)li * QW * TH;
        const __half* vg  = wh + O_VG  + (size_t)li * TH * TI;
        const __half* vu  = wh + O_VU  + (size_t)li * TH * TI;
        const __half* vd  = wh + O_VD  + (size_t)li * TI * TH;
        const __half* eq  = wh + O_EQ  + (size_t)li * EH * QW;
        const __half* eo  = wh + O_EO  + (size_t)li * QW * EH;
        const __half* eg  = wh + O_EG  + (size_t)li * EH * EI;
        const __half* eu  = wh + O_EU  + (size_t)li * EH * EI;
        const __half* ed  = wh + O_ED  + (size_t)li * EI * EH;

        rms2_kernel<true><<<PL + EL, 256>>>(vlm, w_vln1 + (size_t)li * TH, hv, TH, PL,
                                            exps, w_eln1 + (size_t)li * EH, he, EH);

        if (li % 2 == 0) {
            const __half* eks = wh + O_EKS + (size_t)(li / 2) * EH * KW;
            const __half* evs = wh + O_EVS + (size_t)(li / 2) * EH * KW;
            batch_init(b, blk);
            batch_add(b, blk, hv, vq,  q,                    PL, QW, TH, 0, 1, 1, 1);
            batch_add(b, blk, hv, vk,  k,                    PL, KW, TH, 0, 1, 1, 1);
            batch_add(b, blk, hv, vv,  v,                    PL, KW, TH, 0, 1, 1, 1);
            batch_add(b, blk, he, eq,  q + (size_t)PL * QW,  EL, QW, EH, 0, 1, 1, 1);
            batch_add(b, blk, he, eks, k + (size_t)PL * KW,  EL, KW, EH, 0, 1, 1, 1);
            batch_add(b, blk, he, evs, v + (size_t)PL * KW,  EL, KW, EH, 0, 1, 1, 1);
            batch_go(b, blk);
            rope2_kernel<<<ropeBlocks, 128>>>(q, k, pos_ids, SS);
            attn_kernel<<<dim3(SS, NKV), 128>>>(q, k, v, att, SS, 1);
        } else {
            const __half* ekc = wh + O_EKC + (size_t)(li / 2) * KW * KW;
            const __half* evc = wh + O_EVC + (size_t)(li / 2) * KW * KW;
            batch_init(b, blk);
            batch_add(b, blk, hv, vq, q,                   PL, QW, TH, 0, 1, 1, 1);
            batch_add(b, blk, hv, vk, k,                   PL, KW, TH, 0, 1, 1, 1);
            batch_add(b, blk, hv, vv, v,                   PL, KW, TH, 0, 1, 1, 1);
            batch_add(b, blk, he, eq, q + (size_t)PL * QW, EL, QW, EH, 0, 1, 1, 1);
            batch_go(b, blk);
            rope2_kernel<<<ropeBlocks, 128>>>(q, k, pos_ids, PL);
            batch_init(b, blk);
            batch_add(b, blk, k, ekc, ke, PL, KW, KW, 0, 1, 1, 1);
            batch_add(b, blk, v, evc, ve, PL, KW, KW, 0, 1, 1, 1);
            batch_go(b, blk);
            attn_kernel<<<dim3(PL, NKV), 128>>>(q, k, v, att, PL, 0);
            attn_kernel<<<dim3(EL, NKV), 128>>>(q + (size_t)PL * QW, ke, ve,
                                                att + (size_t)PL * QW, PL, 0);
        }

        // ---- wo: M64 + split-K, atomic accumulate (456 blocks) ----
        batch_init(b, blk);
        batch_add(b, blk, att,                    vo, vlm,  PL, TH, QW, 1, 0, 3, 1);
        batch_add(b, blk, att + (size_t)PL * QW,  eo, exps, EL, EH, QW, 1, 0, 4, 1);
        batch_go(b, blk);

        rms2_kernel<true><<<PL + EL, 256>>>(vlm, w_vln2 + (size_t)li * TH, hv, TH, PL,
                                            exps, w_eln2 + (size_t)li * EH, he, EH);

        // ---- gate + up: vlm M128 (single wave), exp M64 (448 blocks) ----
        batch_init(b, blk);
        batch_add(b, blk, hv, vg, m1, PL, TI, TH, 0, 0, 1, 0);
        batch_add(b, blk, hv, vu, m2, PL, TI, TH, 0, 0, 1, 0);
        batch_add(b, blk, he, eg, e1, EL, EI, EH, 0, 0, 1, 1);
        batch_add(b, blk, he, eu, e2, EL, EI, EH, 0, 0, 1, 1);
        batch_go(b, blk);

        silu2_kernel<<<(PL * TI + EL * EI + 255) / 256, 256>>>(
            m1, m2, m2h, PL * TI, e1, e2, e2h, EL * EI);

        // ---- down: M64 + split-K, atomic accumulate (456 blocks) ----
        batch_init(b, blk);
        batch_add(b, blk, m2h, vd, vlm,  PL, TH, TI, 1, 0, 3, 1);
        batch_add(b, blk, e2h, ed, exps, EL, EH, EI, 1, 0, 4, 1);
        batch_go(b, blk);
    }

    // final norms -> fp32 output (merged)
    rms2_kernel<false><<<PL + EL, 256>>>(vlm, w_vfn, out, TH, PL,
                                         exps, w_efn, out + (size_t)PL * TH, EH);
}